// round 6
// baseline (speedup 1.0000x reference)
#include <cuda_runtime.h>
#include <cuda_bf16.h>
#include <math.h>

// ---------------- problem constants ----------------
#define NN   512
#define BB   64
#define LL   12
#define HH   12
#define RNN  64
#define DDEC 128
#define KENC 390        // logical enc feature count
#define KDEC 804        // logical dec feature count
#define SECE 416        // enc section (pad to /32)
#define SECD 832        // dec section
#define KPE  (3*SECE)   // 1248
#define KPD  (3*SECD)   // 2496
#define KGC  (3*NN)     // 1536 (graph conv K')
#define ROWS (NN*BB)    // 32768

typedef __nv_bfloat16 bf16;

// ---------------- scratch (device globals; zero-init, no allocation) ----------------
__device__ float g_S[4*NN*NN];
__device__ float g_e1[NN*64];
__device__ float g_e2[NN*64];
__device__ float g_xT[NN*LL*BB];
__device__ float g_GX[4*NN*LL*BB];
__device__ float g_henc[ROWS*RNN];
__device__ float g_hdec[ROWS*DDEC];
__device__ float g_r [ROWS*DDEC];
__device__ float g_go[ROWS];
__device__ float g_Ggo[4*NN*BB];
// bf16 split operands
__device__ bf16 g_Sbig [4*NN*KGC];       // A: [hi|lo|hi], 2048 x 1536
__device__ bf16 g_hB   [KGC*BB*DDEC];    // B: [hi|hi|lo], up to 1536 x 8192
__device__ bf16 g_xgEg [ROWS*KPE];       // enc gate-input features
__device__ bf16 g_xgEu [ROWS*KPE];       // enc upd-input features
__device__ bf16 g_xgDg [ROWS*KPD];       // dec gate-input features
__device__ bf16 g_xgDu [ROWS*KPD];       // dec upd-input features
__device__ bf16 g_egWB [KPE*128];
__device__ bf16 g_euWB [KPE*64];
__device__ bf16 g_dgWB [KPD*256];
__device__ bf16 g_duWB [KPD*128];

// ---------------- helpers ----------------
__device__ __forceinline__ void split2(float v, bf16 &h, bf16 &l) {
    h = __float2bfloat16(v);
    l = __float2bfloat16(v - __bfloat162float(h));
}
__device__ __forceinline__ void store3(bf16* p, int off, int sec, float v) {
    bf16 h, l; split2(v, h, l);
    p[off] = h; p[sec + off] = l; p[2 * sec + off] = h;   // A-layout [hi|lo|hi]
}
__device__ __forceinline__ void storeB3(bf16* hB, int n, size_t col, int Ncols, float v) {
    bf16 h, l; split2(v, h, l);                           // B-layout [hi|hi|lo]
    hB[(size_t)n * Ncols + col]            = h;
    hB[(size_t)(NN + n) * Ncols + col]     = h;
    hB[(size_t)(2 * NN + n) * Ncols + col] = l;
}
__device__ __forceinline__ void fma2(unsigned long long &d, unsigned long long a, unsigned long long b) {
    asm("fma.rn.f32x2 %0, %1, %2, %0;" : "+l"(d) : "l"(a), "l"(b));
}
__device__ __forceinline__ unsigned long long bcast2(float x) {
    unsigned long long r;
    asm("mov.b64 %0, {%1, %1};" : "=l"(r) : "f"(x));
    return r;
}

// ================= bf16 tensor-core GEMM, 128x128x32, 2-stage reg-staged ========
// (round-3 mainloop: measured faster than cp.async 3-stage on this workload)
// A: row-major M x Kp, B: row-major Kp x N. M%128==0, Kp%32==0.
// MODE 2 (gate):  v=sigmoid(acc+bias[c]); c<hd: zh=v*h_in -> hB triple + xg_u id triples
//                 c>=hd: rbuf = v
// MODE 3 (upd):   hc=tanh(acc+bias[c]); hn=r*h+(1-r)*hc -> h, hB triple, xg_g id triples
// MODE 4 (conv):  scatter into xg conv blocks (triples)
template<int MODE>
__global__ void __launch_bounds__(256)
bgemm(const bf16* __restrict__ A, const bf16* __restrict__ Bm,
      bf16* __restrict__ xg, int M, int N, int Kp,
      const float* __restrict__ bias, const float* __restrict__ h_in,
      float* __restrict__ rbuf, float* __restrict__ h_out,
      bf16* __restrict__ hB, int Ncols,
      int sec, int off0, int off3, int hdshift,
      int o0, int o1, int o2, int o3)
{
    __shared__ __align__(16) bf16 As[2][128 * 40];
    __shared__ __align__(16) bf16 Bs[2][32 * 136];

    const int tid  = threadIdx.x;
    const int lane = tid & 31;
    const int warp = tid >> 5;
    const int wm   = warp & 1;
    const int wn   = warp >> 1;
    const int row0 = blockIdx.y * 128;
    const int col0 = blockIdx.x * 128;

    float acc[4][4][4];
    #pragma unroll
    for (int i = 0; i < 4; i++)
        #pragma unroll
        for (int j = 0; j < 4; j++)
            #pragma unroll
            for (int g = 0; g < 4; g++) acc[i][j][g] = 0.f;

    const int aq0 = tid * 2;
    const int ar0 = aq0 >> 2, ac0 = (aq0 & 3) * 8;
    const int ar1 = (aq0 + 1) >> 2, ac1 = ((aq0 + 1) & 3) * 8;
    const int br0 = aq0 >> 4, bc0 = (aq0 & 15) * 8;
    const int br1 = (aq0 + 1) >> 4, bc1 = ((aq0 + 1) & 15) * 8;
    const bool ok0 = (col0 + bc0) < N;
    const bool ok1 = (col0 + bc1) < N;

    const int T = Kp >> 5;
    int4 pa0, pa1, pb0, pb1;
    const int4 z4 = make_int4(0, 0, 0, 0);

    // prologue: tile 0
    pa0 = *(const int4*)(A + (size_t)(row0 + ar0) * Kp + ac0);
    pa1 = *(const int4*)(A + (size_t)(row0 + ar1) * Kp + ac1);
    pb0 = ok0 ? *(const int4*)(Bm + (size_t)br0 * N + col0 + bc0) : z4;
    pb1 = ok1 ? *(const int4*)(Bm + (size_t)br1 * N + col0 + bc1) : z4;
    *(int4*)&As[0][ar0 * 40 + ac0] = pa0;
    *(int4*)&As[0][ar1 * 40 + ac1] = pa1;
    *(int4*)&Bs[0][br0 * 136 + bc0] = pb0;
    *(int4*)&Bs[0][br1 * 136 + bc1] = pb1;
    __syncthreads();

    for (int kt = 0; kt < T; kt++) {
        const int cur = kt & 1;
        if (kt + 1 < T) {
            const int k0 = (kt + 1) * 32;
            pa0 = *(const int4*)(A + (size_t)(row0 + ar0) * Kp + k0 + ac0);
            pa1 = *(const int4*)(A + (size_t)(row0 + ar1) * Kp + k0 + ac1);
            pb0 = ok0 ? *(const int4*)(Bm + (size_t)(k0 + br0) * N + col0 + bc0) : z4;
            pb1 = ok1 ? *(const int4*)(Bm + (size_t)(k0 + br1) * N + col0 + bc1) : z4;
        }
        #pragma unroll
        for (int kk = 0; kk < 2; kk++) {
            unsigned af[4][4], bfg[4][2];
            #pragma unroll
            for (int i = 0; i < 4; i++) {
                const bf16* p = &As[cur][(wm * 64 + i * 16 + (lane & 15)) * 40 + kk * 16 + (lane >> 4) * 8];
                unsigned addr = (unsigned)__cvta_generic_to_shared(p);
                asm volatile("ldmatrix.sync.aligned.m8n8.x4.shared.b16 {%0,%1,%2,%3}, [%4];"
                             : "=r"(af[i][0]), "=r"(af[i][1]), "=r"(af[i][2]), "=r"(af[i][3])
                             : "r"(addr));
            }
            #pragma unroll
            for (int j = 0; j < 4; j++) {
                const bf16* p = &Bs[cur][(kk * 16 + (lane & 15)) * 136 + wn * 32 + j * 8];
                unsigned addr = (unsigned)__cvta_generic_to_shared(p);
                asm volatile("ldmatrix.sync.aligned.m8n8.x2.trans.shared.b16 {%0,%1}, [%2];"
                             : "=r"(bfg[j][0]), "=r"(bfg[j][1]) : "r"(addr));
            }
            #pragma unroll
            for (int i = 0; i < 4; i++)
                #pragma unroll
                for (int j = 0; j < 4; j++)
                    asm volatile(
                        "mma.sync.aligned.m16n8k16.row.col.f32.bf16.bf16.f32 "
                        "{%0,%1,%2,%3}, {%4,%5,%6,%7}, {%8,%9}, {%0,%1,%2,%3};"
                        : "+f"(acc[i][j][0]), "+f"(acc[i][j][1]), "+f"(acc[i][j][2]), "+f"(acc[i][j][3])
                        : "r"(af[i][0]), "r"(af[i][1]), "r"(af[i][2]), "r"(af[i][3]),
                          "r"(bfg[j][0]), "r"(bfg[j][1]));
        }
        if (kt + 1 < T) {
            const int nxt = cur ^ 1;
            *(int4*)&As[nxt][ar0 * 40 + ac0] = pa0;
            *(int4*)&As[nxt][ar1 * 40 + ac1] = pa1;
            *(int4*)&Bs[nxt][br0 * 136 + bc0] = pb0;
            *(int4*)&Bs[nxt][br1 * 136 + bc1] = pb1;
        }
        __syncthreads();
    }

    const int hd = 1 << hdshift;
    const int hmask = hd - 1;

    #pragma unroll
    for (int i = 0; i < 4; i++)
        #pragma unroll
        for (int j = 0; j < 4; j++)
            #pragma unroll
            for (int g = 0; g < 4; g++) {
                const int rr = row0 + wm * 64 + i * 16 + (lane >> 2) + ((g >> 1) << 3);
                const int cc = col0 + wn * 32 + j * 8 + ((lane & 3) << 1) + (g & 1);
                if (cc >= N) continue;
                float v = acc[i][j][g];
                if (MODE == 4) {
                    const int jblk = row0 >> 9;
                    const int off  = (jblk == 0) ? o0 : (jblk == 1) ? o1 : (jblk == 2) ? o2 : o3;
                    const int n = rr & (NN - 1);
                    const int b = cc >> hdshift;
                    const int c = cc & hmask;
                    store3(xg + (size_t)(n * BB + b) * 3 * sec, off + c, sec, v);
                } else if (MODE == 2) {
                    v = 1.f / (1.f + expf(-(v + bias[cc])));
                    if (cc < hd) {
                        const float zh = v * h_in[(size_t)rr * hd + cc];
                        const int n = rr >> 6, b = rr & 63;
                        storeB3(hB, n, (size_t)b * hd + cc, Ncols, zh);
                        bf16* p = xg + (size_t)rr * 3 * sec;
                        store3(p, off0 + cc, sec, zh);
                        store3(p, off3 + cc, sec, zh);
                    } else {
                        rbuf[(size_t)rr * hd + (cc - hd)] = v;
                    }
                } else { // MODE 3
                    const float hc = tanhf(v + bias[cc]);
                    const size_t idx = (size_t)rr * hd + cc;
                    const float rv = rbuf[idx];
                    const float hn = rv * h_out[idx] + (1.f - rv) * hc;
                    h_out[idx] = hn;
                    const int n = rr >> 6, b = rr & 63;
                    storeB3(hB, n, (size_t)b * hd + cc, Ncols, hn);
                    bf16* p = xg + (size_t)rr * 3 * sec;
                    store3(p, off0 + cc, sec, hn);
                    store3(p, off3 + cc, sec, hn);
                }
            }
}

// ================= fp32 f32x2 SGEMM (small GEMMs only) =====================
template<int MODE>   // MODE 0: plain, MODE 1: 2*acc - I
__global__ void __launch_bounds__(256)
sgemm(const float* __restrict__ A, const float* __restrict__ Bm, float* __restrict__ C,
      int M, int N, int K)
{
    __shared__ __align__(16) float As[2][16][132];
    __shared__ __align__(16) float Bsh[2][16][132];
    const int tid = threadIdx.x;
    const int tx  = tid & 15;
    const int ty  = tid >> 4;
    const int row0 = blockIdx.y * 128;
    const int col0 = blockIdx.x * 128;

    const int am  = tid >> 1;
    const int ak0 = (tid & 1) << 2;
    const int bk  = tid >> 5;
    const int bn  = (tid & 31) << 2;
    const int gn  = col0 + bn;
    const bool bok = gn < N;

    unsigned long long acc[8][4];
    #pragma unroll
    for (int i = 0; i < 8; i++)
        #pragma unroll
        for (int j = 0; j < 4; j++) acc[i][j] = 0ull;

    const int T = K >> 4;
    const float4 z4 = make_float4(0.f, 0.f, 0.f, 0.f);
    const float* Abase = A + (size_t)(row0 + am) * K + ak0;

    float4 ra0 = *(const float4*)(Abase);
    float4 ra1 = *(const float4*)(Abase + 8);
    float4 rb0 = bok ? *(const float4*)(Bm + (size_t)bk * N + gn) : z4;
    float4 rb1 = bok ? *(const float4*)(Bm + (size_t)(bk + 8) * N + gn) : z4;
    As[0][ak0 + 0][am] = ra0.x; As[0][ak0 + 1][am] = ra0.y;
    As[0][ak0 + 2][am] = ra0.z; As[0][ak0 + 3][am] = ra0.w;
    As[0][ak0 + 8][am] = ra1.x; As[0][ak0 + 9][am] = ra1.y;
    As[0][ak0 +10][am] = ra1.z; As[0][ak0 +11][am] = ra1.w;
    *(float4*)&Bsh[0][bk][bn]     = rb0;
    *(float4*)&Bsh[0][bk + 8][bn] = rb1;
    __syncthreads();

    for (int kt = 0; kt < T; kt++) {
        const int cur = kt & 1;
        if (kt + 1 < T) {
            const float* Ap = Abase + (kt + 1) * 16;
            ra0 = *(const float4*)(Ap);
            ra1 = *(const float4*)(Ap + 8);
            const int gk = (kt + 1) * 16;
            rb0 = bok ? *(const float4*)(Bm + (size_t)(gk + bk) * N + gn) : z4;
            rb1 = bok ? *(const float4*)(Bm + (size_t)(gk + bk + 8) * N + gn) : z4;
        }
        #pragma unroll
        for (int kk = 0; kk < 16; kk++) {
            float4 a0 = *(const float4*)&As[cur][kk][ty * 8];
            float4 a1 = *(const float4*)&As[cur][kk][ty * 8 + 4];
            ulonglong2 bp0 = *(const ulonglong2*)&Bsh[cur][kk][tx * 8];
            ulonglong2 bp1 = *(const ulonglong2*)&Bsh[cur][kk][tx * 8 + 4];
            unsigned long long b2[4] = { bp0.x, bp0.y, bp1.x, bp1.y };
            unsigned long long a2[8] = {
                bcast2(a0.x), bcast2(a0.y), bcast2(a0.z), bcast2(a0.w),
                bcast2(a1.x), bcast2(a1.y), bcast2(a1.z), bcast2(a1.w)
            };
            #pragma unroll
            for (int i = 0; i < 8; i++)
                #pragma unroll
                for (int j = 0; j < 4; j++)
                    fma2(acc[i][j], a2[i], b2[j]);
        }
        if (kt + 1 < T) {
            const int nxt = cur ^ 1;
            As[nxt][ak0 + 0][am] = ra0.x; As[nxt][ak0 + 1][am] = ra0.y;
            As[nxt][ak0 + 2][am] = ra0.z; As[nxt][ak0 + 3][am] = ra0.w;
            As[nxt][ak0 + 8][am] = ra1.x; As[nxt][ak0 + 9][am] = ra1.y;
            As[nxt][ak0 +10][am] = ra1.z; As[nxt][ak0 +11][am] = ra1.w;
            *(float4*)&Bsh[nxt][bk][bn]     = rb0;
            *(float4*)&Bsh[nxt][bk + 8][bn] = rb1;
        }
        __syncthreads();
    }

    #pragma unroll
    for (int i = 0; i < 8; i++) {
        const int r = row0 + ty * 8 + i;
        #pragma unroll
        for (int j = 0; j < 4; j++) {
            #pragma unroll
            for (int h = 0; h < 2; h++) {
                const int cc = col0 + tx * 8 + 2 * j + h;
                if (cc >= N) continue;
                float v = h ? __uint_as_float((unsigned)(acc[i][j] >> 32))
                            : __uint_as_float((unsigned)(acc[i][j]));
                if (MODE == 0) C[(size_t)r * N + cc] = v;
                else           C[(size_t)r * N + cc] = 2.f * v - ((r == cc) ? 1.f : 0.f);
            }
        }
    }
}

// ---------------- small kernels ----------------
__global__ void k_zero(float* p, int n) {
    int i = blockIdx.x * blockDim.x + threadIdx.x;
    if (i < n) p[i] = 0.f;
}

__global__ void k_splitA(const float* __restrict__ in, bf16* __restrict__ out, int K, int total) {
    int i = blockIdx.x * blockDim.x + threadIdx.x;
    if (i >= total) return;
    int m = i / K, k = i - m * K;
    bf16 h, l; split2(in[i], h, l);
    bf16* p = out + (size_t)m * 3 * K;
    p[k] = h; p[K + k] = l; p[2 * K + k] = h;
}

__global__ void k_splitB(const float* __restrict__ in, bf16* __restrict__ out,
                         int Ksec, int N, int total) {
    int i = blockIdx.x * blockDim.x + threadIdx.x;
    if (i >= total) return;
    int k = i / N, j = i - k * N;
    bf16 h, l; split2(in[i], h, l);
    out[(size_t)k * N + j]              = h;
    out[(size_t)(Ksec + k) * N + j]     = h;
    out[(size_t)(2 * Ksec + k) * N + j] = l;
}

__global__ void k_eW(const float* __restrict__ We, const float* __restrict__ Mem,
                     float* __restrict__ e) {
    int idx = blockIdx.x * blockDim.x + threadIdx.x;
    if (idx >= NN * 64) return;
    int n = idx >> 6, d = idx & 63;
    float s = 0.f;
    #pragma unroll
    for (int k = 0; k < 20; k++) s += We[n * 20 + k] * Mem[k * 64 + d];
    e[idx] = s;
}

__global__ void k_gsoftmax(const float* __restrict__ ea, const float* __restrict__ eb,
                           float* __restrict__ g) {
    __shared__ float er[64];
    __shared__ float buf[NN];
    __shared__ float red[128];
    int n = blockIdx.x, tid = threadIdx.x;
    if (tid < 64) er[tid] = ea[n * 64 + tid];
    __syncthreads();
    for (int m = tid; m < NN; m += 128) {
        float s = 0.f;
        #pragma unroll
        for (int d = 0; d < 64; d++) s += er[d] * eb[m * 64 + d];
        buf[m] = s > 0.f ? s : 0.f;
    }
    __syncthreads();
    float mx = -1e30f;
    for (int m = tid; m < NN; m += 128) mx = fmaxf(mx, buf[m]);
    red[tid] = mx; __syncthreads();
    for (int s = 64; s > 0; s >>= 1) { if (tid < s) red[tid] = fmaxf(red[tid], red[tid + s]); __syncthreads(); }
    mx = red[0]; __syncthreads();
    float sm = 0.f;
    for (int m = tid; m < NN; m += 128) { float e = expf(buf[m] - mx); buf[m] = e; sm += e; }
    red[tid] = sm; __syncthreads();
    for (int s = 64; s > 0; s >>= 1) { if (tid < s) red[tid] += red[tid + s]; __syncthreads(); }
    float inv = 1.f / red[0];
    for (int m = tid; m < NN; m += 128) g[n * NN + m] = buf[m] * inv;
}

__global__ void k_xT(const float* __restrict__ x, float* __restrict__ xT) {
    int idx = blockIdx.x * blockDim.x + threadIdx.x;
    if (idx >= BB * NN * LL) return;
    int l = idx % LL;
    int n = (idx / LL) % NN;
    int b = idx / (LL * NN);
    xT[(n * LL + l) * BB + b] = x[idx];
}

// fill x-channels of both enc feature buffers for step l
__global__ void k_fill_enc_x(bf16* __restrict__ xgg, bf16* __restrict__ xgu,
                             const float* __restrict__ xT, const float* __restrict__ GX, int l) {
    int row = blockIdx.x * blockDim.x + threadIdx.x;
    if (row >= ROWS) return;
    int n = row >> 6, b = row & 63;
    float xv = xT[(n * LL + l) * BB + b];
    float c0 = GX[(size_t)(0 * NN + n) * (LL * BB) + l * BB + b];
    float c1 = GX[(size_t)(1 * NN + n) * (LL * BB) + l * BB + b];
    float c2 = GX[(size_t)(2 * NN + n) * (LL * BB) + l * BB + b];
    float c3 = GX[(size_t)(3 * NN + n) * (LL * BB) + l * BB + b];
    bf16* pg = xgg + (size_t)row * KPE;
    bf16* pu = xgu + (size_t)row * KPE;
    store3(pg, 0, SECE, xv);   store3(pu, 0, SECE, xv);
    store3(pg, 195, SECE, xv); store3(pu, 195, SECE, xv);
    store3(pg, 65,  SECE, c0); store3(pu, 65,  SECE, c0);
    store3(pg, 130, SECE, c1); store3(pu, 130, SECE, c1);
    store3(pg, 260, SECE, c2); store3(pu, 260, SECE, c2);
    store3(pg, 325, SECE, c3); store3(pu, 325, SECE, c3);
}

// init id-blocks from fp32 h (used once for enc h0 and dec h_de)
__global__ void k_fill_h_id(bf16* __restrict__ xg, const float* __restrict__ h,
                            int hdshift, int sec, int off0, int off3, int total) {
    int i = blockIdx.x * blockDim.x + threadIdx.x;
    if (i >= total) return;
    int row = i >> hdshift;
    int c   = i & ((1 << hdshift) - 1);
    float v = h[i];
    bf16* p = xg + (size_t)row * 3 * sec;
    store3(p, off0 + c, sec, v);
    store3(p, off3 + c, sec, v);
}

// fill decoder go+ycov channels of both buffers for step t
__global__ void k_fill_dec(bf16* __restrict__ xgg, bf16* __restrict__ xgu,
                           const float* __restrict__ go,
                           const float* __restrict__ Ggo, const float* __restrict__ tt, int t) {
    int row = blockIdx.x * blockDim.x + threadIdx.x;
    if (row >= ROWS) return;
    int n = row >> 6, b = row & 63;
    bf16* pg = xgg + (size_t)row * KPD;
    bf16* pu = xgu + (size_t)row * KPD;
    float gv = go[row];
    float c0 = Ggo[(0 * NN + n) * BB + b];
    float c1 = Ggo[(1 * NN + n) * BB + b];
    float c2 = Ggo[(2 * NN + n) * BB + b];
    float c3 = Ggo[(3 * NN + n) * BB + b];
    store3(pg, 0,   SECD, gv); store3(pu, 0,   SECD, gv);
    store3(pg, 402, SECD, gv); store3(pu, 402, SECD, gv);
    store3(pg, 134, SECD, c0); store3(pu, 134, SECD, c0);
    store3(pg, 268, SECD, c1); store3(pu, 268, SECD, c1);
    store3(pg, 536, SECD, c2); store3(pu, 536, SECD, c2);
    store3(pg, 670, SECD, c3); store3(pu, 670, SECD, c3);
    #pragma unroll
    for (int c = 0; c < 5; c++) {
        float v = tt[(b * 5 + c) * HH + t];
        store3(pg, 1 + c,   SECD, v); store3(pu, 1 + c,   SECD, v);
        store3(pg, 135 + c, SECD, v); store3(pu, 135 + c, SECD, v);
        store3(pg, 269 + c, SECD, v); store3(pu, 269 + c, SECD, v);
        store3(pg, 403 + c, SECD, v); store3(pu, 403 + c, SECD, v);
        store3(pg, 537 + c, SECD, v); store3(pu, 537 + c, SECD, v);
        store3(pg, 671 + c, SECD, v); store3(pu, 671 + c, SECD, v);
    }
}

__global__ void k_attn(const float* __restrict__ h, const float* __restrict__ Wq,
                       const float* __restrict__ Mem, float* __restrict__ hde) {
    __shared__ float hr[64];
    __shared__ float q[64];
    __shared__ float sc[20];
    int row = blockIdx.x, tid = threadIdx.x;
    hr[tid] = h[row * 64 + tid];
    __syncthreads();
    float s = 0.f;
    #pragma unroll
    for (int c = 0; c < 64; c++) s += hr[c] * Wq[c * 64 + tid];
    q[tid] = s;
    __syncthreads();
    if (tid < 20) {
        float v = 0.f;
        #pragma unroll
        for (int c = 0; c < 64; c++) v += q[c] * Mem[tid * 64 + c];
        sc[tid] = v;
    }
    __syncthreads();
    if (tid == 0) {
        float mx = -1e30f;
        for (int j = 0; j < 20; j++) mx = fmaxf(mx, sc[j]);
        float sm = 0.f;
        for (int j = 0; j < 20; j++) { sc[j] = expf(sc[j] - mx); sm += sc[j]; }
        float inv = 1.f / sm;
        for (int j = 0; j < 20; j++) sc[j] *= inv;
    }
    __syncthreads();
    float ha = 0.f;
    #pragma unroll
    for (int j = 0; j < 20; j++) ha += sc[j] * Mem[j * 64 + tid];
    hde[row * 128 + tid]      = hr[tid];
    hde[row * 128 + 64 + tid] = ha;
}

// decoder projection: go = h . pW + pb, write output
__global__ void k_proj(const float* __restrict__ h, const float* __restrict__ pW,
                       const float* __restrict__ pb, float* __restrict__ go,
                       float* __restrict__ out, int t) {
    __shared__ float red[128];
    int row = blockIdx.x, c = threadIdx.x;
    red[c] = h[(size_t)row * 128 + c] * pW[c];
    __syncthreads();
    for (int s = 64; s > 0; s >>= 1) { if (c < s) red[c] += red[c + s]; __syncthreads(); }
    if (c == 0) {
        float g = red[0] + pb[0];
        go[row] = g;
        int n = row >> 6, b = row & 63;
        out[(b * NN + n) * HH + t] = g;
    }
}

// ---------------- host side ----------------
static void bg(int mode, const bf16* A, const bf16* B, bf16* xg,
               int M, int N, int Kp,
               const float* bias = nullptr, const float* h_in = nullptr,
               float* rbuf = nullptr, float* h_out = nullptr,
               bf16* hB = nullptr, int Ncols = 0,
               int sec = 0, int off0 = 0, int off3 = 0, int hdshift = 0,
               int o0 = 0, int o1 = 0, int o2 = 0, int o3 = 0)
{
    dim3 grid((N + 127) / 128, M / 128);
    switch (mode) {
        case 2: bgemm<2><<<grid, 256>>>(A, B, xg, M, N, Kp, bias, h_in, rbuf, h_out, hB, Ncols, sec, off0, off3, hdshift, o0, o1, o2, o3); break;
        case 3: bgemm<3><<<grid, 256>>>(A, B, xg, M, N, Kp, bias, h_in, rbuf, h_out, hB, Ncols, sec, off0, off3, hdshift, o0, o1, o2, o3); break;
        case 4: bgemm<4><<<grid, 256>>>(A, B, xg, M, N, Kp, bias, h_in, rbuf, h_out, hB, Ncols, sec, off0, off3, hdshift, o0, o1, o2, o3); break;
    }
}

extern "C" void kernel_launch(void* const* d_in, const int* in_sizes, int n_in,
                              void* d_out, int out_size)
{
    const float* x   = (const float*)d_in[0];
    const float* tt  = (const float*)d_in[3];
    const float* Mem = (const float*)d_in[5];
    const float* Wq  = (const float*)d_in[6];
    const float* We1 = (const float*)d_in[7];
    const float* We2 = (const float*)d_in[8];
    const float* egW = (const float*)d_in[9];
    const float* egb = (const float*)d_in[10];
    const float* euW = (const float*)d_in[11];
    const float* eub = (const float*)d_in[12];
    const float* dgW = (const float*)d_in[13];
    const float* dgb = (const float*)d_in[14];
    const float* duW = (const float*)d_in[15];
    const float* dub = (const float*)d_in[16];
    const float* pW  = (const float*)d_in[17];
    const float* pb  = (const float*)d_in[18];
    float* out = (float*)d_out;

    float *S, *e1, *e2, *xT, *GX, *henc, *hdec, *r, *go, *Ggo;
    bf16 *Sbig, *hB, *xgEg, *xgEu, *xgDg, *xgDu, *egWB, *euWB, *dgWB, *duWB;
    cudaGetSymbolAddress((void**)&S,    g_S);
    cudaGetSymbolAddress((void**)&e1,   g_e1);
    cudaGetSymbolAddress((void**)&e2,   g_e2);
    cudaGetSymbolAddress((void**)&xT,   g_xT);
    cudaGetSymbolAddress((void**)&GX,   g_GX);
    cudaGetSymbolAddress((void**)&henc, g_henc);
    cudaGetSymbolAddress((void**)&hdec, g_hdec);
    cudaGetSymbolAddress((void**)&r,    g_r);
    cudaGetSymbolAddress((void**)&go,   g_go);
    cudaGetSymbolAddress((void**)&Ggo,  g_Ggo);
    cudaGetSymbolAddress((void**)&Sbig, g_Sbig);
    cudaGetSymbolAddress((void**)&hB,   g_hB);
    cudaGetSymbolAddress((void**)&xgEg, g_xgEg);
    cudaGetSymbolAddress((void**)&xgEu, g_xgEu);
    cudaGetSymbolAddress((void**)&xgDg, g_xgDg);
    cudaGetSymbolAddress((void**)&xgDu, g_xgDu);
    cudaGetSymbolAddress((void**)&egWB, g_egWB);
    cudaGetSymbolAddress((void**)&euWB, g_euWB);
    cudaGetSymbolAddress((void**)&dgWB, g_dgWB);
    cudaGetSymbolAddress((void**)&duWB, g_duWB);

    // --- weight splits (pad rows stay zero) ---
    k_splitB<<<(KENC * 128 + 255) / 256, 256>>>(egW, egWB, SECE, 128, KENC * 128);
    k_splitB<<<(KENC * 64  + 255) / 256, 256>>>(euW, euWB, SECE, 64,  KENC * 64);
    k_splitB<<<(KDEC * 256 + 255) / 256, 256>>>(dgW, dgWB, SECD, 256, KDEC * 256);
    k_splitB<<<(KDEC * 128 + 255) / 256, 256>>>(duW, duWB, SECD, 128, KDEC * 128);

    // --- supports (fp32) ---
    k_eW<<<(NN * 64 + 255) / 256, 256>>>(We1, Mem, e1);
    k_eW<<<(NN * 64 + 255) / 256, 256>>>(We2, Mem, e2);
    k_gsoftmax<<<NN, 128>>>(e1, e2, S);
    k_gsoftmax<<<NN, 128>>>(e2, e1, S + 2 * NN * NN);
    {
        dim3 g1(NN / 128, NN / 128);
        sgemm<1><<<g1, 256>>>(S,               S,               S + 1 * NN * NN, NN, NN, NN);
        sgemm<1><<<g1, 256>>>(S + 2 * NN * NN, S + 2 * NN * NN, S + 3 * NN * NN, NN, NN, NN);
    }
    k_splitA<<<(4 * NN * NN + 255) / 256, 256>>>(S, Sbig, NN, 4 * NN * NN);

    // --- encoder x precompute ---
    k_xT<<<(BB * NN * LL + 255) / 256, 256>>>(x, xT);
    {
        dim3 g2((LL * BB + 127) / 128, 4 * NN / 128);
        sgemm<0><<<g2, 256>>>(S, xT, GX, 4 * NN, LL * BB, NN);
    }

    // --- init states: henc=0, go=0, hB zeros, xgEg id-blocks=0 ---
    k_zero<<<(ROWS * RNN + 255) / 256, 256>>>(henc, ROWS * RNN);
    k_zero<<<(ROWS + 255) / 256, 256>>>(go, ROWS);
    k_fill_h_id<<<(ROWS * RNN) / 256, 256>>>(xgEg, henc, 6, SECE, 1, 196, ROWS * RNN);
    k_splitB<<<(ROWS * RNN + 255) / 256, 256>>>(henc, hB, NN, BB * RNN, ROWS * RNN);

    // --- encoder ---
    for (int l = 0; l < LL; l++) {
        k_fill_enc_x<<<ROWS / 256, 256>>>(xgEg, xgEu, xT, GX, l);
        // conv(h) -> xgEg conv blocks
        bg(4, Sbig, hB, xgEg, 4 * NN, BB * RNN, KGC,
           nullptr, nullptr, nullptr, nullptr, nullptr, 0, SECE, 0, 0, 6, 66, 131, 261, 326);
        // gate: z,r ; fused zh -> hB + xgEu id blocks
        bg(2, xgEg, egWB, xgEu, ROWS, 2 * RNN, KPE,
           egb, henc, r, nullptr, hB, BB * RNN, SECE, 1, 196, 6);
        // conv(zh) -> xgEu conv blocks
        bg(4, Sbig, hB, xgEu, 4 * NN, BB * RNN, KGC,
           nullptr, nullptr, nullptr, nullptr, nullptr, 0, SECE, 0, 0, 6, 66, 131, 261, 326);
        // upd: hc ; fused h' -> henc + hB + xgEg id blocks
        bg(3, xgEu, euWB, xgEg, ROWS, RNN, KPE,
           eub, nullptr, r, henc, hB, BB * RNN, SECE, 1, 196, 6);
    }

    // --- memory attention -> decoder initial hidden ---
    k_attn<<<ROWS, 64>>>(henc, Wq, Mem, hdec);
    k_fill_h_id<<<(ROWS * DDEC) / 256, 256>>>(xgDg, hdec, 7, SECD, 6, 408, ROWS * DDEC);
    k_splitB<<<(ROWS * DDEC + 255) / 256, 256>>>(hdec, hB, NN, BB * DDEC, ROWS * DDEC);

    // --- decoder ---
    for (int t = 0; t < HH; t++) {
        {
            dim3 g3(1, 4 * NN / 128);
            sgemm<0><<<g3, 256>>>(S, go, Ggo, 4 * NN, BB, NN);
        }
        k_fill_dec<<<ROWS / 256, 256>>>(xgDg, xgDu, go, Ggo, tt, t);
        bg(4, Sbig, hB, xgDg, 4 * NN, BB * DDEC, KGC,
           nullptr, nullptr, nullptr, nullptr, nullptr, 0, SECD, 0, 0, 7, 140, 274, 542, 676);
        bg(2, xgDg, dgWB, xgDu, ROWS, 2 * DDEC, KPD,
           dgb, hdec, r, nullptr, hB, BB * DDEC, SECD, 6, 408, 7);
        bg(4, Sbig, hB, xgDu, 4 * NN, BB * DDEC, KGC,
           nullptr, nullptr, nullptr, nullptr, nullptr, 0, SECD, 0, 0, 7, 140, 274, 542, 676);
        bg(3, xgDu, duWB, xgDg, ROWS, DDEC, KPD,
           dub, nullptr, r, hdec, hB, BB * DDEC, SECD, 6, 408, 7);
        k_proj<<<ROWS, 128>>>(hdec, pW, pb, go, out, t);
    }
}

// round 7
// speedup vs baseline: 1.7727x; 1.7727x over previous
#include <cuda_runtime.h>
#include <cuda_fp16.h>
#include <math.h>

// ---------------- problem constants ----------------
#define NN   512
#define BB   64
#define LL   12
#define HH   12
#define RNN  64
#define DDEC 128
#define KENC 390        // logical enc feature count
#define KDEC 804        // logical dec feature count
#define SECE 416        // enc section (pad to /32)
#define SECD 832        // dec section
#define KPE  (2*SECE)   // 832
#define KPD  (2*SECD)   // 1664
#define KGC  (2*NN)     // 1024 (graph conv K')
#define ROWS (NN*BB)    // 32768

typedef __half hf;

// ---------------- scratch (device globals; zero-init, no allocation) ----------------
__device__ float g_S[4*NN*NN];
__device__ float g_e1[NN*64];
__device__ float g_e2[NN*64];
__device__ float g_xT[NN*LL*BB];
__device__ float g_GX[4*NN*LL*BB];
__device__ float g_henc[ROWS*RNN];
__device__ float g_hdec[ROWS*DDEC];
__device__ float g_z [ROWS*DDEC];
__device__ float g_r [ROWS*DDEC];
__device__ float g_hc[ROWS*DDEC];
__device__ float g_zh[ROWS*DDEC];
__device__ float g_go[ROWS];
__device__ float g_Ggo[4*NN*BB];
// fp16 2-term split operands
__device__ hf g_Sbig [4*NN*KGC];       // A: [hi|lo], 2048 x 1024
__device__ hf g_hB   [KGC*BB*DDEC];    // B: [hi|hi], up to 1024 x 8192
__device__ hf g_xgE  [ROWS*KPE];       // enc feature A (pads stay 0)
__device__ hf g_xgD  [ROWS*KPD];       // dec feature A
__device__ hf g_egWB [KPE*128];
__device__ hf g_euWB [KPE*64];
__device__ hf g_dgWB [KPD*256];
__device__ hf g_duWB [KPD*128];

// ---------------- helpers ----------------
__device__ __forceinline__ void split2h(float v, hf &h, hf &l) {
    h = __float2half(v);
    l = __float2half(v - __half2float(h));
}
// A-layout pair write: [hi | lo] at offsets off, sec+off
__device__ __forceinline__ void store2(hf* p, int off, int sec, float v) {
    hf h, l; split2h(v, h, l);
    p[off] = h; p[sec + off] = l;
}
__device__ __forceinline__ void fma2(unsigned long long &d, unsigned long long a, unsigned long long b) {
    asm("fma.rn.f32x2 %0, %1, %2, %0;" : "+l"(d) : "l"(a), "l"(b));
}
__device__ __forceinline__ unsigned long long bcast2(float x) {
    unsigned long long r;
    asm("mov.b64 %0, {%1, %1};" : "=l"(r) : "f"(x));
    return r;
}

// ================= fp16 tensor-core GEMM, 128x128x32, 2-stage reg-staged ========
// A: row-major M x Kp (hf), B: row-major Kp x N (hf). M%128==0, Kp%32==0.
// MODE 2: v=sigmoid(acc+bias[c]); c<splitN -> Cz else Cr (fp32, stride splitN)
// MODE 3: C[r*ldC+c] = tanh(acc+bias[c])     (fp32)
// MODE 4: graph-conv scatter into xg (hf pair): row=j*512+n, col=b*hd+c ->
//         xg[(n*BB+b)*(2*sec) + off_j + c] (hi/lo)
template<int MODE>
__global__ void __launch_bounds__(256)
bgemm(const hf* __restrict__ A, const hf* __restrict__ Bm, void* __restrict__ Cv,
      int M, int N, int Kp, const float* __restrict__ bias, float* __restrict__ C2,
      int splitN, int ldC, int hdshift, int sec, int o0, int o1, int o2, int o3)
{
    __shared__ __align__(16) hf As[2][128 * 40];
    __shared__ __align__(16) hf Bs[2][32 * 136];

    const int tid  = threadIdx.x;
    const int lane = tid & 31;
    const int warp = tid >> 5;
    const int wm   = warp & 1;
    const int wn   = warp >> 1;
    const int row0 = blockIdx.y * 128;
    const int col0 = blockIdx.x * 128;

    float acc[4][4][4];
    #pragma unroll
    for (int i = 0; i < 4; i++)
        #pragma unroll
        for (int j = 0; j < 4; j++)
            #pragma unroll
            for (int g = 0; g < 4; g++) acc[i][j][g] = 0.f;

    const int aq0 = tid * 2;
    const int ar0 = aq0 >> 2, ac0 = (aq0 & 3) * 8;
    const int ar1 = (aq0 + 1) >> 2, ac1 = ((aq0 + 1) & 3) * 8;
    const int br0 = aq0 >> 4, bc0 = (aq0 & 15) * 8;
    const int br1 = (aq0 + 1) >> 4, bc1 = ((aq0 + 1) & 15) * 8;
    const bool ok0 = (col0 + bc0) < N;
    const bool ok1 = (col0 + bc1) < N;

    const int T = Kp >> 5;
    int4 pa0, pa1, pb0, pb1;
    const int4 z4 = make_int4(0, 0, 0, 0);

    // prologue: tile 0
    pa0 = *(const int4*)(A + (size_t)(row0 + ar0) * Kp + ac0);
    pa1 = *(const int4*)(A + (size_t)(row0 + ar1) * Kp + ac1);
    pb0 = ok0 ? *(const int4*)(Bm + (size_t)br0 * N + col0 + bc0) : z4;
    pb1 = ok1 ? *(const int4*)(Bm + (size_t)br1 * N + col0 + bc1) : z4;
    *(int4*)&As[0][ar0 * 40 + ac0] = pa0;
    *(int4*)&As[0][ar1 * 40 + ac1] = pa1;
    *(int4*)&Bs[0][br0 * 136 + bc0] = pb0;
    *(int4*)&Bs[0][br1 * 136 + bc1] = pb1;
    __syncthreads();

    for (int kt = 0; kt < T; kt++) {
        const int cur = kt & 1;
        if (kt + 1 < T) {
            const int k0 = (kt + 1) * 32;
            pa0 = *(const int4*)(A + (size_t)(row0 + ar0) * Kp + k0 + ac0);
            pa1 = *(const int4*)(A + (size_t)(row0 + ar1) * Kp + k0 + ac1);
            pb0 = ok0 ? *(const int4*)(Bm + (size_t)(k0 + br0) * N + col0 + bc0) : z4;
            pb1 = ok1 ? *(const int4*)(Bm + (size_t)(k0 + br1) * N + col0 + bc1) : z4;
        }
        #pragma unroll
        for (int kk = 0; kk < 2; kk++) {
            unsigned af[4][4], bfg[4][2];
            #pragma unroll
            for (int i = 0; i < 4; i++) {
                const hf* p = &As[cur][(wm * 64 + i * 16 + (lane & 15)) * 40 + kk * 16 + (lane >> 4) * 8];
                unsigned addr = (unsigned)__cvta_generic_to_shared(p);
                asm volatile("ldmatrix.sync.aligned.m8n8.x4.shared.b16 {%0,%1,%2,%3}, [%4];"
                             : "=r"(af[i][0]), "=r"(af[i][1]), "=r"(af[i][2]), "=r"(af[i][3])
                             : "r"(addr));
            }
            #pragma unroll
            for (int j = 0; j < 4; j++) {
                const hf* p = &Bs[cur][(kk * 16 + (lane & 15)) * 136 + wn * 32 + j * 8];
                unsigned addr = (unsigned)__cvta_generic_to_shared(p);
                asm volatile("ldmatrix.sync.aligned.m8n8.x2.trans.shared.b16 {%0,%1}, [%2];"
                             : "=r"(bfg[j][0]), "=r"(bfg[j][1]) : "r"(addr));
            }
            #pragma unroll
            for (int i = 0; i < 4; i++)
                #pragma unroll
                for (int j = 0; j < 4; j++)
                    asm volatile(
                        "mma.sync.aligned.m16n8k16.row.col.f32.f16.f16.f32 "
                        "{%0,%1,%2,%3}, {%4,%5,%6,%7}, {%8,%9}, {%0,%1,%2,%3};"
                        : "+f"(acc[i][j][0]), "+f"(acc[i][j][1]), "+f"(acc[i][j][2]), "+f"(acc[i][j][3])
                        : "r"(af[i][0]), "r"(af[i][1]), "r"(af[i][2]), "r"(af[i][3]),
                          "r"(bfg[j][0]), "r"(bfg[j][1]));
        }
        if (kt + 1 < T) {
            const int nxt = cur ^ 1;
            *(int4*)&As[nxt][ar0 * 40 + ac0] = pa0;
            *(int4*)&As[nxt][ar1 * 40 + ac1] = pa1;
            *(int4*)&Bs[nxt][br0 * 136 + bc0] = pb0;
            *(int4*)&Bs[nxt][br1 * 136 + bc1] = pb1;
        }
        __syncthreads();
    }

    // epilogue
    if (MODE == 4) {
        hf* C = (hf*)Cv;
        const int jblk = row0 >> 9;
        const int off  = (jblk == 0) ? o0 : (jblk == 1) ? o1 : (jblk == 2) ? o2 : o3;
        const int hmask = (1 << hdshift) - 1;
        const int Ktot = 2 * sec;
        #pragma unroll
        for (int i = 0; i < 4; i++)
            #pragma unroll
            for (int j = 0; j < 4; j++)
                #pragma unroll
                for (int g = 0; g < 4; g++) {
                    int rr = row0 + wm * 64 + i * 16 + (lane >> 2) + ((g >> 1) << 3);
                    int cc = col0 + wn * 32 + j * 8 + ((lane & 3) << 1) + (g & 1);
                    if (cc < N) {
                        int n = rr & (NN - 1);
                        int b = cc >> hdshift;
                        int c = cc & hmask;
                        store2(C + (size_t)(n * BB + b) * Ktot, off + c, sec, acc[i][j][g]);
                    }
                }
    } else {
        float* C = (float*)Cv;
        #pragma unroll
        for (int i = 0; i < 4; i++)
            #pragma unroll
            for (int j = 0; j < 4; j++)
                #pragma unroll
                for (int g = 0; g < 4; g++) {
                    int rr = row0 + wm * 64 + i * 16 + (lane >> 2) + ((g >> 1) << 3);
                    int cc = col0 + wn * 32 + j * 8 + ((lane & 3) << 1) + (g & 1);
                    if (cc >= N) continue;
                    float v = acc[i][j][g];
                    if (MODE == 2) {
                        v = 1.f / (1.f + expf(-(v + bias[cc])));
                        if (cc < splitN) C [(size_t)rr * splitN + cc]            = v;
                        else             C2[(size_t)rr * splitN + (cc - splitN)] = v;
                    } else { // MODE 3
                        C[(size_t)rr * ldC + cc] = tanhf(v + bias[cc]);
                    }
                }
    }
}

// ================= fp32 f32x2 SGEMM (small GEMMs only) =====================
template<int MODE>   // MODE 0: plain, MODE 1: 2*acc - I
__global__ void __launch_bounds__(256)
sgemm(const float* __restrict__ A, const float* __restrict__ Bm, float* __restrict__ C,
      int M, int N, int K)
{
    __shared__ __align__(16) float As[2][16][132];
    __shared__ __align__(16) float Bsh[2][16][132];
    const int tid = threadIdx.x;
    const int tx  = tid & 15;
    const int ty  = tid >> 4;
    const int row0 = blockIdx.y * 128;
    const int col0 = blockIdx.x * 128;

    const int am  = tid >> 1;
    const int ak0 = (tid & 1) << 2;
    const int bk  = tid >> 5;
    const int bn  = (tid & 31) << 2;
    const int gn  = col0 + bn;
    const bool bok = gn < N;

    unsigned long long acc[8][4];
    #pragma unroll
    for (int i = 0; i < 8; i++)
        #pragma unroll
        for (int j = 0; j < 4; j++) acc[i][j] = 0ull;

    const int T = K >> 4;
    const float4 z4 = make_float4(0.f, 0.f, 0.f, 0.f);
    const float* Abase = A + (size_t)(row0 + am) * K + ak0;

    float4 ra0 = *(const float4*)(Abase);
    float4 ra1 = *(const float4*)(Abase + 8);
    float4 rb0 = bok ? *(const float4*)(Bm + (size_t)bk * N + gn) : z4;
    float4 rb1 = bok ? *(const float4*)(Bm + (size_t)(bk + 8) * N + gn) : z4;
    As[0][ak0 + 0][am] = ra0.x; As[0][ak0 + 1][am] = ra0.y;
    As[0][ak0 + 2][am] = ra0.z; As[0][ak0 + 3][am] = ra0.w;
    As[0][ak0 + 8][am] = ra1.x; As[0][ak0 + 9][am] = ra1.y;
    As[0][ak0 +10][am] = ra1.z; As[0][ak0 +11][am] = ra1.w;
    *(float4*)&Bsh[0][bk][bn]     = rb0;
    *(float4*)&Bsh[0][bk + 8][bn] = rb1;
    __syncthreads();

    for (int kt = 0; kt < T; kt++) {
        const int cur = kt & 1;
        if (kt + 1 < T) {
            const float* Ap = Abase + (kt + 1) * 16;
            ra0 = *(const float4*)(Ap);
            ra1 = *(const float4*)(Ap + 8);
            const int gk = (kt + 1) * 16;
            rb0 = bok ? *(const float4*)(Bm + (size_t)(gk + bk) * N + gn) : z4;
            rb1 = bok ? *(const float4*)(Bm + (size_t)(gk + bk + 8) * N + gn) : z4;
        }
        #pragma unroll
        for (int kk = 0; kk < 16; kk++) {
            float4 a0 = *(const float4*)&As[cur][kk][ty * 8];
            float4 a1 = *(const float4*)&As[cur][kk][ty * 8 + 4];
            ulonglong2 bp0 = *(const ulonglong2*)&Bsh[cur][kk][tx * 8];
            ulonglong2 bp1 = *(const ulonglong2*)&Bsh[cur][kk][tx * 8 + 4];
            unsigned long long b2[4] = { bp0.x, bp0.y, bp1.x, bp1.y };
            unsigned long long a2[8] = {
                bcast2(a0.x), bcast2(a0.y), bcast2(a0.z), bcast2(a0.w),
                bcast2(a1.x), bcast2(a1.y), bcast2(a1.z), bcast2(a1.w)
            };
            #pragma unroll
            for (int i = 0; i < 8; i++)
                #pragma unroll
                for (int j = 0; j < 4; j++)
                    fma2(acc[i][j], a2[i], b2[j]);
        }
        if (kt + 1 < T) {
            const int nxt = cur ^ 1;
            As[nxt][ak0 + 0][am] = ra0.x; As[nxt][ak0 + 1][am] = ra0.y;
            As[nxt][ak0 + 2][am] = ra0.z; As[nxt][ak0 + 3][am] = ra0.w;
            As[nxt][ak0 + 8][am] = ra1.x; As[nxt][ak0 + 9][am] = ra1.y;
            As[nxt][ak0 +10][am] = ra1.z; As[nxt][ak0 +11][am] = ra1.w;
            *(float4*)&Bsh[nxt][bk][bn]     = rb0;
            *(float4*)&Bsh[nxt][bk + 8][bn] = rb1;
        }
        __syncthreads();
    }

    #pragma unroll
    for (int i = 0; i < 8; i++) {
        const int r = row0 + ty * 8 + i;
        #pragma unroll
        for (int j = 0; j < 4; j++) {
            #pragma unroll
            for (int h = 0; h < 2; h++) {
                const int cc = col0 + tx * 8 + 2 * j + h;
                if (cc >= N) continue;
                float v = h ? __uint_as_float((unsigned)(acc[i][j] >> 32))
                            : __uint_as_float((unsigned)(acc[i][j]));
                if (MODE == 0) C[(size_t)r * N + cc] = v;
                else           C[(size_t)r * N + cc] = 2.f * v - ((r == cc) ? 1.f : 0.f);
            }
        }
    }
}

// ---------------- small kernels ----------------
__global__ void k_zero(float* p, int n) {
    int i = blockIdx.x * blockDim.x + threadIdx.x;
    if (i < n) p[i] = 0.f;
}

// split fp32 (M x K) -> A-layout hf (M x 2K): [hi | lo]
__global__ void k_splitA(const float* __restrict__ in, hf* __restrict__ out, int K, int total) {
    int i = blockIdx.x * blockDim.x + threadIdx.x;
    if (i >= total) return;
    int m = i / K, k = i - m * K;
    hf h, l; split2h(in[i], h, l);
    hf* p = out + (size_t)m * 2 * K;
    p[k] = h; p[K + k] = l;
}

// fp32 (Kreal x N) -> B-layout hf (2*Ksec x N): [hi | hi] (fp16-rounded operand)
__global__ void k_splitB(const float* __restrict__ in, hf* __restrict__ out,
                         int Ksec, int N, int total) {
    int i = blockIdx.x * blockDim.x + threadIdx.x;
    if (i >= total) return;
    int k = i / N, j = i - k * N;
    hf h = __float2half(in[i]);
    out[(size_t)k * N + j]          = h;
    out[(size_t)(Ksec + k) * N + j] = h;
}

__global__ void k_eW(const float* __restrict__ We, const float* __restrict__ Mem,
                     float* __restrict__ e) {
    int idx = blockIdx.x * blockDim.x + threadIdx.x;
    if (idx >= NN * 64) return;
    int n = idx >> 6, d = idx & 63;
    float s = 0.f;
    #pragma unroll
    for (int k = 0; k < 20; k++) s += We[n * 20 + k] * Mem[k * 64 + d];
    e[idx] = s;
}

__global__ void k_gsoftmax(const float* __restrict__ ea, const float* __restrict__ eb,
                           float* __restrict__ g) {
    __shared__ float er[64];
    __shared__ float buf[NN];
    __shared__ float red[128];
    int n = blockIdx.x, tid = threadIdx.x;
    if (tid < 64) er[tid] = ea[n * 64 + tid];
    __syncthreads();
    for (int m = tid; m < NN; m += 128) {
        float s = 0.f;
        #pragma unroll
        for (int d = 0; d < 64; d++) s += er[d] * eb[m * 64 + d];
        buf[m] = s > 0.f ? s : 0.f;
    }
    __syncthreads();
    float mx = -1e30f;
    for (int m = tid; m < NN; m += 128) mx = fmaxf(mx, buf[m]);
    red[tid] = mx; __syncthreads();
    for (int s = 64; s > 0; s >>= 1) { if (tid < s) red[tid] = fmaxf(red[tid], red[tid + s]); __syncthreads(); }
    mx = red[0]; __syncthreads();
    float sm = 0.f;
    for (int m = tid; m < NN; m += 128) { float e = expf(buf[m] - mx); buf[m] = e; sm += e; }
    red[tid] = sm; __syncthreads();
    for (int s = 64; s > 0; s >>= 1) { if (tid < s) red[tid] += red[tid + s]; __syncthreads(); }
    float inv = 1.f / red[0];
    for (int m = tid; m < NN; m += 128) g[n * NN + m] = buf[m] * inv;
}

__global__ void k_xT(const float* __restrict__ x, float* __restrict__ xT) {
    int idx = blockIdx.x * blockDim.x + threadIdx.x;
    if (idx >= BB * NN * LL) return;
    int l = idx % LL;
    int n = (idx / LL) % NN;
    int b = idx / (LL * NN);
    xT[(n * LL + l) * BB + b] = x[idx];
}

// fill encoder x-channels of xgE for step l (pairs)
__global__ void k_fill_enc_x(hf* __restrict__ xg, const float* __restrict__ xT,
                             const float* __restrict__ GX, int l) {
    int row = blockIdx.x * blockDim.x + threadIdx.x;
    if (row >= ROWS) return;
    int n = row >> 6, b = row & 63;
    hf* p = xg + (size_t)row * KPE;
    float xv = xT[(n * LL + l) * BB + b];
    store2(p, 0, SECE, xv);
    store2(p, 195, SECE, xv);
    store2(p, 65,  SECE, GX[(size_t)(0 * NN + n) * (LL * BB) + l * BB + b]);
    store2(p, 130, SECE, GX[(size_t)(1 * NN + n) * (LL * BB) + l * BB + b]);
    store2(p, 260, SECE, GX[(size_t)(2 * NN + n) * (LL * BB) + l * BB + b]);
    store2(p, 325, SECE, GX[(size_t)(3 * NN + n) * (LL * BB) + l * BB + b]);
}

// fill identity-support h-channels (blocks 0 and 3) as pairs
__global__ void k_fill_h_id(hf* __restrict__ xg, const float* __restrict__ h,
                            int hdshift, int sec, int off0, int off3, int total) {
    int i = blockIdx.x * blockDim.x + threadIdx.x;
    if (i >= total) return;
    int row = i >> hdshift;
    int c   = i & ((1 << hdshift) - 1);
    float v = h[i];
    hf* p = xg + (size_t)row * 2 * sec;
    store2(p, off0 + c, sec, v);
    store2(p, off3 + c, sec, v);
}

// fill decoder go + ycov channels for step t
__global__ void k_fill_dec(hf* __restrict__ xg, const float* __restrict__ go,
                           const float* __restrict__ Ggo, const float* __restrict__ tt, int t) {
    int row = blockIdx.x * blockDim.x + threadIdx.x;
    if (row >= ROWS) return;
    int n = row >> 6, b = row & 63;
    hf* p = xg + (size_t)row * KPD;
    float gv = go[row];
    store2(p, 0,   SECD, gv);
    store2(p, 402, SECD, gv);
    store2(p, 134, SECD, Ggo[(0 * NN + n) * BB + b]);
    store2(p, 268, SECD, Ggo[(1 * NN + n) * BB + b]);
    store2(p, 536, SECD, Ggo[(2 * NN + n) * BB + b]);
    store2(p, 670, SECD, Ggo[(3 * NN + n) * BB + b]);
    #pragma unroll
    for (int c = 0; c < 5; c++) {
        float v = tt[(b * 5 + c) * HH + t];
        store2(p, 1 + c,   SECD, v); store2(p, 135 + c, SECD, v);
        store2(p, 269 + c, SECD, v); store2(p, 403 + c, SECD, v);
        store2(p, 537 + c, SECD, v); store2(p, 671 + c, SECD, v);
    }
}

__global__ void k_zh(const float* __restrict__ z, const float* __restrict__ h,
                     float* __restrict__ zh, int n) {
    int i = blockIdx.x * blockDim.x + threadIdx.x;
    if (i < n) zh[i] = z[i] * h[i];
}

__global__ void k_hupd(const float* __restrict__ r, const float* __restrict__ hc,
                       float* __restrict__ h, int n) {
    int i = blockIdx.x * blockDim.x + threadIdx.x;
    if (i < n) { float rv = r[i]; h[i] = rv * h[i] + (1.f - rv) * hc[i]; }
}

__global__ void k_attn(const float* __restrict__ h, const float* __restrict__ Wq,
                       const float* __restrict__ Mem, float* __restrict__ hde) {
    __shared__ float hr[64];
    __shared__ float q[64];
    __shared__ float sc[20];
    int row = blockIdx.x, tid = threadIdx.x;
    hr[tid] = h[row * 64 + tid];
    __syncthreads();
    float s = 0.f;
    #pragma unroll
    for (int c = 0; c < 64; c++) s += hr[c] * Wq[c * 64 + tid];
    q[tid] = s;
    __syncthreads();
    if (tid < 20) {
        float v = 0.f;
        #pragma unroll
        for (int c = 0; c < 64; c++) v += q[c] * Mem[tid * 64 + c];
        sc[tid] = v;
    }
    __syncthreads();
    if (tid == 0) {
        float mx = -1e30f;
        for (int j = 0; j < 20; j++) mx = fmaxf(mx, sc[j]);
        float sm = 0.f;
        for (int j = 0; j < 20; j++) { sc[j] = expf(sc[j] - mx); sm += sc[j]; }
        float inv = 1.f / sm;
        for (int j = 0; j < 20; j++) sc[j] *= inv;
    }
    __syncthreads();
    float ha = 0.f;
    #pragma unroll
    for (int j = 0; j < 20; j++) ha += sc[j] * Mem[j * 64 + tid];
    hde[row * 128 + tid]      = hr[tid];
    hde[row * 128 + 64 + tid] = ha;
}

__global__ void k_hupd_dec(const float* __restrict__ r, const float* __restrict__ hc,
                           float* __restrict__ h, const float* __restrict__ pW,
                           const float* __restrict__ pb, float* __restrict__ go,
                           float* __restrict__ out, int t) {
    __shared__ float red[128];
    int row = blockIdx.x, c = threadIdx.x;
    int i = row * 128 + c;
    float rv = r[i];
    float hn = rv * h[i] + (1.f - rv) * hc[i];
    h[i] = hn;
    red[c] = hn * pW[c];
    __syncthreads();
    for (int s = 64; s > 0; s >>= 1) { if (c < s) red[c] += red[c + s]; __syncthreads(); }
    if (c == 0) {
        float g = red[0] + pb[0];
        go[row] = g;
        int n = row >> 6, b = row & 63;
        out[(b * NN + n) * HH + t] = g;
    }
}

// ---------------- host side ----------------
static void bgemm_launch(int mode, const hf* A, const hf* B, void* C,
                         int M, int N, int Kp,
                         const float* bias = nullptr, float* C2 = nullptr,
                         int splitN = 0, int ldC = 0, int hdshift = 0, int sec = 0,
                         int o0 = 0, int o1 = 0, int o2 = 0, int o3 = 0)
{
    dim3 grid((N + 127) / 128, M / 128);
    switch (mode) {
        case 2: bgemm<2><<<grid, 256>>>(A, B, C, M, N, Kp, bias, C2, splitN, ldC, hdshift, sec, o0, o1, o2, o3); break;
        case 3: bgemm<3><<<grid, 256>>>(A, B, C, M, N, Kp, bias, C2, splitN, ldC, hdshift, sec, o0, o1, o2, o3); break;
        case 4: bgemm<4><<<grid, 256>>>(A, B, C, M, N, Kp, bias, C2, splitN, ldC, hdshift, sec, o0, o1, o2, o3); break;
    }
}

extern "C" void kernel_launch(void* const* d_in, const int* in_sizes, int n_in,
                              void* d_out, int out_size)
{
    const float* x   = (const float*)d_in[0];
    const float* tt  = (const float*)d_in[3];
    const float* Mem = (const float*)d_in[5];
    const float* Wq  = (const float*)d_in[6];
    const float* We1 = (const float*)d_in[7];
    const float* We2 = (const float*)d_in[8];
    const float* egW = (const float*)d_in[9];
    const float* egb = (const float*)d_in[10];
    const float* euW = (const float*)d_in[11];
    const float* eub = (const float*)d_in[12];
    const float* dgW = (const float*)d_in[13];
    const float* dgb = (const float*)d_in[14];
    const float* duW = (const float*)d_in[15];
    const float* dub = (const float*)d_in[16];
    const float* pW  = (const float*)d_in[17];
    const float* pb  = (const float*)d_in[18];
    float* out = (float*)d_out;

    float *S, *e1, *e2, *xT, *GX, *henc, *hdec, *z, *r, *hc, *zh, *go, *Ggo;
    hf *Sbig, *hB, *xgE, *xgD, *egWB, *euWB, *dgWB, *duWB;
    cudaGetSymbolAddress((void**)&S,    g_S);
    cudaGetSymbolAddress((void**)&e1,   g_e1);
    cudaGetSymbolAddress((void**)&e2,   g_e2);
    cudaGetSymbolAddress((void**)&xT,   g_xT);
    cudaGetSymbolAddress((void**)&GX,   g_GX);
    cudaGetSymbolAddress((void**)&henc, g_henc);
    cudaGetSymbolAddress((void**)&hdec, g_hdec);
    cudaGetSymbolAddress((void**)&z,    g_z);
    cudaGetSymbolAddress((void**)&r,    g_r);
    cudaGetSymbolAddress((void**)&hc,   g_hc);
    cudaGetSymbolAddress((void**)&zh,   g_zh);
    cudaGetSymbolAddress((void**)&go,   g_go);
    cudaGetSymbolAddress((void**)&Ggo,  g_Ggo);
    cudaGetSymbolAddress((void**)&Sbig, g_Sbig);
    cudaGetSymbolAddress((void**)&hB,   g_hB);
    cudaGetSymbolAddress((void**)&xgE,  g_xgE);
    cudaGetSymbolAddress((void**)&xgD,  g_xgD);
    cudaGetSymbolAddress((void**)&egWB, g_egWB);
    cudaGetSymbolAddress((void**)&euWB, g_euWB);
    cudaGetSymbolAddress((void**)&dgWB, g_dgWB);
    cudaGetSymbolAddress((void**)&duWB, g_duWB);

    // --- weight splits (pad rows of big buffers stay zero) ---
    k_splitB<<<(KENC * 128 + 255) / 256, 256>>>(egW, egWB, SECE, 128, KENC * 128);
    k_splitB<<<(KENC * 64  + 255) / 256, 256>>>(euW, euWB, SECE, 64,  KENC * 64);
    k_splitB<<<(KDEC * 256 + 255) / 256, 256>>>(dgW, dgWB, SECD, 256, KDEC * 256);
    k_splitB<<<(KDEC * 128 + 255) / 256, 256>>>(duW, duWB, SECD, 128, KDEC * 128);

    // --- supports (fp32) ---
    k_eW<<<(NN * 64 + 255) / 256, 256>>>(We1, Mem, e1);
    k_eW<<<(NN * 64 + 255) / 256, 256>>>(We2, Mem, e2);
    k_gsoftmax<<<NN, 128>>>(e1, e2, S);
    k_gsoftmax<<<NN, 128>>>(e2, e1, S + 2 * NN * NN);
    {
        dim3 g1(NN / 128, NN / 128);
        sgemm<1><<<g1, 256>>>(S,               S,               S + 1 * NN * NN, NN, NN, NN);
        sgemm<1><<<g1, 256>>>(S + 2 * NN * NN, S + 2 * NN * NN, S + 3 * NN * NN, NN, NN, NN);
    }
    k_splitA<<<(4 * NN * NN + 255) / 256, 256>>>(S, Sbig, NN, 4 * NN * NN);

    // --- encoder x precompute (fp32) ---
    k_xT<<<(BB * NN * LL + 255) / 256, 256>>>(x, xT);
    {
        dim3 g2((LL * BB + 127) / 128, 4 * NN / 128);
        sgemm<0><<<g2, 256>>>(S, xT, GX, 4 * NN, LL * BB, NN);
    }

    // --- init states ---
    k_zero<<<(ROWS * RNN + 255) / 256, 256>>>(henc, ROWS * RNN);
    k_zero<<<(ROWS + 255) / 256, 256>>>(go, ROWS);

    // --- encoder ---
    for (int l = 0; l < LL; l++) {
        k_fill_enc_x<<<ROWS / 256, 256>>>(xgE, xT, GX, l);
        k_fill_h_id<<<(ROWS * RNN) / 256, 256>>>(xgE, henc, 6, SECE, 1, 196, ROWS * RNN);
        k_splitB<<<(ROWS * RNN + 255) / 256, 256>>>(henc, hB, NN, BB * RNN, ROWS * RNN);
        bgemm_launch(4, Sbig, hB, xgE, 4 * NN, BB * RNN, KGC,
                     nullptr, nullptr, 0, 0, 6, SECE, 66, 131, 261, 326);
        bgemm_launch(2, xgE, egWB, z, ROWS, 2 * RNN, KPE, egb, r, RNN);
        k_zh<<<(ROWS * RNN) / 256, 256>>>(z, henc, zh, ROWS * RNN);
        k_fill_h_id<<<(ROWS * RNN) / 256, 256>>>(xgE, zh, 6, SECE, 1, 196, ROWS * RNN);
        k_splitB<<<(ROWS * RNN + 255) / 256, 256>>>(zh, hB, NN, BB * RNN, ROWS * RNN);
        bgemm_launch(4, Sbig, hB, xgE, 4 * NN, BB * RNN, KGC,
                     nullptr, nullptr, 0, 0, 6, SECE, 66, 131, 261, 326);
        bgemm_launch(3, xgE, euWB, hc, ROWS, RNN, KPE, eub, nullptr, 0, RNN);
        k_hupd<<<(ROWS * RNN) / 256, 256>>>(r, hc, henc, ROWS * RNN);
    }

    // --- memory attention -> decoder initial hidden ---
    k_attn<<<ROWS, 64>>>(henc, Wq, Mem, hdec);

    // --- decoder ---
    for (int t = 0; t < HH; t++) {
        {
            dim3 g3(1, 4 * NN / 128);
            sgemm<0><<<g3, 256>>>(S, go, Ggo, 4 * NN, BB, NN);
        }
        k_fill_dec<<<ROWS / 256, 256>>>(xgD, go, Ggo, tt, t);
        k_fill_h_id<<<(ROWS * DDEC) / 256, 256>>>(xgD, hdec, 7, SECD, 6, 408, ROWS * DDEC);
        k_splitB<<<(ROWS * DDEC + 255) / 256, 256>>>(hdec, hB, NN, BB * DDEC, ROWS * DDEC);
        bgemm_launch(4, Sbig, hB, xgD, 4 * NN, BB * DDEC, KGC,
                     nullptr, nullptr, 0, 0, 7, SECD, 140, 274, 542, 676);
        bgemm_launch(2, xgD, dgWB, z, ROWS, 2 * DDEC, KPD, dgb, r, DDEC);
        k_zh<<<(ROWS * DDEC) / 256, 256>>>(z, hdec, zh, ROWS * DDEC);
        k_fill_h_id<<<(ROWS * DDEC) / 256, 256>>>(xgD, zh, 7, SECD, 6, 408, ROWS * DDEC);
        k_splitB<<<(ROWS * DDEC + 255) / 256, 256>>>(zh, hB, NN, BB * DDEC, ROWS * DDEC);
        bgemm_launch(4, Sbig, hB, xgD, 4 * NN, BB * DDEC, KGC,
                     nullptr, nullptr, 0, 0, 7, SECD, 140, 274, 542, 676);
        bgemm_launch(3, xgD, duWB, hc, ROWS, DDEC, KPD, dub, nullptr, 0, DDEC);
        k_hupd_dec<<<ROWS, 128>>>(r, hc, hdec, pW, pb, go, out, t);
    }
}

// round 8
// speedup vs baseline: 1.8389x; 1.0373x over previous
#include <cuda_runtime.h>
#include <cuda_fp16.h>
#include <math.h>

// ---------------- problem constants ----------------
#define NN   512
#define BB   64
#define LL   12
#define HH   12
#define RNN  64
#define DDEC 128
#define KENC 390        // logical enc feature count
#define KDEC 804        // logical dec feature count
#define SECE 416        // enc section (pad to /32)
#define SECD 832        // dec section
#define KPE  (2*SECE)   // 832
#define KPD  (2*SECD)   // 1664
#define KGC  (2*NN)     // 1024 (graph conv K')
#define ROWS (NN*BB)    // 32768

typedef __half hf;

// ---------------- scratch (device globals; zero-init, no allocation) ----------------
__device__ float g_S[4*NN*NN];
__device__ float g_e1[NN*64];
__device__ float g_e2[NN*64];
__device__ float g_xT[NN*LL*BB];
__device__ float g_GX[4*NN*LL*BB];
__device__ float g_henc[ROWS*RNN];
__device__ float g_hdec[ROWS*DDEC];
__device__ float g_z [ROWS*DDEC];
__device__ float g_r [ROWS*DDEC];
__device__ float g_hc[ROWS*DDEC];
__device__ float g_go[ROWS];
__device__ float g_Ggo[4*NN*BB];
// fp16 2-term split operands
__device__ hf g_Sbig [4*NN*KGC];       // A: [hi|lo], 2048 x 1024
__device__ hf g_hB   [KGC*BB*DDEC];    // B: [hi|hi], up to 1024 x 8192
__device__ hf g_xgE  [ROWS*KPE];       // enc feature A (pads stay 0)
__device__ hf g_xgD  [ROWS*KPD];       // dec feature A
__device__ hf g_egWB [KPE*128];
__device__ hf g_euWB [KPE*64];
__device__ hf g_dgWB [KPD*256];
__device__ hf g_duWB [KPD*128];

// ---------------- helpers ----------------
__device__ __forceinline__ void split2h(float v, hf &h, hf &l) {
    h = __float2half(v);
    l = __float2half(v - __half2float(h));
}
// A-layout pair write: [hi | lo] at offsets off, sec+off
__device__ __forceinline__ void store2(hf* p, int off, int sec, float v) {
    hf h, l; split2h(v, h, l);
    p[off] = h; p[sec + off] = l;
}
__device__ __forceinline__ void fma2(unsigned long long &d, unsigned long long a, unsigned long long b) {
    asm("fma.rn.f32x2 %0, %1, %2, %0;" : "+l"(d) : "l"(a), "l"(b));
}
__device__ __forceinline__ unsigned long long bcast2(float x) {
    unsigned long long r;
    asm("mov.b64 %0, {%1, %1};" : "=l"(r) : "f"(x));
    return r;
}

// ================= fp16 tensor-core GEMM, 128x128x32, 2-stage reg-staged ========
// A: row-major M x Kp (hf), B: row-major Kp x N (hf). M%128==0, Kp%32==0.
// MODE 2: v=sigmoid(acc+bias[c]); c<splitN -> Cz else Cr (fp32, stride splitN)
// MODE 3: C[r*ldC+c] = tanh(acc+bias[c])     (fp32)
// MODE 4: graph-conv scatter into xg (hf pair): row=j*512+n, col=b*hd+c ->
//         xg[(n*BB+b)*(2*sec) + off_j + c] (hi/lo)
template<int MODE>
__global__ void __launch_bounds__(256)
bgemm(const hf* __restrict__ A, const hf* __restrict__ Bm, void* __restrict__ Cv,
      int M, int N, int Kp, const float* __restrict__ bias, float* __restrict__ C2,
      int splitN, int ldC, int hdshift, int sec, int o0, int o1, int o2, int o3)
{
    __shared__ __align__(16) hf As[2][128 * 40];
    __shared__ __align__(16) hf Bs[2][32 * 136];

    const int tid  = threadIdx.x;
    const int lane = tid & 31;
    const int warp = tid >> 5;
    const int wm   = warp & 1;
    const int wn   = warp >> 1;
    const int row0 = blockIdx.y * 128;
    const int col0 = blockIdx.x * 128;

    float acc[4][4][4];
    #pragma unroll
    for (int i = 0; i < 4; i++)
        #pragma unroll
        for (int j = 0; j < 4; j++)
            #pragma unroll
            for (int g = 0; g < 4; g++) acc[i][j][g] = 0.f;

    const int aq0 = tid * 2;
    const int ar0 = aq0 >> 2, ac0 = (aq0 & 3) * 8;
    const int ar1 = (aq0 + 1) >> 2, ac1 = ((aq0 + 1) & 3) * 8;
    const int br0 = aq0 >> 4, bc0 = (aq0 & 15) * 8;
    const int br1 = (aq0 + 1) >> 4, bc1 = ((aq0 + 1) & 15) * 8;
    const bool ok0 = (col0 + bc0) < N;
    const bool ok1 = (col0 + bc1) < N;

    const int T = Kp >> 5;
    int4 pa0, pa1, pb0, pb1;
    const int4 z4 = make_int4(0, 0, 0, 0);

    // prologue: tile 0
    pa0 = *(const int4*)(A + (size_t)(row0 + ar0) * Kp + ac0);
    pa1 = *(const int4*)(A + (size_t)(row0 + ar1) * Kp + ac1);
    pb0 = ok0 ? *(const int4*)(Bm + (size_t)br0 * N + col0 + bc0) : z4;
    pb1 = ok1 ? *(const int4*)(Bm + (size_t)br1 * N + col0 + bc1) : z4;
    *(int4*)&As[0][ar0 * 40 + ac0] = pa0;
    *(int4*)&As[0][ar1 * 40 + ac1] = pa1;
    *(int4*)&Bs[0][br0 * 136 + bc0] = pb0;
    *(int4*)&Bs[0][br1 * 136 + bc1] = pb1;
    __syncthreads();

    for (int kt = 0; kt < T; kt++) {
        const int cur = kt & 1;
        if (kt + 1 < T) {
            const int k0 = (kt + 1) * 32;
            pa0 = *(const int4*)(A + (size_t)(row0 + ar0) * Kp + k0 + ac0);
            pa1 = *(const int4*)(A + (size_t)(row0 + ar1) * Kp + k0 + ac1);
            pb0 = ok0 ? *(const int4*)(Bm + (size_t)(k0 + br0) * N + col0 + bc0) : z4;
            pb1 = ok1 ? *(const int4*)(Bm + (size_t)(k0 + br1) * N + col0 + bc1) : z4;
        }
        #pragma unroll
        for (int kk = 0; kk < 2; kk++) {
            unsigned af[4][4], bfg[4][2];
            #pragma unroll
            for (int i = 0; i < 4; i++) {
                const hf* p = &As[cur][(wm * 64 + i * 16 + (lane & 15)) * 40 + kk * 16 + (lane >> 4) * 8];
                unsigned addr = (unsigned)__cvta_generic_to_shared(p);
                asm volatile("ldmatrix.sync.aligned.m8n8.x4.shared.b16 {%0,%1,%2,%3}, [%4];"
                             : "=r"(af[i][0]), "=r"(af[i][1]), "=r"(af[i][2]), "=r"(af[i][3])
                             : "r"(addr));
            }
            #pragma unroll
            for (int j = 0; j < 4; j++) {
                const hf* p = &Bs[cur][(kk * 16 + (lane & 15)) * 136 + wn * 32 + j * 8];
                unsigned addr = (unsigned)__cvta_generic_to_shared(p);
                asm volatile("ldmatrix.sync.aligned.m8n8.x2.trans.shared.b16 {%0,%1}, [%2];"
                             : "=r"(bfg[j][0]), "=r"(bfg[j][1]) : "r"(addr));
            }
            #pragma unroll
            for (int i = 0; i < 4; i++)
                #pragma unroll
                for (int j = 0; j < 4; j++)
                    asm volatile(
                        "mma.sync.aligned.m16n8k16.row.col.f32.f16.f16.f32 "
                        "{%0,%1,%2,%3}, {%4,%5,%6,%7}, {%8,%9}, {%0,%1,%2,%3};"
                        : "+f"(acc[i][j][0]), "+f"(acc[i][j][1]), "+f"(acc[i][j][2]), "+f"(acc[i][j][3])
                        : "r"(af[i][0]), "r"(af[i][1]), "r"(af[i][2]), "r"(af[i][3]),
                          "r"(bfg[j][0]), "r"(bfg[j][1]));
        }
        if (kt + 1 < T) {
            const int nxt = cur ^ 1;
            *(int4*)&As[nxt][ar0 * 40 + ac0] = pa0;
            *(int4*)&As[nxt][ar1 * 40 + ac1] = pa1;
            *(int4*)&Bs[nxt][br0 * 136 + bc0] = pb0;
            *(int4*)&Bs[nxt][br1 * 136 + bc1] = pb1;
        }
        __syncthreads();
    }

    // epilogue
    if (MODE == 4) {
        hf* C = (hf*)Cv;
        const int jblk = row0 >> 9;
        const int off  = (jblk == 0) ? o0 : (jblk == 1) ? o1 : (jblk == 2) ? o2 : o3;
        const int hmask = (1 << hdshift) - 1;
        const int Ktot = 2 * sec;
        #pragma unroll
        for (int i = 0; i < 4; i++)
            #pragma unroll
            for (int j = 0; j < 4; j++)
                #pragma unroll
                for (int g = 0; g < 4; g++) {
                    int rr = row0 + wm * 64 + i * 16 + (lane >> 2) + ((g >> 1) << 3);
                    int cc = col0 + wn * 32 + j * 8 + ((lane & 3) << 1) + (g & 1);
                    if (cc < N) {
                        int n = rr & (NN - 1);
                        int b = cc >> hdshift;
                        int c = cc & hmask;
                        store2(C + (size_t)(n * BB + b) * Ktot, off + c, sec, acc[i][j][g]);
                    }
                }
    } else {
        float* C = (float*)Cv;
        #pragma unroll
        for (int i = 0; i < 4; i++)
            #pragma unroll
            for (int j = 0; j < 4; j++)
                #pragma unroll
                for (int g = 0; g < 4; g++) {
                    int rr = row0 + wm * 64 + i * 16 + (lane >> 2) + ((g >> 1) << 3);
                    int cc = col0 + wn * 32 + j * 8 + ((lane & 3) << 1) + (g & 1);
                    if (cc >= N) continue;
                    float v = acc[i][j][g];
                    if (MODE == 2) {
                        v = 1.f / (1.f + expf(-(v + bias[cc])));
                        if (cc < splitN) C [(size_t)rr * splitN + cc]            = v;
                        else             C2[(size_t)rr * splitN + (cc - splitN)] = v;
                    } else { // MODE 3
                        C[(size_t)rr * ldC + cc] = tanhf(v + bias[cc]);
                    }
                }
    }
}

// ================= fp32 f32x2 SGEMM (small GEMMs only) =====================
template<int MODE>   // MODE 0: plain, MODE 1: 2*acc - I
__global__ void __launch_bounds__(256)
sgemm(const float* __restrict__ A, const float* __restrict__ Bm, float* __restrict__ C,
      int M, int N, int K)
{
    __shared__ __align__(16) float As[2][16][132];
    __shared__ __align__(16) float Bsh[2][16][132];
    const int tid = threadIdx.x;
    const int tx  = tid & 15;
    const int ty  = tid >> 4;
    const int row0 = blockIdx.y * 128;
    const int col0 = blockIdx.x * 128;

    const int am  = tid >> 1;
    const int ak0 = (tid & 1) << 2;
    const int bk  = tid >> 5;
    const int bn  = (tid & 31) << 2;
    const int gn  = col0 + bn;
    const bool bok = gn < N;

    unsigned long long acc[8][4];
    #pragma unroll
    for (int i = 0; i < 8; i++)
        #pragma unroll
        for (int j = 0; j < 4; j++) acc[i][j] = 0ull;

    const int T = K >> 4;
    const float4 z4 = make_float4(0.f, 0.f, 0.f, 0.f);
    const float* Abase = A + (size_t)(row0 + am) * K + ak0;

    float4 ra0 = *(const float4*)(Abase);
    float4 ra1 = *(const float4*)(Abase + 8);
    float4 rb0 = bok ? *(const float4*)(Bm + (size_t)bk * N + gn) : z4;
    float4 rb1 = bok ? *(const float4*)(Bm + (size_t)(bk + 8) * N + gn) : z4;
    As[0][ak0 + 0][am] = ra0.x; As[0][ak0 + 1][am] = ra0.y;
    As[0][ak0 + 2][am] = ra0.z; As[0][ak0 + 3][am] = ra0.w;
    As[0][ak0 + 8][am] = ra1.x; As[0][ak0 + 9][am] = ra1.y;
    As[0][ak0 +10][am] = ra1.z; As[0][ak0 +11][am] = ra1.w;
    *(float4*)&Bsh[0][bk][bn]     = rb0;
    *(float4*)&Bsh[0][bk + 8][bn] = rb1;
    __syncthreads();

    for (int kt = 0; kt < T; kt++) {
        const int cur = kt & 1;
        if (kt + 1 < T) {
            const float* Ap = Abase + (kt + 1) * 16;
            ra0 = *(const float4*)(Ap);
            ra1 = *(const float4*)(Ap + 8);
            const int gk = (kt + 1) * 16;
            rb0 = bok ? *(const float4*)(Bm + (size_t)(gk + bk) * N + gn) : z4;
            rb1 = bok ? *(const float4*)(Bm + (size_t)(gk + bk + 8) * N + gn) : z4;
        }
        #pragma unroll
        for (int kk = 0; kk < 16; kk++) {
            float4 a0 = *(const float4*)&As[cur][kk][ty * 8];
            float4 a1 = *(const float4*)&As[cur][kk][ty * 8 + 4];
            ulonglong2 bp0 = *(const ulonglong2*)&Bsh[cur][kk][tx * 8];
            ulonglong2 bp1 = *(const ulonglong2*)&Bsh[cur][kk][tx * 8 + 4];
            unsigned long long b2[4] = { bp0.x, bp0.y, bp1.x, bp1.y };
            unsigned long long a2[8] = {
                bcast2(a0.x), bcast2(a0.y), bcast2(a0.z), bcast2(a0.w),
                bcast2(a1.x), bcast2(a1.y), bcast2(a1.z), bcast2(a1.w)
            };
            #pragma unroll
            for (int i = 0; i < 8; i++)
                #pragma unroll
                for (int j = 0; j < 4; j++)
                    fma2(acc[i][j], a2[i], b2[j]);
        }
        if (kt + 1 < T) {
            const int nxt = cur ^ 1;
            As[nxt][ak0 + 0][am] = ra0.x; As[nxt][ak0 + 1][am] = ra0.y;
            As[nxt][ak0 + 2][am] = ra0.z; As[nxt][ak0 + 3][am] = ra0.w;
            As[nxt][ak0 + 8][am] = ra1.x; As[nxt][ak0 + 9][am] = ra1.y;
            As[nxt][ak0 +10][am] = ra1.z; As[nxt][ak0 +11][am] = ra1.w;
            *(float4*)&Bsh[nxt][bk][bn]     = rb0;
            *(float4*)&Bsh[nxt][bk + 8][bn] = rb1;
        }
        __syncthreads();
    }

    #pragma unroll
    for (int i = 0; i < 8; i++) {
        const int r = row0 + ty * 8 + i;
        #pragma unroll
        for (int j = 0; j < 4; j++) {
            #pragma unroll
            for (int h = 0; h < 2; h++) {
                const int cc = col0 + tx * 8 + 2 * j + h;
                if (cc >= N) continue;
                float v = h ? __uint_as_float((unsigned)(acc[i][j] >> 32))
                            : __uint_as_float((unsigned)(acc[i][j]));
                if (MODE == 0) C[(size_t)r * N + cc] = v;
                else           C[(size_t)r * N + cc] = 2.f * v - ((r == cc) ? 1.f : 0.f);
            }
        }
    }
}

// ---------------- small kernels ----------------
__global__ void k_zero(float* p, int n) {
    int i = blockIdx.x * blockDim.x + threadIdx.x;
    if (i < n) p[i] = 0.f;
}

// split fp32 (M x K) -> A-layout hf (M x 2K): [hi | lo]
__global__ void k_splitA(const float* __restrict__ in, hf* __restrict__ out, int K, int total) {
    int i = blockIdx.x * blockDim.x + threadIdx.x;
    if (i >= total) return;
    int m = i / K, k = i - m * K;
    hf h, l; split2h(in[i], h, l);
    hf* p = out + (size_t)m * 2 * K;
    p[k] = h; p[K + k] = l;
}

// fp32 (Kreal x N) -> B-layout hf (2*Ksec x N): [hi | hi] (fp16-rounded operand)
__global__ void k_splitB(const float* __restrict__ in, hf* __restrict__ out,
                         int Ksec, int N, int total) {
    int i = blockIdx.x * blockDim.x + threadIdx.x;
    if (i >= total) return;
    int k = i / N, j = i - k * N;
    hf h = __float2half(in[i]);
    out[(size_t)k * N + j]          = h;
    out[(size_t)(Ksec + k) * N + j] = h;
}

__global__ void k_eW(const float* __restrict__ We, const float* __restrict__ Mem,
                     float* __restrict__ e) {
    int idx = blockIdx.x * blockDim.x + threadIdx.x;
    if (idx >= NN * 64) return;
    int n = idx >> 6, d = idx & 63;
    float s = 0.f;
    #pragma unroll
    for (int k = 0; k < 20; k++) s += We[n * 20 + k] * Mem[k * 64 + d];
    e[idx] = s;
}

__global__ void k_gsoftmax(const float* __restrict__ ea, const float* __restrict__ eb,
                           float* __restrict__ g) {
    __shared__ float er[64];
    __shared__ float buf[NN];
    __shared__ float red[128];
    int n = blockIdx.x, tid = threadIdx.x;
    if (tid < 64) er[tid] = ea[n * 64 + tid];
    __syncthreads();
    for (int m = tid; m < NN; m += 128) {
        float s = 0.f;
        #pragma unroll
        for (int d = 0; d < 64; d++) s += er[d] * eb[m * 64 + d];
        buf[m] = s > 0.f ? s : 0.f;
    }
    __syncthreads();
    float mx = -1e30f;
    for (int m = tid; m < NN; m += 128) mx = fmaxf(mx, buf[m]);
    red[tid] = mx; __syncthreads();
    for (int s = 64; s > 0; s >>= 1) { if (tid < s) red[tid] = fmaxf(red[tid], red[tid + s]); __syncthreads(); }
    mx = red[0]; __syncthreads();
    float sm = 0.f;
    for (int m = tid; m < NN; m += 128) { float e = expf(buf[m] - mx); buf[m] = e; sm += e; }
    red[tid] = sm; __syncthreads();
    for (int s = 64; s > 0; s >>= 1) { if (tid < s) red[tid] += red[tid + s]; __syncthreads(); }
    float inv = 1.f / red[0];
    for (int m = tid; m < NN; m += 128) g[n * NN + m] = buf[m] * inv;
}

__global__ void k_xT(const float* __restrict__ x, float* __restrict__ xT) {
    int idx = blockIdx.x * blockDim.x + threadIdx.x;
    if (idx >= BB * NN * LL) return;
    int l = idx % LL;
    int n = (idx / LL) % NN;
    int b = idx / (LL * NN);
    xT[(n * LL + l) * BB + b] = x[idx];
}

// fill encoder x-channels of xgE for step l (pairs)
__global__ void k_fill_enc_x(hf* __restrict__ xg, const float* __restrict__ xT,
                             const float* __restrict__ GX, int l) {
    int row = blockIdx.x * blockDim.x + threadIdx.x;
    if (row >= ROWS) return;
    int n = row >> 6, b = row & 63;
    hf* p = xg + (size_t)row * KPE;
    float xv = xT[(n * LL + l) * BB + b];
    store2(p, 0, SECE, xv);
    store2(p, 195, SECE, xv);
    store2(p, 65,  SECE, GX[(size_t)(0 * NN + n) * (LL * BB) + l * BB + b]);
    store2(p, 130, SECE, GX[(size_t)(1 * NN + n) * (LL * BB) + l * BB + b]);
    store2(p, 260, SECE, GX[(size_t)(2 * NN + n) * (LL * BB) + l * BB + b]);
    store2(p, 325, SECE, GX[(size_t)(3 * NN + n) * (LL * BB) + l * BB + b]);
}

// fill identity-support h-channels (blocks 0 and 3) as pairs (init only)
__global__ void k_fill_h_id(hf* __restrict__ xg, const float* __restrict__ h,
                            int hdshift, int sec, int off0, int off3, int total) {
    int i = blockIdx.x * blockDim.x + threadIdx.x;
    if (i >= total) return;
    int row = i >> hdshift;
    int c   = i & ((1 << hdshift) - 1);
    float v = h[i];
    hf* p = xg + (size_t)row * 2 * sec;
    store2(p, off0 + c, sec, v);
    store2(p, off3 + c, sec, v);
}

// FUSED: zh = z*h -> xg id-blocks (pairs) + hB ([hi|hi])
__global__ void k_zh_pack(const float* __restrict__ z, const float* __restrict__ h,
                          hf* __restrict__ xg, hf* __restrict__ hB,
                          int hdshift, int sec, int off0, int off3, int total) {
    int i = blockIdx.x * blockDim.x + threadIdx.x;
    if (i >= total) return;
    int row = i >> hdshift;
    int c   = i & ((1 << hdshift) - 1);
    float v = z[i] * h[i];
    hf* p = xg + (size_t)row * 2 * sec;
    store2(p, off0 + c, sec, v);
    store2(p, off3 + c, sec, v);
    int n = row >> 6, b = row & 63;
    int Ncols = BB << hdshift;
    size_t col = ((size_t)b << hdshift) + c;
    hf hv = __float2half(v);
    hB[(size_t)n * Ncols + col]        = hv;
    hB[(size_t)(NN + n) * Ncols + col] = hv;
}

// FUSED: h' = r*h+(1-r)*hc -> h, xg id-blocks, hB  (encoder)
__global__ void k_hupd_pack(const float* __restrict__ r, const float* __restrict__ hc,
                            float* __restrict__ h,
                            hf* __restrict__ xg, hf* __restrict__ hB,
                            int hdshift, int sec, int off0, int off3, int total) {
    int i = blockIdx.x * blockDim.x + threadIdx.x;
    if (i >= total) return;
    int row = i >> hdshift;
    int c   = i & ((1 << hdshift) - 1);
    float rv = r[i];
    float hn = rv * h[i] + (1.f - rv) * hc[i];
    h[i] = hn;
    hf* p = xg + (size_t)row * 2 * sec;
    store2(p, off0 + c, sec, hn);
    store2(p, off3 + c, sec, hn);
    int n = row >> 6, b = row & 63;
    int Ncols = BB << hdshift;
    size_t col = ((size_t)b << hdshift) + c;
    hf hv = __float2half(hn);
    hB[(size_t)n * Ncols + col]        = hv;
    hB[(size_t)(NN + n) * Ncols + col] = hv;
}

// fill decoder go + ycov channels for step t
__global__ void k_fill_dec(hf* __restrict__ xg, const float* __restrict__ go,
                           const float* __restrict__ Ggo, const float* __restrict__ tt, int t) {
    int row = blockIdx.x * blockDim.x + threadIdx.x;
    if (row >= ROWS) return;
    int n = row >> 6, b = row & 63;
    hf* p = xg + (size_t)row * KPD;
    float gv = go[row];
    store2(p, 0,   SECD, gv);
    store2(p, 402, SECD, gv);
    store2(p, 134, SECD, Ggo[(0 * NN + n) * BB + b]);
    store2(p, 268, SECD, Ggo[(1 * NN + n) * BB + b]);
    store2(p, 536, SECD, Ggo[(2 * NN + n) * BB + b]);
    store2(p, 670, SECD, Ggo[(3 * NN + n) * BB + b]);
    #pragma unroll
    for (int c = 0; c < 5; c++) {
        float v = tt[(b * 5 + c) * HH + t];
        store2(p, 1 + c,   SECD, v); store2(p, 135 + c, SECD, v);
        store2(p, 269 + c, SECD, v); store2(p, 403 + c, SECD, v);
        store2(p, 537 + c, SECD, v); store2(p, 671 + c, SECD, v);
    }
}

__global__ void k_attn(const float* __restrict__ h, const float* __restrict__ Wq,
                       const float* __restrict__ Mem, float* __restrict__ hde) {
    __shared__ float hr[64];
    __shared__ float q[64];
    __shared__ float sc[20];
    int row = blockIdx.x, tid = threadIdx.x;
    hr[tid] = h[row * 64 + tid];
    __syncthreads();
    float s = 0.f;
    #pragma unroll
    for (int c = 0; c < 64; c++) s += hr[c] * Wq[c * 64 + tid];
    q[tid] = s;
    __syncthreads();
    if (tid < 20) {
        float v = 0.f;
        #pragma unroll
        for (int c = 0; c < 64; c++) v += q[c] * Mem[tid * 64 + c];
        sc[tid] = v;
    }
    __syncthreads();
    if (tid == 0) {
        float mx = -1e30f;
        for (int j = 0; j < 20; j++) mx = fmaxf(mx, sc[j]);
        float sm = 0.f;
        for (int j = 0; j < 20; j++) { sc[j] = expf(sc[j] - mx); sm += sc[j]; }
        float inv = 1.f / sm;
        for (int j = 0; j < 20; j++) sc[j] *= inv;
    }
    __syncthreads();
    float ha = 0.f;
    #pragma unroll
    for (int j = 0; j < 20; j++) ha += sc[j] * Mem[j * 64 + tid];
    hde[row * 128 + tid]      = hr[tid];
    hde[row * 128 + 64 + tid] = ha;
}

// FUSED decoder h update + pack + projection + output write; one block/row, 128 thr
__global__ void k_hupd_dec_pack(const float* __restrict__ r, const float* __restrict__ hc,
                                float* __restrict__ h, const float* __restrict__ pW,
                                const float* __restrict__ pb, float* __restrict__ go,
                                float* __restrict__ out, int t,
                                hf* __restrict__ xg, hf* __restrict__ hB) {
    __shared__ float red[128];
    int row = blockIdx.x, c = threadIdx.x;
    int i = row * 128 + c;
    float rv = r[i];
    float hn = rv * h[i] + (1.f - rv) * hc[i];
    h[i] = hn;
    // pack for next step
    hf* p = xg + (size_t)row * KPD;
    store2(p, 6 + c, SECD, hn);
    store2(p, 408 + c, SECD, hn);
    int n = row >> 6, b = row & 63;
    hf hv = __float2half(hn);
    hB[(size_t)n * (BB * DDEC) + b * DDEC + c]        = hv;
    hB[(size_t)(NN + n) * (BB * DDEC) + b * DDEC + c] = hv;
    // projection
    red[c] = hn * pW[c];
    __syncthreads();
    for (int s = 64; s > 0; s >>= 1) { if (c < s) red[c] += red[c + s]; __syncthreads(); }
    if (c == 0) {
        float g = red[0] + pb[0];
        go[row] = g;
        out[(b * NN + n) * HH + t] = g;
    }
}

// ---------------- host side ----------------
static void bgemm_launch(int mode, const hf* A, const hf* B, void* C,
                         int M, int N, int Kp,
                         const float* bias = nullptr, float* C2 = nullptr,
                         int splitN = 0, int ldC = 0, int hdshift = 0, int sec = 0,
                         int o0 = 0, int o1 = 0, int o2 = 0, int o3 = 0)
{
    dim3 grid((N + 127) / 128, M / 128);
    switch (mode) {
        case 2: bgemm<2><<<grid, 256>>>(A, B, C, M, N, Kp, bias, C2, splitN, ldC, hdshift, sec, o0, o1, o2, o3); break;
        case 3: bgemm<3><<<grid, 256>>>(A, B, C, M, N, Kp, bias, C2, splitN, ldC, hdshift, sec, o0, o1, o2, o3); break;
        case 4: bgemm<4><<<grid, 256>>>(A, B, C, M, N, Kp, bias, C2, splitN, ldC, hdshift, sec, o0, o1, o2, o3); break;
    }
}

extern "C" void kernel_launch(void* const* d_in, const int* in_sizes, int n_in,
                              void* d_out, int out_size)
{
    const float* x   = (const float*)d_in[0];
    const float* tt  = (const float*)d_in[3];
    const float* Mem = (const float*)d_in[5];
    const float* Wq  = (const float*)d_in[6];
    const float* We1 = (const float*)d_in[7];
    const float* We2 = (const float*)d_in[8];
    const float* egW = (const float*)d_in[9];
    const float* egb = (const float*)d_in[10];
    const float* euW = (const float*)d_in[11];
    const float* eub = (const float*)d_in[12];
    const float* dgW = (const float*)d_in[13];
    const float* dgb = (const float*)d_in[14];
    const float* duW = (const float*)d_in[15];
    const float* dub = (const float*)d_in[16];
    const float* pW  = (const float*)d_in[17];
    const float* pb  = (const float*)d_in[18];
    float* out = (float*)d_out;

    float *S, *e1, *e2, *xT, *GX, *henc, *hdec, *z, *r, *hc, *go, *Ggo;
    hf *Sbig, *hB, *xgE, *xgD, *egWB, *euWB, *dgWB, *duWB;
    cudaGetSymbolAddress((void**)&S,    g_S);
    cudaGetSymbolAddress((void**)&e1,   g_e1);
    cudaGetSymbolAddress((void**)&e2,   g_e2);
    cudaGetSymbolAddress((void**)&xT,   g_xT);
    cudaGetSymbolAddress((void**)&GX,   g_GX);
    cudaGetSymbolAddress((void**)&henc, g_henc);
    cudaGetSymbolAddress((void**)&hdec, g_hdec);
    cudaGetSymbolAddress((void**)&z,    g_z);
    cudaGetSymbolAddress((void**)&r,    g_r);
    cudaGetSymbolAddress((void**)&hc,   g_hc);
    cudaGetSymbolAddress((void**)&go,   g_go);
    cudaGetSymbolAddress((void**)&Ggo,  g_Ggo);
    cudaGetSymbolAddress((void**)&Sbig, g_Sbig);
    cudaGetSymbolAddress((void**)&hB,   g_hB);
    cudaGetSymbolAddress((void**)&xgE,  g_xgE);
    cudaGetSymbolAddress((void**)&xgD,  g_xgD);
    cudaGetSymbolAddress((void**)&egWB, g_egWB);
    cudaGetSymbolAddress((void**)&euWB, g_euWB);
    cudaGetSymbolAddress((void**)&dgWB, g_dgWB);
    cudaGetSymbolAddress((void**)&duWB, g_duWB);

    // --- weight splits (pad rows of big buffers stay zero) ---
    k_splitB<<<(KENC * 128 + 255) / 256, 256>>>(egW, egWB, SECE, 128, KENC * 128);
    k_splitB<<<(KENC * 64  + 255) / 256, 256>>>(euW, euWB, SECE, 64,  KENC * 64);
    k_splitB<<<(KDEC * 256 + 255) / 256, 256>>>(dgW, dgWB, SECD, 256, KDEC * 256);
    k_splitB<<<(KDEC * 128 + 255) / 256, 256>>>(duW, duWB, SECD, 128, KDEC * 128);

    // --- supports (fp32) ---
    k_eW<<<(NN * 64 + 255) / 256, 256>>>(We1, Mem, e1);
    k_eW<<<(NN * 64 + 255) / 256, 256>>>(We2, Mem, e2);
    k_gsoftmax<<<NN, 128>>>(e1, e2, S);
    k_gsoftmax<<<NN, 128>>>(e2, e1, S + 2 * NN * NN);
    {
        dim3 g1(NN / 128, NN / 128);
        sgemm<1><<<g1, 256>>>(S,               S,               S + 1 * NN * NN, NN, NN, NN);
        sgemm<1><<<g1, 256>>>(S + 2 * NN * NN, S + 2 * NN * NN, S + 3 * NN * NN, NN, NN, NN);
    }
    k_splitA<<<(4 * NN * NN + 255) / 256, 256>>>(S, Sbig, NN, 4 * NN * NN);

    // --- encoder x precompute (fp32) ---
    k_xT<<<(BB * NN * LL + 255) / 256, 256>>>(x, xT);
    {
        dim3 g2((LL * BB + 127) / 128, 4 * NN / 128);
        sgemm<0><<<g2, 256>>>(S, xT, GX, 4 * NN, LL * BB, NN);
    }

    // --- init states (explicit: globals persist across graph replays) ---
    k_zero<<<(ROWS * RNN + 255) / 256, 256>>>(henc, ROWS * RNN);
    k_zero<<<(ROWS + 255) / 256, 256>>>(go, ROWS);
    k_fill_h_id<<<(ROWS * RNN) / 256, 256>>>(xgE, henc, 6, SECE, 1, 196, ROWS * RNN);
    k_splitB<<<(ROWS * RNN + 255) / 256, 256>>>(henc, hB, NN, BB * RNN, ROWS * RNN);

    // --- encoder ---
    for (int l = 0; l < LL; l++) {
        k_fill_enc_x<<<ROWS / 256, 256>>>(xgE, xT, GX, l);
        bgemm_launch(4, Sbig, hB, xgE, 4 * NN, BB * RNN, KGC,
                     nullptr, nullptr, 0, 0, 6, SECE, 66, 131, 261, 326);
        bgemm_launch(2, xgE, egWB, z, ROWS, 2 * RNN, KPE, egb, r, RNN);
        k_zh_pack<<<(ROWS * RNN) / 256, 256>>>(z, henc, xgE, hB, 6, SECE, 1, 196, ROWS * RNN);
        bgemm_launch(4, Sbig, hB, xgE, 4 * NN, BB * RNN, KGC,
                     nullptr, nullptr, 0, 0, 6, SECE, 66, 131, 261, 326);
        bgemm_launch(3, xgE, euWB, hc, ROWS, RNN, KPE, eub, nullptr, 0, RNN);
        k_hupd_pack<<<(ROWS * RNN) / 256, 256>>>(r, hc, henc, xgE, hB, 6, SECE, 1, 196, ROWS * RNN);
    }

    // --- memory attention -> decoder initial hidden ---
    k_attn<<<ROWS, 64>>>(henc, Wq, Mem, hdec);
    k_fill_h_id<<<(ROWS * DDEC) / 256, 256>>>(xgD, hdec, 7, SECD, 6, 408, ROWS * DDEC);
    k_splitB<<<(ROWS * DDEC + 255) / 256, 256>>>(hdec, hB, NN, BB * DDEC, ROWS * DDEC);

    // --- decoder ---
    for (int t = 0; t < HH; t++) {
        {
            dim3 g3(1, 4 * NN / 128);
            sgemm<0><<<g3, 256>>>(S, go, Ggo, 4 * NN, BB, NN);
        }
        k_fill_dec<<<ROWS / 256, 256>>>(xgD, go, Ggo, tt, t);
        bgemm_launch(4, Sbig, hB, xgD, 4 * NN, BB * DDEC, KGC,
                     nullptr, nullptr, 0, 0, 7, SECD, 140, 274, 542, 676);
        bgemm_launch(2, xgD, dgWB, z, ROWS, 2 * DDEC, KPD, dgb, r, DDEC);
        k_zh_pack<<<(ROWS * DDEC) / 256, 256>>>(z, hdec, xgD, hB, 7, SECD, 6, 408, ROWS * DDEC);
        bgemm_launch(4, Sbig, hB, xgD, 4 * NN, BB * DDEC, KGC,
                     nullptr, nullptr, 0, 0, 7, SECD, 140, 274, 542, 676);
        bgemm_launch(3, xgD, duWB, hc, ROWS, DDEC, KPD, dub, nullptr, 0, DDEC);
        k_hupd_dec_pack<<<ROWS, 128>>>(r, hc, hdec, pW, pb, go, out, t, xgD, hB);
    }
}

// round 9
// speedup vs baseline: 1.8902x; 1.0279x over previous
#include <cuda_runtime.h>
#include <cuda_fp16.h>
#include <math.h>

// ---------------- problem constants ----------------
#define NN   512
#define BB   64
#define LL   12
#define HH   12
#define RNN  64
#define DDEC 128
#define KENC 390        // logical enc feature count
#define KDEC 804        // logical dec feature count
#define SECE 416        // enc section (pad to /32)
#define SECD 832        // dec section
#define KPE  (2*SECE)   // 832
#define KPD  (2*SECD)   // 1664
#define KGC  (2*NN)     // 1024 (graph conv K')
#define ROWS (NN*BB)    // 32768

// bgemm pipeline: 4 stages of As(128x40 hf) + Bs(32x136 hf), dynamic smem
#define AS_ELEMS (128*40)
#define BS_ELEMS (32*136)
#define NSTAGE   4
#define SMEM_BYTES (NSTAGE * (AS_ELEMS + BS_ELEMS) * 2)   // 75776

typedef __half hf;

// ---------------- scratch (device globals; zero-init, no allocation) ----------------
__device__ float g_S[4*NN*NN];
__device__ float g_e1[NN*64];
__device__ float g_e2[NN*64];
__device__ float g_xT[NN*LL*BB];
__device__ float g_GX[4*NN*LL*BB];
__device__ float g_henc[ROWS*RNN];
__device__ float g_hdec[ROWS*DDEC];
__device__ float g_z [ROWS*DDEC];
__device__ float g_r [ROWS*DDEC];
__device__ float g_hc[ROWS*DDEC];
__device__ float g_go[ROWS];
__device__ float g_Ggo[4*NN*BB];
// fp16 2-term split operands
__device__ hf g_Sbig [4*NN*KGC];       // A: [hi|lo], 2048 x 1024
__device__ hf g_hB   [KGC*BB*DDEC];    // B: [hi|hi], up to 1024 x 8192
__device__ hf g_xgE  [ROWS*KPE];       // enc feature A (pads stay 0)
__device__ hf g_xgD  [ROWS*KPD];       // dec feature A
__device__ hf g_egWB [KPE*128];
__device__ hf g_euWB [KPE*64];
__device__ hf g_dgWB [KPD*256];
__device__ hf g_duWB [KPD*128];

// ---------------- helpers ----------------
__device__ __forceinline__ void split2h(float v, hf &h, hf &l) {
    h = __float2half(v);
    l = __float2half(v - __half2float(h));
}
// A-layout pair write: [hi | lo] at offsets off, sec+off
__device__ __forceinline__ void store2(hf* p, int off, int sec, float v) {
    hf h, l; split2h(v, h, l);
    p[off] = h; p[sec + off] = l;
}
__device__ __forceinline__ void fma2(unsigned long long &d, unsigned long long a, unsigned long long b) {
    asm("fma.rn.f32x2 %0, %1, %2, %0;" : "+l"(d) : "l"(a), "l"(b));
}
__device__ __forceinline__ unsigned long long bcast2(float x) {
    unsigned long long r;
    asm("mov.b64 %0, {%1, %1};" : "=l"(r) : "f"(x));
    return r;
}
__device__ __forceinline__ void cpa16(void* s, const void* g, bool ok) {
    unsigned sa = (unsigned)__cvta_generic_to_shared(s);
    int sz = ok ? 16 : 0;
    asm volatile("cp.async.cg.shared.global [%0], [%1], 16, %2;"
                 :: "r"(sa), "l"(g), "r"(sz));
}

// ================= fp16 tensor-core GEMM, 128x128x32, 4-stage cp.async ==========
// A: row-major M x Kp (hf), B: row-major Kp x N (hf). M%128==0, Kp%32==0.
// MODE 2: v=sigmoid(acc+bias[c]); c<splitN -> Cz else Cr (fp32, stride splitN)
// MODE 3: C[r*ldC+c] = tanh(acc+bias[c])     (fp32)
// MODE 4: graph-conv scatter into xg (hf pair): row=j*512+n, col=b*hd+c ->
//         xg[(n*BB+b)*(2*sec) + off_j + c] (hi/lo)
template<int MODE>
__global__ void __launch_bounds__(256)
bgemm(const hf* __restrict__ A, const hf* __restrict__ Bm, void* __restrict__ Cv,
      int M, int N, int Kp, const float* __restrict__ bias, float* __restrict__ C2,
      int splitN, int ldC, int hdshift, int sec, int o0, int o1, int o2, int o3)
{
    extern __shared__ __align__(16) char smem_raw[];
    hf* AsBase = (hf*)smem_raw;                        // NSTAGE x AS_ELEMS
    hf* BsBase = (hf*)smem_raw + NSTAGE * AS_ELEMS;    // NSTAGE x BS_ELEMS

    const int tid  = threadIdx.x;
    const int lane = tid & 31;
    const int warp = tid >> 5;
    const int wm   = warp & 1;
    const int wn   = warp >> 1;
    const int row0 = blockIdx.y * 128;
    const int col0 = blockIdx.x * 128;

    float acc[4][4][4];
    #pragma unroll
    for (int i = 0; i < 4; i++)
        #pragma unroll
        for (int j = 0; j < 4; j++)
            #pragma unroll
            for (int g = 0; g < 4; g++) acc[i][j][g] = 0.f;

    const int aq0 = tid * 2;
    const int ar0 = aq0 >> 2, ac0 = (aq0 & 3) * 8;
    const int ar1 = (aq0 + 1) >> 2, ac1 = ((aq0 + 1) & 3) * 8;
    const int br0 = aq0 >> 4, bc0 = (aq0 & 15) * 8;
    const int br1 = (aq0 + 1) >> 4, bc1 = ((aq0 + 1) & 15) * 8;
    const bool ok0 = (col0 + bc0) < N;
    const bool ok1 = (col0 + bc1) < N;

    const int T = Kp >> 5;

    #define ISSUE(s, kt) do {                                                          \
        hf* As_ = AsBase + (s) * AS_ELEMS;                                             \
        hf* Bs_ = BsBase + (s) * BS_ELEMS;                                             \
        const int k0_ = (kt) * 32;                                                     \
        cpa16(&As_[ar0 * 40 + ac0], A + (size_t)(row0 + ar0) * Kp + k0_ + ac0, true);  \
        cpa16(&As_[ar1 * 40 + ac1], A + (size_t)(row0 + ar1) * Kp + k0_ + ac1, true);  \
        cpa16(&Bs_[br0 * 136 + bc0],                                                   \
              ok0 ? (Bm + (size_t)(k0_ + br0) * N + col0 + bc0) : Bm, ok0);            \
        cpa16(&Bs_[br1 * 136 + bc1],                                                   \
              ok1 ? (Bm + (size_t)(k0_ + br1) * N + col0 + bc1) : Bm, ok1);            \
    } while (0)

    // prologue: issue stages 0..NSTAGE-2
    #pragma unroll
    for (int s = 0; s < NSTAGE - 1; s++) {
        if (s < T) ISSUE(s, s);
        asm volatile("cp.async.commit_group;");
    }

    for (int kt = 0; kt < T; kt++) {
        asm volatile("cp.async.wait_group %0;" :: "n"(NSTAGE - 2));
        __syncthreads();
        if (kt + NSTAGE - 1 < T) ISSUE((kt + NSTAGE - 1) % NSTAGE, kt + NSTAGE - 1);
        asm volatile("cp.async.commit_group;");

        const int cur = kt % NSTAGE;
        const hf* As = AsBase + cur * AS_ELEMS;
        const hf* Bs = BsBase + cur * BS_ELEMS;
        #pragma unroll
        for (int kk = 0; kk < 2; kk++) {
            unsigned af[4][4], bfg[4][2];
            #pragma unroll
            for (int i = 0; i < 4; i++) {
                const hf* p = &As[(wm * 64 + i * 16 + (lane & 15)) * 40 + kk * 16 + (lane >> 4) * 8];
                unsigned addr = (unsigned)__cvta_generic_to_shared(p);
                asm volatile("ldmatrix.sync.aligned.m8n8.x4.shared.b16 {%0,%1,%2,%3}, [%4];"
                             : "=r"(af[i][0]), "=r"(af[i][1]), "=r"(af[i][2]), "=r"(af[i][3])
                             : "r"(addr));
            }
            #pragma unroll
            for (int j = 0; j < 4; j++) {
                const hf* p = &Bs[(kk * 16 + (lane & 15)) * 136 + wn * 32 + j * 8];
                unsigned addr = (unsigned)__cvta_generic_to_shared(p);
                asm volatile("ldmatrix.sync.aligned.m8n8.x2.trans.shared.b16 {%0,%1}, [%2];"
                             : "=r"(bfg[j][0]), "=r"(bfg[j][1]) : "r"(addr));
            }
            #pragma unroll
            for (int i = 0; i < 4; i++)
                #pragma unroll
                for (int j = 0; j < 4; j++)
                    asm volatile(
                        "mma.sync.aligned.m16n8k16.row.col.f32.f16.f16.f32 "
                        "{%0,%1,%2,%3}, {%4,%5,%6,%7}, {%8,%9}, {%0,%1,%2,%3};"
                        : "+f"(acc[i][j][0]), "+f"(acc[i][j][1]), "+f"(acc[i][j][2]), "+f"(acc[i][j][3])
                        : "r"(af[i][0]), "r"(af[i][1]), "r"(af[i][2]), "r"(af[i][3]),
                          "r"(bfg[j][0]), "r"(bfg[j][1]));
        }
        __syncthreads();
    }
    #undef ISSUE

    // epilogue
    if (MODE == 4) {
        hf* C = (hf*)Cv;
        const int jblk = row0 >> 9;
        const int off  = (jblk == 0) ? o0 : (jblk == 1) ? o1 : (jblk == 2) ? o2 : o3;
        const int hmask = (1 << hdshift) - 1;
        const int Ktot = 2 * sec;
        #pragma unroll
        for (int i = 0; i < 4; i++)
            #pragma unroll
            for (int j = 0; j < 4; j++)
                #pragma unroll
                for (int g = 0; g < 4; g++) {
                    int rr = row0 + wm * 64 + i * 16 + (lane >> 2) + ((g >> 1) << 3);
                    int cc = col0 + wn * 32 + j * 8 + ((lane & 3) << 1) + (g & 1);
                    if (cc < N) {
                        int n = rr & (NN - 1);
                        int b = cc >> hdshift;
                        int c = cc & hmask;
                        store2(C + (size_t)(n * BB + b) * Ktot, off + c, sec, acc[i][j][g]);
                    }
                }
    } else {
        float* C = (float*)Cv;
        #pragma unroll
        for (int i = 0; i < 4; i++)
            #pragma unroll
            for (int j = 0; j < 4; j++)
                #pragma unroll
                for (int g = 0; g < 4; g++) {
                    int rr = row0 + wm * 64 + i * 16 + (lane >> 2) + ((g >> 1) << 3);
                    int cc = col0 + wn * 32 + j * 8 + ((lane & 3) << 1) + (g & 1);
                    if (cc >= N) continue;
                    float v = acc[i][j][g];
                    if (MODE == 2) {
                        v = 1.f / (1.f + expf(-(v + bias[cc])));
                        if (cc < splitN) C [(size_t)rr * splitN + cc]            = v;
                        else             C2[(size_t)rr * splitN + (cc - splitN)] = v;
                    } else { // MODE 3
                        C[(size_t)rr * ldC + cc] = tanhf(v + bias[cc]);
                    }
                }
    }
}

// ================= fp32 f32x2 SGEMM (small GEMMs only) =====================
template<int MODE>   // MODE 0: plain, MODE 1: 2*acc - I
__global__ void __launch_bounds__(256)
sgemm(const float* __restrict__ A, const float* __restrict__ Bm, float* __restrict__ C,
      int M, int N, int K)
{
    __shared__ __align__(16) float As[2][16][132];
    __shared__ __align__(16) float Bsh[2][16][132];
    const int tid = threadIdx.x;
    const int tx  = tid & 15;
    const int ty  = tid >> 4;
    const int row0 = blockIdx.y * 128;
    const int col0 = blockIdx.x * 128;

    const int am  = tid >> 1;
    const int ak0 = (tid & 1) << 2;
    const int bk  = tid >> 5;
    const int bn  = (tid & 31) << 2;
    const int gn  = col0 + bn;
    const bool bok = gn < N;

    unsigned long long acc[8][4];
    #pragma unroll
    for (int i = 0; i < 8; i++)
        #pragma unroll
        for (int j = 0; j < 4; j++) acc[i][j] = 0ull;

    const int T = K >> 4;
    const float4 z4 = make_float4(0.f, 0.f, 0.f, 0.f);
    const float* Abase = A + (size_t)(row0 + am) * K + ak0;

    float4 ra0 = *(const float4*)(Abase);
    float4 ra1 = *(const float4*)(Abase + 8);
    float4 rb0 = bok ? *(const float4*)(Bm + (size_t)bk * N + gn) : z4;
    float4 rb1 = bok ? *(const float4*)(Bm + (size_t)(bk + 8) * N + gn) : z4;
    As[0][ak0 + 0][am] = ra0.x; As[0][ak0 + 1][am] = ra0.y;
    As[0][ak0 + 2][am] = ra0.z; As[0][ak0 + 3][am] = ra0.w;
    As[0][ak0 + 8][am] = ra1.x; As[0][ak0 + 9][am] = ra1.y;
    As[0][ak0 +10][am] = ra1.z; As[0][ak0 +11][am] = ra1.w;
    *(float4*)&Bsh[0][bk][bn]     = rb0;
    *(float4*)&Bsh[0][bk + 8][bn] = rb1;
    __syncthreads();

    for (int kt = 0; kt < T; kt++) {
        const int cur = kt & 1;
        if (kt + 1 < T) {
            const float* Ap = Abase + (kt + 1) * 16;
            ra0 = *(const float4*)(Ap);
            ra1 = *(const float4*)(Ap + 8);
            const int gk = (kt + 1) * 16;
            rb0 = bok ? *(const float4*)(Bm + (size_t)(gk + bk) * N + gn) : z4;
            rb1 = bok ? *(const float4*)(Bm + (size_t)(gk + bk + 8) * N + gn) : z4;
        }
        #pragma unroll
        for (int kk = 0; kk < 16; kk++) {
            float4 a0 = *(const float4*)&As[cur][kk][ty * 8];
            float4 a1 = *(const float4*)&As[cur][kk][ty * 8 + 4];
            ulonglong2 bp0 = *(const ulonglong2*)&Bsh[cur][kk][tx * 8];
            ulonglong2 bp1 = *(const ulonglong2*)&Bsh[cur][kk][tx * 8 + 4];
            unsigned long long b2[4] = { bp0.x, bp0.y, bp1.x, bp1.y };
            unsigned long long a2[8] = {
                bcast2(a0.x), bcast2(a0.y), bcast2(a0.z), bcast2(a0.w),
                bcast2(a1.x), bcast2(a1.y), bcast2(a1.z), bcast2(a1.w)
            };
            #pragma unroll
            for (int i = 0; i < 8; i++)
                #pragma unroll
                for (int j = 0; j < 4; j++)
                    fma2(acc[i][j], a2[i], b2[j]);
        }
        if (kt + 1 < T) {
            const int nxt = cur ^ 1;
            As[nxt][ak0 + 0][am] = ra0.x; As[nxt][ak0 + 1][am] = ra0.y;
            As[nxt][ak0 + 2][am] = ra0.z; As[nxt][ak0 + 3][am] = ra0.w;
            As[nxt][ak0 + 8][am] = ra1.x; As[nxt][ak0 + 9][am] = ra1.y;
            As[nxt][ak0 +10][am] = ra1.z; As[nxt][ak0 +11][am] = ra1.w;
            *(float4*)&Bsh[nxt][bk][bn]     = rb0;
            *(float4*)&Bsh[nxt][bk + 8][bn] = rb1;
        }
        __syncthreads();
    }

    #pragma unroll
    for (int i = 0; i < 8; i++) {
        const int r = row0 + ty * 8 + i;
        #pragma unroll
        for (int j = 0; j < 4; j++) {
            #pragma unroll
            for (int h = 0; h < 2; h++) {
                const int cc = col0 + tx * 8 + 2 * j + h;
                if (cc >= N) continue;
                float v = h ? __uint_as_float((unsigned)(acc[i][j] >> 32))
                            : __uint_as_float((unsigned)(acc[i][j]));
                if (MODE == 0) C[(size_t)r * N + cc] = v;
                else           C[(size_t)r * N + cc] = 2.f * v - ((r == cc) ? 1.f : 0.f);
            }
        }
    }
}

// ---------------- small kernels ----------------
__global__ void k_zero(float* p, int n) {
    int i = blockIdx.x * blockDim.x + threadIdx.x;
    if (i < n) p[i] = 0.f;
}

// split fp32 (M x K) -> A-layout hf (M x 2K): [hi | lo]
__global__ void k_splitA(const float* __restrict__ in, hf* __restrict__ out, int K, int total) {
    int i = blockIdx.x * blockDim.x + threadIdx.x;
    if (i >= total) return;
    int m = i / K, k = i - m * K;
    hf h, l; split2h(in[i], h, l);
    hf* p = out + (size_t)m * 2 * K;
    p[k] = h; p[K + k] = l;
}

// fp32 (Kreal x N) -> B-layout hf (2*Ksec x N): [hi | hi]
__global__ void k_splitB(const float* __restrict__ in, hf* __restrict__ out,
                         int Ksec, int N, int total) {
    int i = blockIdx.x * blockDim.x + threadIdx.x;
    if (i >= total) return;
    int k = i / N, j = i - k * N;
    hf h = __float2half(in[i]);
    out[(size_t)k * N + j]          = h;
    out[(size_t)(Ksec + k) * N + j] = h;
}

__global__ void k_eW(const float* __restrict__ We, const float* __restrict__ Mem,
                     float* __restrict__ e) {
    int idx = blockIdx.x * blockDim.x + threadIdx.x;
    if (idx >= NN * 64) return;
    int n = idx >> 6, d = idx & 63;
    float s = 0.f;
    #pragma unroll
    for (int k = 0; k < 20; k++) s += We[n * 20 + k] * Mem[k * 64 + d];
    e[idx] = s;
}

__global__ void k_gsoftmax(const float* __restrict__ ea, const float* __restrict__ eb,
                           float* __restrict__ g) {
    __shared__ float er[64];
    __shared__ float buf[NN];
    __shared__ float red[128];
    int n = blockIdx.x, tid = threadIdx.x;
    if (tid < 64) er[tid] = ea[n * 64 + tid];
    __syncthreads();
    for (int m = tid; m < NN; m += 128) {
        float s = 0.f;
        #pragma unroll
        for (int d = 0; d < 64; d++) s += er[d] * eb[m * 64 + d];
        buf[m] = s > 0.f ? s : 0.f;
    }
    __syncthreads();
    float mx = -1e30f;
    for (int m = tid; m < NN; m += 128) mx = fmaxf(mx, buf[m]);
    red[tid] = mx; __syncthreads();
    for (int s = 64; s > 0; s >>= 1) { if (tid < s) red[tid] = fmaxf(red[tid], red[tid + s]); __syncthreads(); }
    mx = red[0]; __syncthreads();
    float sm = 0.f;
    for (int m = tid; m < NN; m += 128) { float e = expf(buf[m] - mx); buf[m] = e; sm += e; }
    red[tid] = sm; __syncthreads();
    for (int s = 64; s > 0; s >>= 1) { if (tid < s) red[tid] += red[tid + s]; __syncthreads(); }
    float inv = 1.f / red[0];
    for (int m = tid; m < NN; m += 128) g[n * NN + m] = buf[m] * inv;
}

__global__ void k_xT(const float* __restrict__ x, float* __restrict__ xT) {
    int idx = blockIdx.x * blockDim.x + threadIdx.x;
    if (idx >= BB * NN * LL) return;
    int l = idx % LL;
    int n = (idx / LL) % NN;
    int b = idx / (LL * NN);
    xT[(n * LL + l) * BB + b] = x[idx];
}

// fill encoder x-channels of xgE for step l (pairs)
__global__ void k_fill_enc_x(hf* __restrict__ xg, const float* __restrict__ xT,
                             const float* __restrict__ GX, int l) {
    int row = blockIdx.x * blockDim.x + threadIdx.x;
    if (row >= ROWS) return;
    int n = row >> 6, b = row & 63;
    hf* p = xg + (size_t)row * KPE;
    float xv = xT[(n * LL + l) * BB + b];
    store2(p, 0, SECE, xv);
    store2(p, 195, SECE, xv);
    store2(p, 65,  SECE, GX[(size_t)(0 * NN + n) * (LL * BB) + l * BB + b]);
    store2(p, 130, SECE, GX[(size_t)(1 * NN + n) * (LL * BB) + l * BB + b]);
    store2(p, 260, SECE, GX[(size_t)(2 * NN + n) * (LL * BB) + l * BB + b]);
    store2(p, 325, SECE, GX[(size_t)(3 * NN + n) * (LL * BB) + l * BB + b]);
}

// fill identity-support h-channels (blocks 0 and 3) as pairs (init only)
__global__ void k_fill_h_id(hf* __restrict__ xg, const float* __restrict__ h,
                            int hdshift, int sec, int off0, int off3, int total) {
    int i = blockIdx.x * blockDim.x + threadIdx.x;
    if (i >= total) return;
    int row = i >> hdshift;
    int c   = i & ((1 << hdshift) - 1);
    float v = h[i];
    hf* p = xg + (size_t)row * 2 * sec;
    store2(p, off0 + c, sec, v);
    store2(p, off3 + c, sec, v);
}

// FUSED: zh = z*h -> xg id-blocks (pairs) + hB ([hi|hi])
__global__ void k_zh_pack(const float* __restrict__ z, const float* __restrict__ h,
                          hf* __restrict__ xg, hf* __restrict__ hB,
                          int hdshift, int sec, int off0, int off3, int total) {
    int i = blockIdx.x * blockDim.x + threadIdx.x;
    if (i >= total) return;
    int row = i >> hdshift;
    int c   = i & ((1 << hdshift) - 1);
    float v = z[i] * h[i];
    hf* p = xg + (size_t)row * 2 * sec;
    store2(p, off0 + c, sec, v);
    store2(p, off3 + c, sec, v);
    int n = row >> 6, b = row & 63;
    int Ncols = BB << hdshift;
    size_t col = ((size_t)b << hdshift) + c;
    hf hv = __float2half(v);
    hB[(size_t)n * Ncols + col]        = hv;
    hB[(size_t)(NN + n) * Ncols + col] = hv;
}

// FUSED: h' = r*h+(1-r)*hc -> h, xg id-blocks, hB  (encoder)
__global__ void k_hupd_pack(const float* __restrict__ r, const float* __restrict__ hc,
                            float* __restrict__ h,
                            hf* __restrict__ xg, hf* __restrict__ hB,
                            int hdshift, int sec, int off0, int off3, int total) {
    int i = blockIdx.x * blockDim.x + threadIdx.x;
    if (i >= total) return;
    int row = i >> hdshift;
    int c   = i & ((1 << hdshift) - 1);
    float rv = r[i];
    float hn = rv * h[i] + (1.f - rv) * hc[i];
    h[i] = hn;
    hf* p = xg + (size_t)row * 2 * sec;
    store2(p, off0 + c, sec, hn);
    store2(p, off3 + c, sec, hn);
    int n = row >> 6, b = row & 63;
    int Ncols = BB << hdshift;
    size_t col = ((size_t)b << hdshift) + c;
    hf hv = __float2half(hn);
    hB[(size_t)n * Ncols + col]        = hv;
    hB[(size_t)(NN + n) * Ncols + col] = hv;
}

// fill decoder go + ycov channels for step t
__global__ void k_fill_dec(hf* __restrict__ xg, const float* __restrict__ go,
                           const float* __restrict__ Ggo, const float* __restrict__ tt, int t) {
    int row = blockIdx.x * blockDim.x + threadIdx.x;
    if (row >= ROWS) return;
    int n = row >> 6, b = row & 63;
    hf* p = xg + (size_t)row * KPD;
    float gv = go[row];
    store2(p, 0,   SECD, gv);
    store2(p, 402, SECD, gv);
    store2(p, 134, SECD, Ggo[(0 * NN + n) * BB + b]);
    store2(p, 268, SECD, Ggo[(1 * NN + n) * BB + b]);
    store2(p, 536, SECD, Ggo[(2 * NN + n) * BB + b]);
    store2(p, 670, SECD, Ggo[(3 * NN + n) * BB + b]);
    #pragma unroll
    for (int c = 0; c < 5; c++) {
        float v = tt[(b * 5 + c) * HH + t];
        store2(p, 1 + c,   SECD, v); store2(p, 135 + c, SECD, v);
        store2(p, 269 + c, SECD, v); store2(p, 403 + c, SECD, v);
        store2(p, 537 + c, SECD, v); store2(p, 671 + c, SECD, v);
    }
}

__global__ void k_attn(const float* __restrict__ h, const float* __restrict__ Wq,
                       const float* __restrict__ Mem, float* __restrict__ hde) {
    __shared__ float hr[64];
    __shared__ float q[64];
    __shared__ float sc[20];
    int row = blockIdx.x, tid = threadIdx.x;
    hr[tid] = h[row * 64 + tid];
    __syncthreads();
    float s = 0.f;
    #pragma unroll
    for (int c = 0; c < 64; c++) s += hr[c] * Wq[c * 64 + tid];
    q[tid] = s;
    __syncthreads();
    if (tid < 20) {
        float v = 0.f;
        #pragma unroll
        for (int c = 0; c < 64; c++) v += q[c] * Mem[tid * 64 + c];
        sc[tid] = v;
    }
    __syncthreads();
    if (tid == 0) {
        float mx = -1e30f;
        for (int j = 0; j < 20; j++) mx = fmaxf(mx, sc[j]);
        float sm = 0.f;
        for (int j = 0; j < 20; j++) { sc[j] = expf(sc[j] - mx); sm += sc[j]; }
        float inv = 1.f / sm;
        for (int j = 0; j < 20; j++) sc[j] *= inv;
    }
    __syncthreads();
    float ha = 0.f;
    #pragma unroll
    for (int j = 0; j < 20; j++) ha += sc[j] * Mem[j * 64 + tid];
    hde[row * 128 + tid]      = hr[tid];
    hde[row * 128 + 64 + tid] = ha;
}

// FUSED decoder h update + pack + projection + output write; one block/row, 128 thr
__global__ void k_hupd_dec_pack(const float* __restrict__ r, const float* __restrict__ hc,
                                float* __restrict__ h, const float* __restrict__ pW,
                                const float* __restrict__ pb, float* __restrict__ go,
                                float* __restrict__ out, int t,
                                hf* __restrict__ xg, hf* __restrict__ hB) {
    __shared__ float red[128];
    int row = blockIdx.x, c = threadIdx.x;
    int i = row * 128 + c;
    float rv = r[i];
    float hn = rv * h[i] + (1.f - rv) * hc[i];
    h[i] = hn;
    // pack for next step
    hf* p = xg + (size_t)row * KPD;
    store2(p, 6 + c, SECD, hn);
    store2(p, 408 + c, SECD, hn);
    int n = row >> 6, b = row & 63;
    hf hv = __float2half(hn);
    hB[(size_t)n * (BB * DDEC) + b * DDEC + c]        = hv;
    hB[(size_t)(NN + n) * (BB * DDEC) + b * DDEC + c] = hv;
    // projection
    red[c] = hn * pW[c];
    __syncthreads();
    for (int s = 64; s > 0; s >>= 1) { if (c < s) red[c] += red[c + s]; __syncthreads(); }
    if (c == 0) {
        float g = red[0] + pb[0];
        go[row] = g;
        out[(b * NN + n) * HH + t] = g;
    }
}

// ---------------- host side ----------------
static void bgemm_launch(int mode, const hf* A, const hf* B, void* C,
                         int M, int N, int Kp,
                         const float* bias = nullptr, float* C2 = nullptr,
                         int splitN = 0, int ldC = 0, int hdshift = 0, int sec = 0,
                         int o0 = 0, int o1 = 0, int o2 = 0, int o3 = 0)
{
    dim3 grid((N + 127) / 128, M / 128);
    switch (mode) {
        case 2: bgemm<2><<<grid, 256, SMEM_BYTES>>>(A, B, C, M, N, Kp, bias, C2, splitN, ldC, hdshift, sec, o0, o1, o2, o3); break;
        case 3: bgemm<3><<<grid, 256, SMEM_BYTES>>>(A, B, C, M, N, Kp, bias, C2, splitN, ldC, hdshift, sec, o0, o1, o2, o3); break;
        case 4: bgemm<4><<<grid, 256, SMEM_BYTES>>>(A, B, C, M, N, Kp, bias, C2, splitN, ldC, hdshift, sec, o0, o1, o2, o3); break;
    }
}

extern "C" void kernel_launch(void* const* d_in, const int* in_sizes, int n_in,
                              void* d_out, int out_size)
{
    const float* x   = (const float*)d_in[0];
    const float* tt  = (const float*)d_in[3];
    const float* Mem = (const float*)d_in[5];
    const float* Wq  = (const float*)d_in[6];
    const float* We1 = (const float*)d_in[7];
    const float* We2 = (const float*)d_in[8];
    const float* egW = (const float*)d_in[9];
    const float* egb = (const float*)d_in[10];
    const float* euW = (const float*)d_in[11];
    const float* eub = (const float*)d_in[12];
    const float* dgW = (const float*)d_in[13];
    const float* dgb = (const float*)d_in[14];
    const float* duW = (const float*)d_in[15];
    const float* dub = (const float*)d_in[16];
    const float* pW  = (const float*)d_in[17];
    const float* pb  = (const float*)d_in[18];
    float* out = (float*)d_out;

    // opt in to >48KB dynamic smem (host attribute; not an allocation)
    cudaFuncSetAttribute(bgemm<2>, cudaFuncAttributeMaxDynamicSharedMemorySize, SMEM_BYTES);
    cudaFuncSetAttribute(bgemm<3>, cudaFuncAttributeMaxDynamicSharedMemorySize, SMEM_BYTES);
    cudaFuncSetAttribute(bgemm<4>, cudaFuncAttributeMaxDynamicSharedMemorySize, SMEM_BYTES);

    float *S, *e1, *e2, *xT, *GX, *henc, *hdec, *z, *r, *hc, *go, *Ggo;
    hf *Sbig, *hB, *xgE, *xgD, *egWB, *euWB, *dgWB, *duWB;
    cudaGetSymbolAddress((void**)&S,    g_S);
    cudaGetSymbolAddress((void**)&e1,   g_e1);
    cudaGetSymbolAddress((void**)&e2,   g_e2);
    cudaGetSymbolAddress((void**)&xT,   g_xT);
    cudaGetSymbolAddress((void**)&GX,   g_GX);
    cudaGetSymbolAddress((void**)&henc, g_henc);
    cudaGetSymbolAddress((void**)&hdec, g_hdec);
    cudaGetSymbolAddress((void**)&z,    g_z);
    cudaGetSymbolAddress((void**)&r,    g_r);
    cudaGetSymbolAddress((void**)&hc,   g_hc);
    cudaGetSymbolAddress((void**)&go,   g_go);
    cudaGetSymbolAddress((void**)&Ggo,  g_Ggo);
    cudaGetSymbolAddress((void**)&Sbig, g_Sbig);
    cudaGetSymbolAddress((void**)&hB,   g_hB);
    cudaGetSymbolAddress((void**)&xgE,  g_xgE);
    cudaGetSymbolAddress((void**)&xgD,  g_xgD);
    cudaGetSymbolAddress((void**)&egWB, g_egWB);
    cudaGetSymbolAddress((void**)&euWB, g_euWB);
    cudaGetSymbolAddress((void**)&dgWB, g_dgWB);
    cudaGetSymbolAddress((void**)&duWB, g_duWB);

    // --- weight splits (pad rows of big buffers stay zero) ---
    k_splitB<<<(KENC * 128 + 255) / 256, 256>>>(egW, egWB, SECE, 128, KENC * 128);
    k_splitB<<<(KENC * 64  + 255) / 256, 256>>>(euW, euWB, SECE, 64,  KENC * 64);
    k_splitB<<<(KDEC * 256 + 255) / 256, 256>>>(dgW, dgWB, SECD, 256, KDEC * 256);
    k_splitB<<<(KDEC * 128 + 255) / 256, 256>>>(duW, duWB, SECD, 128, KDEC * 128);

    // --- supports (fp32) ---
    k_eW<<<(NN * 64 + 255) / 256, 256>>>(We1, Mem, e1);
    k_eW<<<(NN * 64 + 255) / 256, 256>>>(We2, Mem, e2);
    k_gsoftmax<<<NN, 128>>>(e1, e2, S);
    k_gsoftmax<<<NN, 128>>>(e2, e1, S + 2 * NN * NN);
    {
        dim3 g1(NN / 128, NN / 128);
        sgemm<1><<<g1, 256>>>(S,               S,               S + 1 * NN * NN, NN, NN, NN);
        sgemm<1><<<g1, 256>>>(S + 2 * NN * NN, S + 2 * NN * NN, S + 3 * NN * NN, NN, NN, NN);
    }
    k_splitA<<<(4 * NN * NN + 255) / 256, 256>>>(S, Sbig, NN, 4 * NN * NN);

    // --- encoder x precompute (fp32) ---
    k_xT<<<(BB * NN * LL + 255) / 256, 256>>>(x, xT);
    {
        dim3 g2((LL * BB + 127) / 128, 4 * NN / 128);
        sgemm<0><<<g2, 256>>>(S, xT, GX, 4 * NN, LL * BB, NN);
    }

    // --- init states (explicit: globals persist across graph replays) ---
    k_zero<<<(ROWS * RNN + 255) / 256, 256>>>(henc, ROWS * RNN);
    k_zero<<<(ROWS + 255) / 256, 256>>>(go, ROWS);
    k_fill_h_id<<<(ROWS * RNN) / 256, 256>>>(xgE, henc, 6, SECE, 1, 196, ROWS * RNN);
    k_splitB<<<(ROWS * RNN + 255) / 256, 256>>>(henc, hB, NN, BB * RNN, ROWS * RNN);

    // --- encoder ---
    for (int l = 0; l < LL; l++) {
        k_fill_enc_x<<<ROWS / 256, 256>>>(xgE, xT, GX, l);
        bgemm_launch(4, Sbig, hB, xgE, 4 * NN, BB * RNN, KGC,
                     nullptr, nullptr, 0, 0, 6, SECE, 66, 131, 261, 326);
        bgemm_launch(2, xgE, egWB, z, ROWS, 2 * RNN, KPE, egb, r, RNN);
        k_zh_pack<<<(ROWS * RNN) / 256, 256>>>(z, henc, xgE, hB, 6, SECE, 1, 196, ROWS * RNN);
        bgemm_launch(4, Sbig, hB, xgE, 4 * NN, BB * RNN, KGC,
                     nullptr, nullptr, 0, 0, 6, SECE, 66, 131, 261, 326);
        bgemm_launch(3, xgE, euWB, hc, ROWS, RNN, KPE, eub, nullptr, 0, RNN);
        k_hupd_pack<<<(ROWS * RNN) / 256, 256>>>(r, hc, henc, xgE, hB, 6, SECE, 1, 196, ROWS * RNN);
    }

    // --- memory attention -> decoder initial hidden ---
    k_attn<<<ROWS, 64>>>(henc, Wq, Mem, hdec);
    k_fill_h_id<<<(ROWS * DDEC) / 256, 256>>>(xgD, hdec, 7, SECD, 6, 408, ROWS * DDEC);
    k_splitB<<<(ROWS * DDEC + 255) / 256, 256>>>(hdec, hB, NN, BB * DDEC, ROWS * DDEC);

    // --- decoder ---
    for (int t = 0; t < HH; t++) {
        {
            dim3 g3(1, 4 * NN / 128);
            sgemm<0><<<g3, 256>>>(S, go, Ggo, 4 * NN, BB, NN);
        }
        k_fill_dec<<<ROWS / 256, 256>>>(xgD, go, Ggo, tt, t);
        bgemm_launch(4, Sbig, hB, xgD, 4 * NN, BB * DDEC, KGC,
                     nullptr, nullptr, 0, 0, 7, SECD, 140, 274, 542, 676);
        bgemm_launch(2, xgD, dgWB, z, ROWS, 2 * DDEC, KPD, dgb, r, DDEC);
        k_zh_pack<<<(ROWS * DDEC) / 256, 256>>>(z, hdec, xgD, hB, 7, SECD, 6, 408, ROWS * DDEC);
        bgemm_launch(4, Sbig, hB, xgD, 4 * NN, BB * DDEC, KGC,
                     nullptr, nullptr, 0, 0, 7, SECD, 140, 274, 542, 676);
        bgemm_launch(3, xgD, duWB, hc, ROWS, DDEC, KPD, dub, nullptr, 0, DDEC);
        k_hupd_dec_pack<<<ROWS, 128>>>(r, hc, hdec, pW, pb, go, out, t, xgD, hB);
    }
}

// round 10
// speedup vs baseline: 2.0382x; 1.0783x over previous
#include <cuda_runtime.h>
#include <cuda_fp16.h>
#include <math.h>

// ---------------- problem constants ----------------
#define NN   512
#define BB   64
#define LL   12
#define HH   12
#define RNN  64
#define DDEC 128
#define KENC 390        // logical enc feature count
#define KDEC 804        // logical dec feature count
#define SECE 416        // enc section (pad to /32)
#define SECD 832        // dec section
#define KPE  (2*SECE)   // 832
#define KPD  (2*SECD)   // 1664
#define KGC  (2*NN)     // 1024 (graph conv K')
#define ROWS (NN*BB)    // 32768

// bgemm pipeline: 4 stages of As(128x40 hf) + Bs(32x136 hf), dynamic smem
#define AS_ELEMS (128*40)
#define BS_ELEMS (32*136)
#define NSTAGE   4
#define SMEM_BYTES (NSTAGE * (AS_ELEMS + BS_ELEMS) * 2)   // 75776

typedef __half hf;

// ---------------- scratch (device globals; zero-init, no allocation) ----------------
__device__ float g_S[4*NN*NN];
__device__ float g_e1[NN*64];
__device__ float g_e2[NN*64];
__device__ float g_xT[NN*LL*BB];
__device__ float g_GX[4*NN*LL*BB];
__device__ float g_henc[ROWS*RNN];
__device__ float g_hdec[ROWS*DDEC];
__device__ float g_z [ROWS*DDEC];
__device__ float g_r [ROWS*DDEC];
__device__ float g_hc[ROWS*DDEC];
__device__ float g_go[ROWS];
__device__ float g_Ggo[4*NN*BB];
// fp16 2-term split operands
__device__ hf g_Sbig [4*NN*KGC];       // A: [hi|lo], 2048 x 1024
__device__ hf g_hB   [KGC*BB*DDEC];    // B: [hi|hi], up to 1024 x 8192
__device__ hf g_xgE  [ROWS*KPE];       // enc feature A (pads stay 0)
__device__ hf g_xgD  [ROWS*KPD];       // dec feature A
__device__ hf g_egWB [KPE*128];
__device__ hf g_euWB [KPE*64];
__device__ hf g_dgWB [KPD*256];
__device__ hf g_duWB [KPD*128];

// ---------------- helpers ----------------
__device__ __forceinline__ void split2h(float v, hf &h, hf &l) {
    h = __float2half(v);
    l = __float2half(v - __half2float(h));
}
// A-layout pair write: [hi | lo] at offsets off, sec+off
__device__ __forceinline__ void store2(hf* p, int off, int sec, float v) {
    hf h, l; split2h(v, h, l);
    p[off] = h; p[sec + off] = l;
}
__device__ __forceinline__ void fma2(unsigned long long &d, unsigned long long a, unsigned long long b) {
    asm("fma.rn.f32x2 %0, %1, %2, %0;" : "+l"(d) : "l"(a), "l"(b));
}
__device__ __forceinline__ unsigned long long bcast2(float x) {
    unsigned long long r;
    asm("mov.b64 %0, {%1, %1};" : "=l"(r) : "f"(x));
    return r;
}
__device__ __forceinline__ void cpa16(void* s, const void* g, bool ok) {
    unsigned sa = (unsigned)__cvta_generic_to_shared(s);
    int sz = ok ? 16 : 0;
    asm volatile("cp.async.cg.shared.global [%0], [%1], 16, %2;"
                 :: "r"(sa), "l"(g), "r"(sz));
}

// ================= fp16 tensor-core GEMM, 128x128x32, 4-stage cp.async ==========
// Single __syncthreads per K-tile: wait -> sync -> compute(kt) -> issue(kt+3).
// Safe because issue targets stage (kt-1)%4, drained by the barrier this iteration.
// A: row-major M x Kp (hf), B: row-major Kp x N (hf). M%128==0, Kp%32==0.
// MODE 2: v=sigmoid(acc+bias[c]); c<splitN -> Cz else Cr (fp32, stride splitN)
// MODE 3: C[r*ldC+c] = tanh(acc+bias[c])     (fp32)
// MODE 4: graph-conv scatter into xg (hf pair)
template<int MODE>
__global__ void __launch_bounds__(256)
bgemm(const hf* __restrict__ A, const hf* __restrict__ Bm, void* __restrict__ Cv,
      int M, int N, int Kp, const float* __restrict__ bias, float* __restrict__ C2,
      int splitN, int ldC, int hdshift, int sec, int o0, int o1, int o2, int o3)
{
    extern __shared__ __align__(16) char smem_raw[];
    hf* AsBase = (hf*)smem_raw;                        // NSTAGE x AS_ELEMS
    hf* BsBase = (hf*)smem_raw + NSTAGE * AS_ELEMS;    // NSTAGE x BS_ELEMS

    const int tid  = threadIdx.x;
    const int lane = tid & 31;
    const int warp = tid >> 5;
    const int wm   = warp & 1;
    const int wn   = warp >> 1;
    const int row0 = blockIdx.y * 128;
    const int col0 = blockIdx.x * 128;

    float acc[4][4][4];
    #pragma unroll
    for (int i = 0; i < 4; i++)
        #pragma unroll
        for (int j = 0; j < 4; j++)
            #pragma unroll
            for (int g = 0; g < 4; g++) acc[i][j][g] = 0.f;

    const int aq0 = tid * 2;
    const int ar0 = aq0 >> 2, ac0 = (aq0 & 3) * 8;
    const int ar1 = (aq0 + 1) >> 2, ac1 = ((aq0 + 1) & 3) * 8;
    const int br0 = aq0 >> 4, bc0 = (aq0 & 15) * 8;
    const int br1 = (aq0 + 1) >> 4, bc1 = ((aq0 + 1) & 15) * 8;
    const bool ok0 = (col0 + bc0) < N;
    const bool ok1 = (col0 + bc1) < N;

    const int T = Kp >> 5;

    #define ISSUE(s, kt) do {                                                          \
        hf* As_ = AsBase + (s) * AS_ELEMS;                                             \
        hf* Bs_ = BsBase + (s) * BS_ELEMS;                                             \
        const int k0_ = (kt) * 32;                                                     \
        cpa16(&As_[ar0 * 40 + ac0], A + (size_t)(row0 + ar0) * Kp + k0_ + ac0, true);  \
        cpa16(&As_[ar1 * 40 + ac1], A + (size_t)(row0 + ar1) * Kp + k0_ + ac1, true);  \
        cpa16(&Bs_[br0 * 136 + bc0],                                                   \
              ok0 ? (Bm + (size_t)(k0_ + br0) * N + col0 + bc0) : Bm, ok0);            \
        cpa16(&Bs_[br1 * 136 + bc1],                                                   \
              ok1 ? (Bm + (size_t)(k0_ + br1) * N + col0 + bc1) : Bm, ok1);            \
    } while (0)

    // prologue: issue stages 0..NSTAGE-2
    #pragma unroll
    for (int s = 0; s < NSTAGE - 1; s++) {
        if (s < T) ISSUE(s, s);
        asm volatile("cp.async.commit_group;");
    }

    for (int kt = 0; kt < T; kt++) {
        asm volatile("cp.async.wait_group %0;" :: "n"(NSTAGE - 2));
        __syncthreads();

        const int cur = kt % NSTAGE;
        const hf* As = AsBase + cur * AS_ELEMS;
        const hf* Bs = BsBase + cur * BS_ELEMS;
        #pragma unroll
        for (int kk = 0; kk < 2; kk++) {
            unsigned af[4][4], bfg[4][2];
            #pragma unroll
            for (int i = 0; i < 4; i++) {
                const hf* p = &As[(wm * 64 + i * 16 + (lane & 15)) * 40 + kk * 16 + (lane >> 4) * 8];
                unsigned addr = (unsigned)__cvta_generic_to_shared(p);
                asm volatile("ldmatrix.sync.aligned.m8n8.x4.shared.b16 {%0,%1,%2,%3}, [%4];"
                             : "=r"(af[i][0]), "=r"(af[i][1]), "=r"(af[i][2]), "=r"(af[i][3])
                             : "r"(addr));
            }
            #pragma unroll
            for (int j = 0; j < 4; j++) {
                const hf* p = &Bs[(kk * 16 + (lane & 15)) * 136 + wn * 32 + j * 8];
                unsigned addr = (unsigned)__cvta_generic_to_shared(p);
                asm volatile("ldmatrix.sync.aligned.m8n8.x2.trans.shared.b16 {%0,%1}, [%2];"
                             : "=r"(bfg[j][0]), "=r"(bfg[j][1]) : "r"(addr));
            }
            #pragma unroll
            for (int i = 0; i < 4; i++)
                #pragma unroll
                for (int j = 0; j < 4; j++)
                    asm volatile(
                        "mma.sync.aligned.m16n8k16.row.col.f32.f16.f16.f32 "
                        "{%0,%1,%2,%3}, {%4,%5,%6,%7}, {%8,%9}, {%0,%1,%2,%3};"
                        : "+f"(acc[i][j][0]), "+f"(acc[i][j][1]), "+f"(acc[i][j][2]), "+f"(acc[i][j][3])
                        : "r"(af[i][0]), "r"(af[i][1]), "r"(af[i][2]), "r"(af[i][3]),
                          "r"(bfg[j][0]), "r"(bfg[j][1]));
        }

        // issue next tile AFTER compute: targets stage (kt-1)%NSTAGE, which the
        // barrier above proved drained by all warps.
        if (kt + NSTAGE - 1 < T) ISSUE((kt + NSTAGE - 1) % NSTAGE, kt + NSTAGE - 1);
        asm volatile("cp.async.commit_group;");
    }
    #undef ISSUE

    // epilogue
    if (MODE == 4) {
        hf* C = (hf*)Cv;
        const int jblk = row0 >> 9;
        const int off  = (jblk == 0) ? o0 : (jblk == 1) ? o1 : (jblk == 2) ? o2 : o3;
        const int hmask = (1 << hdshift) - 1;
        const int Ktot = 2 * sec;
        #pragma unroll
        for (int i = 0; i < 4; i++)
            #pragma unroll
            for (int j = 0; j < 4; j++)
                #pragma unroll
                for (int g = 0; g < 4; g++) {
                    int rr = row0 + wm * 64 + i * 16 + (lane >> 2) + ((g >> 1) << 3);
                    int cc = col0 + wn * 32 + j * 8 + ((lane & 3) << 1) + (g & 1);
                    if (cc < N) {
                        int n = rr & (NN - 1);
                        int b = cc >> hdshift;
                        int c = cc & hmask;
                        store2(C + (size_t)(n * BB + b) * Ktot, off + c, sec, acc[i][j][g]);
                    }
                }
    } else {
        float* C = (float*)Cv;
        #pragma unroll
        for (int i = 0; i < 4; i++)
            #pragma unroll
            for (int j = 0; j < 4; j++)
                #pragma unroll
                for (int g = 0; g < 4; g++) {
                    int rr = row0 + wm * 64 + i * 16 + (lane >> 2) + ((g >> 1) << 3);
                    int cc = col0 + wn * 32 + j * 8 + ((lane & 3) << 1) + (g & 1);
                    if (cc >= N) continue;
                    float v = acc[i][j][g];
                    if (MODE == 2) {
                        v = 1.f / (1.f + expf(-(v + bias[cc])));
                        if (cc < splitN) C [(size_t)rr * splitN + cc]            = v;
                        else             C2[(size_t)rr * splitN + (cc - splitN)] = v;
                    } else { // MODE 3
                        C[(size_t)rr * ldC + cc] = tanhf(v + bias[cc]);
                    }
                }
    }
}

// ================= fp32 f32x2 SGEMM (small GEMMs only) =====================
template<int MODE>   // MODE 0: plain, MODE 1: 2*acc - I
__global__ void __launch_bounds__(256)
sgemm(const float* __restrict__ A, const float* __restrict__ Bm, float* __restrict__ C,
      int M, int N, int K)
{
    __shared__ __align__(16) float As[2][16][132];
    __shared__ __align__(16) float Bsh[2][16][132];
    const int tid = threadIdx.x;
    const int tx  = tid & 15;
    const int ty  = tid >> 4;
    const int row0 = blockIdx.y * 128;
    const int col0 = blockIdx.x * 128;

    const int am  = tid >> 1;
    const int ak0 = (tid & 1) << 2;
    const int bk  = tid >> 5;
    const int bn  = (tid & 31) << 2;
    const int gn  = col0 + bn;
    const bool bok = gn < N;

    unsigned long long acc[8][4];
    #pragma unroll
    for (int i = 0; i < 8; i++)
        #pragma unroll
        for (int j = 0; j < 4; j++) acc[i][j] = 0ull;

    const int T = K >> 4;
    const float4 z4 = make_float4(0.f, 0.f, 0.f, 0.f);
    const float* Abase = A + (size_t)(row0 + am) * K + ak0;

    float4 ra0 = *(const float4*)(Abase);
    float4 ra1 = *(const float4*)(Abase + 8);
    float4 rb0 = bok ? *(const float4*)(Bm + (size_t)bk * N + gn) : z4;
    float4 rb1 = bok ? *(const float4*)(Bm + (size_t)(bk + 8) * N + gn) : z4;
    As[0][ak0 + 0][am] = ra0.x; As[0][ak0 + 1][am] = ra0.y;
    As[0][ak0 + 2][am] = ra0.z; As[0][ak0 + 3][am] = ra0.w;
    As[0][ak0 + 8][am] = ra1.x; As[0][ak0 + 9][am] = ra1.y;
    As[0][ak0 +10][am] = ra1.z; As[0][ak0 +11][am] = ra1.w;
    *(float4*)&Bsh[0][bk][bn]     = rb0;
    *(float4*)&Bsh[0][bk + 8][bn] = rb1;
    __syncthreads();

    for (int kt = 0; kt < T; kt++) {
        const int cur = kt & 1;
        if (kt + 1 < T) {
            const float* Ap = Abase + (kt + 1) * 16;
            ra0 = *(const float4*)(Ap);
            ra1 = *(const float4*)(Ap + 8);
            const int gk = (kt + 1) * 16;
            rb0 = bok ? *(const float4*)(Bm + (size_t)(gk + bk) * N + gn) : z4;
            rb1 = bok ? *(const float4*)(Bm + (size_t)(gk + bk + 8) * N + gn) : z4;
        }
        #pragma unroll
        for (int kk = 0; kk < 16; kk++) {
            float4 a0 = *(const float4*)&As[cur][kk][ty * 8];
            float4 a1 = *(const float4*)&As[cur][kk][ty * 8 + 4];
            ulonglong2 bp0 = *(const ulonglong2*)&Bsh[cur][kk][tx * 8];
            ulonglong2 bp1 = *(const ulonglong2*)&Bsh[cur][kk][tx * 8 + 4];
            unsigned long long b2[4] = { bp0.x, bp0.y, bp1.x, bp1.y };
            unsigned long long a2[8] = {
                bcast2(a0.x), bcast2(a0.y), bcast2(a0.z), bcast2(a0.w),
                bcast2(a1.x), bcast2(a1.y), bcast2(a1.z), bcast2(a1.w)
            };
            #pragma unroll
            for (int i = 0; i < 8; i++)
                #pragma unroll
                for (int j = 0; j < 4; j++)
                    fma2(acc[i][j], a2[i], b2[j]);
        }
        if (kt + 1 < T) {
            const int nxt = cur ^ 1;
            As[nxt][ak0 + 0][am] = ra0.x; As[nxt][ak0 + 1][am] = ra0.y;
            As[nxt][ak0 + 2][am] = ra0.z; As[nxt][ak0 + 3][am] = ra0.w;
            As[nxt][ak0 + 8][am] = ra1.x; As[nxt][ak0 + 9][am] = ra1.y;
            As[nxt][ak0 +10][am] = ra1.z; As[nxt][ak0 +11][am] = ra1.w;
            *(float4*)&Bsh[nxt][bk][bn]     = rb0;
            *(float4*)&Bsh[nxt][bk + 8][bn] = rb1;
        }
        __syncthreads();
    }

    #pragma unroll
    for (int i = 0; i < 8; i++) {
        const int r = row0 + ty * 8 + i;
        #pragma unroll
        for (int j = 0; j < 4; j++) {
            #pragma unroll
            for (int h = 0; h < 2; h++) {
                const int cc = col0 + tx * 8 + 2 * j + h;
                if (cc >= N) continue;
                float v = h ? __uint_as_float((unsigned)(acc[i][j] >> 32))
                            : __uint_as_float((unsigned)(acc[i][j]));
                if (MODE == 0) C[(size_t)r * N + cc] = v;
                else           C[(size_t)r * N + cc] = 2.f * v - ((r == cc) ? 1.f : 0.f);
            }
        }
    }
}

// ---------------- small kernels ----------------
__global__ void k_zero(float* p, int n) {
    int i = blockIdx.x * blockDim.x + threadIdx.x;
    if (i < n) p[i] = 0.f;
}

// split fp32 (M x K) -> A-layout hf (M x 2K): [hi | lo]
__global__ void k_splitA(const float* __restrict__ in, hf* __restrict__ out, int K, int total) {
    int i = blockIdx.x * blockDim.x + threadIdx.x;
    if (i >= total) return;
    int m = i / K, k = i - m * K;
    hf h, l; split2h(in[i], h, l);
    hf* p = out + (size_t)m * 2 * K;
    p[k] = h; p[K + k] = l;
}

// fp32 (Kreal x N) -> B-layout hf (2*Ksec x N): [hi | hi]
__global__ void k_splitB(const float* __restrict__ in, hf* __restrict__ out,
                         int Ksec, int N, int total) {
    int i = blockIdx.x * blockDim.x + threadIdx.x;
    if (i >= total) return;
    int k = i / N, j = i - k * N;
    hf h = __float2half(in[i]);
    out[(size_t)k * N + j]          = h;
    out[(size_t)(Ksec + k) * N + j] = h;
}

__global__ void k_eW(const float* __restrict__ We, const float* __restrict__ Mem,
                     float* __restrict__ e) {
    int idx = blockIdx.x * blockDim.x + threadIdx.x;
    if (idx >= NN * 64) return;
    int n = idx >> 6, d = idx & 63;
    float s = 0.f;
    #pragma unroll
    for (int k = 0; k < 20; k++) s += We[n * 20 + k] * Mem[k * 64 + d];
    e[idx] = s;
}

__global__ void k_gsoftmax(const float* __restrict__ ea, const float* __restrict__ eb,
                           float* __restrict__ g) {
    __shared__ float er[64];
    __shared__ float buf[NN];
    __shared__ float red[128];
    int n = blockIdx.x, tid = threadIdx.x;
    if (tid < 64) er[tid] = ea[n * 64 + tid];
    __syncthreads();
    for (int m = tid; m < NN; m += 128) {
        float s = 0.f;
        #pragma unroll
        for (int d = 0; d < 64; d++) s += er[d] * eb[m * 64 + d];
        buf[m] = s > 0.f ? s : 0.f;
    }
    __syncthreads();
    float mx = -1e30f;
    for (int m = tid; m < NN; m += 128) mx = fmaxf(mx, buf[m]);
    red[tid] = mx; __syncthreads();
    for (int s = 64; s > 0; s >>= 1) { if (tid < s) red[tid] = fmaxf(red[tid], red[tid + s]); __syncthreads(); }
    mx = red[0]; __syncthreads();
    float sm = 0.f;
    for (int m = tid; m < NN; m += 128) { float e = expf(buf[m] - mx); buf[m] = e; sm += e; }
    red[tid] = sm; __syncthreads();
    for (int s = 64; s > 0; s >>= 1) { if (tid < s) red[tid] += red[tid + s]; __syncthreads(); }
    float inv = 1.f / red[0];
    for (int m = tid; m < NN; m += 128) g[n * NN + m] = buf[m] * inv;
}

__global__ void k_xT(const float* __restrict__ x, float* __restrict__ xT) {
    int idx = blockIdx.x * blockDim.x + threadIdx.x;
    if (idx >= BB * NN * LL) return;
    int l = idx % LL;
    int n = (idx / LL) % NN;
    int b = idx / (LL * NN);
    xT[(n * LL + l) * BB + b] = x[idx];
}

// fill encoder x-channels of xgE for step l (pairs)
__global__ void k_fill_enc_x(hf* __restrict__ xg, const float* __restrict__ xT,
                             const float* __restrict__ GX, int l) {
    int row = blockIdx.x * blockDim.x + threadIdx.x;
    if (row >= ROWS) return;
    int n = row >> 6, b = row & 63;
    hf* p = xg + (size_t)row * KPE;
    float xv = xT[(n * LL + l) * BB + b];
    store2(p, 0, SECE, xv);
    store2(p, 195, SECE, xv);
    store2(p, 65,  SECE, GX[(size_t)(0 * NN + n) * (LL * BB) + l * BB + b]);
    store2(p, 130, SECE, GX[(size_t)(1 * NN + n) * (LL * BB) + l * BB + b]);
    store2(p, 260, SECE, GX[(size_t)(2 * NN + n) * (LL * BB) + l * BB + b]);
    store2(p, 325, SECE, GX[(size_t)(3 * NN + n) * (LL * BB) + l * BB + b]);
}

// fill identity-support h-channels (blocks 0 and 3) as pairs (init only)
__global__ void k_fill_h_id(hf* __restrict__ xg, const float* __restrict__ h,
                            int hdshift, int sec, int off0, int off3, int total) {
    int i = blockIdx.x * blockDim.x + threadIdx.x;
    if (i >= total) return;
    int row = i >> hdshift;
    int c   = i & ((1 << hdshift) - 1);
    float v = h[i];
    hf* p = xg + (size_t)row * 2 * sec;
    store2(p, off0 + c, sec, v);
    store2(p, off3 + c, sec, v);
}

// FUSED: zh = z*h -> xg id-blocks (pairs) + hB ([hi|hi])
__global__ void k_zh_pack(const float* __restrict__ z, const float* __restrict__ h,
                          hf* __restrict__ xg, hf* __restrict__ hB,
                          int hdshift, int sec, int off0, int off3, int total) {
    int i = blockIdx.x * blockDim.x + threadIdx.x;
    if (i >= total) return;
    int row = i >> hdshift;
    int c   = i & ((1 << hdshift) - 1);
    float v = z[i] * h[i];
    hf* p = xg + (size_t)row * 2 * sec;
    store2(p, off0 + c, sec, v);
    store2(p, off3 + c, sec, v);
    int n = row >> 6, b = row & 63;
    int Ncols = BB << hdshift;
    size_t col = ((size_t)b << hdshift) + c;
    hf hv = __float2half(v);
    hB[(size_t)n * Ncols + col]        = hv;
    hB[(size_t)(NN + n) * Ncols + col] = hv;
}

// FUSED: h' = r*h+(1-r)*hc -> h, xg id-blocks, hB  (encoder)
__global__ void k_hupd_pack(const float* __restrict__ r, const float* __restrict__ hc,
                            float* __restrict__ h,
                            hf* __restrict__ xg, hf* __restrict__ hB,
                            int hdshift, int sec, int off0, int off3, int total) {
    int i = blockIdx.x * blockDim.x + threadIdx.x;
    if (i >= total) return;
    int row = i >> hdshift;
    int c   = i & ((1 << hdshift) - 1);
    float rv = r[i];
    float hn = rv * h[i] + (1.f - rv) * hc[i];
    h[i] = hn;
    hf* p = xg + (size_t)row * 2 * sec;
    store2(p, off0 + c, sec, hn);
    store2(p, off3 + c, sec, hn);
    int n = row >> 6, b = row & 63;
    int Ncols = BB << hdshift;
    size_t col = ((size_t)b << hdshift) + c;
    hf hv = __float2half(hn);
    hB[(size_t)n * Ncols + col]        = hv;
    hB[(size_t)(NN + n) * Ncols + col] = hv;
}

// fill decoder go + ycov channels for step t
__global__ void k_fill_dec(hf* __restrict__ xg, const float* __restrict__ go,
                           const float* __restrict__ Ggo, const float* __restrict__ tt, int t) {
    int row = blockIdx.x * blockDim.x + threadIdx.x;
    if (row >= ROWS) return;
    int n = row >> 6, b = row & 63;
    hf* p = xg + (size_t)row * KPD;
    float gv = go[row];
    store2(p, 0,   SECD, gv);
    store2(p, 402, SECD, gv);
    store2(p, 134, SECD, Ggo[(0 * NN + n) * BB + b]);
    store2(p, 268, SECD, Ggo[(1 * NN + n) * BB + b]);
    store2(p, 536, SECD, Ggo[(2 * NN + n) * BB + b]);
    store2(p, 670, SECD, Ggo[(3 * NN + n) * BB + b]);
    #pragma unroll
    for (int c = 0; c < 5; c++) {
        float v = tt[(b * 5 + c) * HH + t];
        store2(p, 1 + c,   SECD, v); store2(p, 135 + c, SECD, v);
        store2(p, 269 + c, SECD, v); store2(p, 403 + c, SECD, v);
        store2(p, 537 + c, SECD, v); store2(p, 671 + c, SECD, v);
    }
}

__global__ void k_attn(const float* __restrict__ h, const float* __restrict__ Wq,
                       const float* __restrict__ Mem, float* __restrict__ hde) {
    __shared__ float hr[64];
    __shared__ float q[64];
    __shared__ float sc[20];
    int row = blockIdx.x, tid = threadIdx.x;
    hr[tid] = h[row * 64 + tid];
    __syncthreads();
    float s = 0.f;
    #pragma unroll
    for (int c = 0; c < 64; c++) s += hr[c] * Wq[c * 64 + tid];
    q[tid] = s;
    __syncthreads();
    if (tid < 20) {
        float v = 0.f;
        #pragma unroll
        for (int c = 0; c < 64; c++) v += q[c] * Mem[tid * 64 + c];
        sc[tid] = v;
    }
    __syncthreads();
    if (tid == 0) {
        float mx = -1e30f;
        for (int j = 0; j < 20; j++) mx = fmaxf(mx, sc[j]);
        float sm = 0.f;
        for (int j = 0; j < 20; j++) { sc[j] = expf(sc[j] - mx); sm += sc[j]; }
        float inv = 1.f / sm;
        for (int j = 0; j < 20; j++) sc[j] *= inv;
    }
    __syncthreads();
    float ha = 0.f;
    #pragma unroll
    for (int j = 0; j < 20; j++) ha += sc[j] * Mem[j * 64 + tid];
    hde[row * 128 + tid]      = hr[tid];
    hde[row * 128 + 64 + tid] = ha;
}

// FUSED decoder h update + pack + projection + output write; one block/row, 128 thr
__global__ void k_hupd_dec_pack(const float* __restrict__ r, const float* __restrict__ hc,
                                float* __restrict__ h, const float* __restrict__ pW,
                                const float* __restrict__ pb, float* __restrict__ go,
                                float* __restrict__ out, int t,
                                hf* __restrict__ xg, hf* __restrict__ hB) {
    __shared__ float red[128];
    int row = blockIdx.x, c = threadIdx.x;
    int i = row * 128 + c;
    float rv = r[i];
    float hn = rv * h[i] + (1.f - rv) * hc[i];
    h[i] = hn;
    // pack for next step
    hf* p = xg + (size_t)row * KPD;
    store2(p, 6 + c, SECD, hn);
    store2(p, 408 + c, SECD, hn);
    int n = row >> 6, b = row & 63;
    hf hv = __float2half(hn);
    hB[(size_t)n * (BB * DDEC) + b * DDEC + c]        = hv;
    hB[(size_t)(NN + n) * (BB * DDEC) + b * DDEC + c] = hv;
    // projection
    red[c] = hn * pW[c];
    __syncthreads();
    for (int s = 64; s > 0; s >>= 1) { if (c < s) red[c] += red[c + s]; __syncthreads(); }
    if (c == 0) {
        float g = red[0] + pb[0];
        go[row] = g;
        out[(b * NN + n) * HH + t] = g;
    }
}

// ---------------- host side ----------------
static void bgemm_launch(int mode, const hf* A, const hf* B, void* C,
                         int M, int N, int Kp,
                         const float* bias = nullptr, float* C2 = nullptr,
                         int splitN = 0, int ldC = 0, int hdshift = 0, int sec = 0,
                         int o0 = 0, int o1 = 0, int o2 = 0, int o3 = 0)
{
    dim3 grid((N + 127) / 128, M / 128);
    switch (mode) {
        case 2: bgemm<2><<<grid, 256, SMEM_BYTES>>>(A, B, C, M, N, Kp, bias, C2, splitN, ldC, hdshift, sec, o0, o1, o2, o3); break;
        case 3: bgemm<3><<<grid, 256, SMEM_BYTES>>>(A, B, C, M, N, Kp, bias, C2, splitN, ldC, hdshift, sec, o0, o1, o2, o3); break;
        case 4: bgemm<4><<<grid, 256, SMEM_BYTES>>>(A, B, C, M, N, Kp, bias, C2, splitN, ldC, hdshift, sec, o0, o1, o2, o3); break;
    }
}

extern "C" void kernel_launch(void* const* d_in, const int* in_sizes, int n_in,
                              void* d_out, int out_size)
{
    const float* x   = (const float*)d_in[0];
    const float* tt  = (const float*)d_in[3];
    const float* Mem = (const float*)d_in[5];
    const float* Wq  = (const float*)d_in[6];
    const float* We1 = (const float*)d_in[7];
    const float* We2 = (const float*)d_in[8];
    const float* egW = (const float*)d_in[9];
    const float* egb = (const float*)d_in[10];
    const float* euW = (const float*)d_in[11];
    const float* eub = (const float*)d_in[12];
    const float* dgW = (const float*)d_in[13];
    const float* dgb = (const float*)d_in[14];
    const float* duW = (const float*)d_in[15];
    const float* dub = (const float*)d_in[16];
    const float* pW  = (const float*)d_in[17];
    const float* pb  = (const float*)d_in[18];
    float* out = (float*)d_out;

    // opt in to >48KB dynamic smem (host attribute; not an allocation)
    cudaFuncSetAttribute(bgemm<2>, cudaFuncAttributeMaxDynamicSharedMemorySize, SMEM_BYTES);
    cudaFuncSetAttribute(bgemm<3>, cudaFuncAttributeMaxDynamicSharedMemorySize, SMEM_BYTES);
    cudaFuncSetAttribute(bgemm<4>, cudaFuncAttributeMaxDynamicSharedMemorySize, SMEM_BYTES);

    float *S, *e1, *e2, *xT, *GX, *henc, *hdec, *z, *r, *hc, *go, *Ggo;
    hf *Sbig, *hB, *xgE, *xgD, *egWB, *euWB, *dgWB, *duWB;
    cudaGetSymbolAddress((void**)&S,    g_S);
    cudaGetSymbolAddress((void**)&e1,   g_e1);
    cudaGetSymbolAddress((void**)&e2,   g_e2);
    cudaGetSymbolAddress((void**)&xT,   g_xT);
    cudaGetSymbolAddress((void**)&GX,   g_GX);
    cudaGetSymbolAddress((void**)&henc, g_henc);
    cudaGetSymbolAddress((void**)&hdec, g_hdec);
    cudaGetSymbolAddress((void**)&z,    g_z);
    cudaGetSymbolAddress((void**)&r,    g_r);
    cudaGetSymbolAddress((void**)&hc,   g_hc);
    cudaGetSymbolAddress((void**)&go,   g_go);
    cudaGetSymbolAddress((void**)&Ggo,  g_Ggo);
    cudaGetSymbolAddress((void**)&Sbig, g_Sbig);
    cudaGetSymbolAddress((void**)&hB,   g_hB);
    cudaGetSymbolAddress((void**)&xgE,  g_xgE);
    cudaGetSymbolAddress((void**)&xgD,  g_xgD);
    cudaGetSymbolAddress((void**)&egWB, g_egWB);
    cudaGetSymbolAddress((void**)&euWB, g_euWB);
    cudaGetSymbolAddress((void**)&dgWB, g_dgWB);
    cudaGetSymbolAddress((void**)&duWB, g_duWB);

    // --- weight splits (pad rows of big buffers stay zero) ---
    k_splitB<<<(KENC * 128 + 255) / 256, 256>>>(egW, egWB, SECE, 128, KENC * 128);
    k_splitB<<<(KENC * 64  + 255) / 256, 256>>>(euW, euWB, SECE, 64,  KENC * 64);
    k_splitB<<<(KDEC * 256 + 255) / 256, 256>>>(dgW, dgWB, SECD, 256, KDEC * 256);
    k_splitB<<<(KDEC * 128 + 255) / 256, 256>>>(duW, duWB, SECD, 128, KDEC * 128);

    // --- supports (fp32) ---
    k_eW<<<(NN * 64 + 255) / 256, 256>>>(We1, Mem, e1);
    k_eW<<<(NN * 64 + 255) / 256, 256>>>(We2, Mem, e2);
    k_gsoftmax<<<NN, 128>>>(e1, e2, S);
    k_gsoftmax<<<NN, 128>>>(e2, e1, S + 2 * NN * NN);
    {
        dim3 g1(NN / 128, NN / 128);
        sgemm<1><<<g1, 256>>>(S,               S,               S + 1 * NN * NN, NN, NN, NN);
        sgemm<1><<<g1, 256>>>(S + 2 * NN * NN, S + 2 * NN * NN, S + 3 * NN * NN, NN, NN, NN);
    }
    k_splitA<<<(4 * NN * NN + 255) / 256, 256>>>(S, Sbig, NN, 4 * NN * NN);

    // --- encoder x precompute (fp32) ---
    k_xT<<<(BB * NN * LL + 255) / 256, 256>>>(x, xT);
    {
        dim3 g2((LL * BB + 127) / 128, 4 * NN / 128);
        sgemm<0><<<g2, 256>>>(S, xT, GX, 4 * NN, LL * BB, NN);
    }

    // --- init states (explicit: globals persist across graph replays) ---
    k_zero<<<(ROWS * RNN + 255) / 256, 256>>>(henc, ROWS * RNN);
    k_zero<<<(ROWS + 255) / 256, 256>>>(go, ROWS);
    k_fill_h_id<<<(ROWS * RNN) / 256, 256>>>(xgE, henc, 6, SECE, 1, 196, ROWS * RNN);
    k_splitB<<<(ROWS * RNN + 255) / 256, 256>>>(henc, hB, NN, BB * RNN, ROWS * RNN);

    // --- encoder ---
    for (int l = 0; l < LL; l++) {
        k_fill_enc_x<<<ROWS / 256, 256>>>(xgE, xT, GX, l);
        bgemm_launch(4, Sbig, hB, xgE, 4 * NN, BB * RNN, KGC,
                     nullptr, nullptr, 0, 0, 6, SECE, 66, 131, 261, 326);
        bgemm_launch(2, xgE, egWB, z, ROWS, 2 * RNN, KPE, egb, r, RNN);
        k_zh_pack<<<(ROWS * RNN) / 256, 256>>>(z, henc, xgE, hB, 6, SECE, 1, 196, ROWS * RNN);
        bgemm_launch(4, Sbig, hB, xgE, 4 * NN, BB * RNN, KGC,
                     nullptr, nullptr, 0, 0, 6, SECE, 66, 131, 261, 326);
        bgemm_launch(3, xgE, euWB, hc, ROWS, RNN, KPE, eub, nullptr, 0, RNN);
        k_hupd_pack<<<(ROWS * RNN) / 256, 256>>>(r, hc, henc, xgE, hB, 6, SECE, 1, 196, ROWS * RNN);
    }

    // --- memory attention -> decoder initial hidden ---
    k_attn<<<ROWS, 64>>>(henc, Wq, Mem, hdec);
    k_fill_h_id<<<(ROWS * DDEC) / 256, 256>>>(xgD, hdec, 7, SECD, 6, 408, ROWS * DDEC);
    k_splitB<<<(ROWS * DDEC + 255) / 256, 256>>>(hdec, hB, NN, BB * DDEC, ROWS * DDEC);

    // --- decoder ---
    for (int t = 0; t < HH; t++) {
        {
            dim3 g3(1, 4 * NN / 128);
            sgemm<0><<<g3, 256>>>(S, go, Ggo, 4 * NN, BB, NN);
        }
        k_fill_dec<<<ROWS / 256, 256>>>(xgD, go, Ggo, tt, t);
        bgemm_launch(4, Sbig, hB, xgD, 4 * NN, BB * DDEC, KGC,
                     nullptr, nullptr, 0, 0, 7, SECD, 140, 274, 542, 676);
        bgemm_launch(2, xgD, dgWB, z, ROWS, 2 * DDEC, KPD, dgb, r, DDEC);
        k_zh_pack<<<(ROWS * DDEC) / 256, 256>>>(z, hdec, xgD, hB, 7, SECD, 6, 408, ROWS * DDEC);
        bgemm_launch(4, Sbig, hB, xgD, 4 * NN, BB * DDEC, KGC,
                     nullptr, nullptr, 0, 0, 7, SECD, 140, 274, 542, 676);
        bgemm_launch(3, xgD, duWB, hc, ROWS, DDEC, KPD, dub, nullptr, 0, DDEC);
        k_hupd_dec_pack<<<ROWS, 128>>>(r, hc, hdec, pW, pb, go, out, t, xgD, hB);
    }
}

// round 11
// speedup vs baseline: 2.0422x; 1.0020x over previous
#include <cuda_runtime.h>
#include <cuda_fp16.h>
#include <math.h>

// ---------------- problem constants ----------------
#define NN   512
#define BB   64
#define LL   12
#define HH   12
#define RNN  64
#define DDEC 128
#define KENC 390        // logical enc feature count
#define KDEC 804        // logical dec feature count
#define SECE 416        // enc section (pad to /32)
#define SECD 832        // dec section
#define KPE  (2*SECE)   // 832
#define KPD  (2*SECD)   // 1664
#define KGC  (2*NN)     // 1024 (graph conv K')
#define ROWS (NN*BB)    // 32768

// bgemm pipeline: 4 stages of As(128x40 hf) + Bs(32x136 hf), dynamic smem
#define AS_ELEMS (128*40)
#define BS_ELEMS (32*136)
#define NSTAGE   4
#define SMEM_BYTES (NSTAGE * (AS_ELEMS + BS_ELEMS) * 2)   // 75776

typedef __half hf;

// ---------------- scratch (device globals; zero-init, no allocation) ----------------
__device__ float g_S[4*NN*NN];
__device__ float g_e1[NN*64];
__device__ float g_e2[NN*64];
__device__ float g_xT[NN*LL*BB];
__device__ float g_GX[4*NN*LL*BB];
__device__ float g_henc[ROWS*RNN];
__device__ float g_hdec[ROWS*DDEC];
__device__ float g_z [ROWS*DDEC];
__device__ float g_r [ROWS*DDEC];
__device__ float g_hc[ROWS*DDEC];
__device__ float g_go[ROWS];
__device__ float g_Ggo[4*NN*BB];
// fp16 2-term split operands. B operands stored ONCE (K rows); bgemm wraps k>=Kp/2.
__device__ hf g_Sbig [4*NN*KGC];       // A: [hi|lo], 2048 x 1024
__device__ hf g_hB   [NN*BB*DDEC];     // B: hi only, up to 512 x 8192
__device__ hf g_xgE  [ROWS*KPE];       // enc feature A (pads stay 0)
__device__ hf g_xgD  [ROWS*KPD];       // dec feature A
__device__ hf g_egWB [SECE*128];
__device__ hf g_euWB [SECE*64];
__device__ hf g_dgWB [SECD*256];
__device__ hf g_duWB [SECD*128];

// ---------------- helpers ----------------
__device__ __forceinline__ void split2h(float v, hf &h, hf &l) {
    h = __float2half(v);
    l = __float2half(v - __half2float(h));
}
// A-layout pair write: [hi | lo] at offsets off, sec+off
__device__ __forceinline__ void store2(hf* p, int off, int sec, float v) {
    hf h, l; split2h(v, h, l);
    p[off] = h; p[sec + off] = l;
}
__device__ __forceinline__ void fma2(unsigned long long &d, unsigned long long a, unsigned long long b) {
    asm("fma.rn.f32x2 %0, %1, %2, %0;" : "+l"(d) : "l"(a), "l"(b));
}
__device__ __forceinline__ unsigned long long bcast2(float x) {
    unsigned long long r;
    asm("mov.b64 %0, {%1, %1};" : "=l"(r) : "f"(x));
    return r;
}
__device__ __forceinline__ void cpa16(void* s, const void* g, bool ok) {
    unsigned sa = (unsigned)__cvta_generic_to_shared(s);
    int sz = ok ? 16 : 0;
    asm volatile("cp.async.cg.shared.global [%0], [%1], 16, %2;"
                 :: "r"(sa), "l"(g), "r"(sz));
}

// ================= fp16 tensor-core GEMM, 128x128x32, 4-stage cp.async ==========
// Single __syncthreads per K-tile: wait -> sync -> compute(kt) -> issue(kt+3).
// B operand is stored once (Kp/2 rows); row index wraps: k >= Kp/2 reads k - Kp/2.
// A: row-major M x Kp (hf). M%128==0, Kp%32==0.
// MODE 2: v=sigmoid(acc+bias[c]); c<splitN -> Cz else Cr (fp32, stride splitN)
// MODE 3: C[r*ldC+c] = tanh(acc+bias[c])     (fp32)
// MODE 4: graph-conv scatter into xg (hf pair)
template<int MODE>
__global__ void __launch_bounds__(256)
bgemm(const hf* __restrict__ A, const hf* __restrict__ Bm, void* __restrict__ Cv,
      int M, int N, int Kp, const float* __restrict__ bias, float* __restrict__ C2,
      int splitN, int ldC, int hdshift, int sec, int o0, int o1, int o2, int o3)
{
    extern __shared__ __align__(16) char smem_raw[];
    hf* AsBase = (hf*)smem_raw;                        // NSTAGE x AS_ELEMS
    hf* BsBase = (hf*)smem_raw + NSTAGE * AS_ELEMS;    // NSTAGE x BS_ELEMS

    const int tid  = threadIdx.x;
    const int lane = tid & 31;
    const int warp = tid >> 5;
    const int wm   = warp & 1;
    const int wn   = warp >> 1;
    const int row0 = blockIdx.y * 128;
    const int col0 = blockIdx.x * 128;
    const int Khalf = Kp >> 1;

    float acc[4][4][4];
    #pragma unroll
    for (int i = 0; i < 4; i++)
        #pragma unroll
        for (int j = 0; j < 4; j++)
            #pragma unroll
            for (int g = 0; g < 4; g++) acc[i][j][g] = 0.f;

    const int aq0 = tid * 2;
    const int ar0 = aq0 >> 2, ac0 = (aq0 & 3) * 8;
    const int ar1 = (aq0 + 1) >> 2, ac1 = ((aq0 + 1) & 3) * 8;
    const int br0 = aq0 >> 4, bc0 = (aq0 & 15) * 8;
    const int br1 = (aq0 + 1) >> 4, bc1 = ((aq0 + 1) & 15) * 8;
    const bool ok0 = (col0 + bc0) < N;
    const bool ok1 = (col0 + bc1) < N;

    const int T = Kp >> 5;

    #define ISSUE(s, kt) do {                                                          \
        hf* As_ = AsBase + (s) * AS_ELEMS;                                             \
        hf* Bs_ = BsBase + (s) * BS_ELEMS;                                             \
        const int k0_ = (kt) * 32;                                                     \
        int kr0_ = k0_ + br0; if (kr0_ >= Khalf) kr0_ -= Khalf;                        \
        int kr1_ = k0_ + br1; if (kr1_ >= Khalf) kr1_ -= Khalf;                        \
        cpa16(&As_[ar0 * 40 + ac0], A + (size_t)(row0 + ar0) * Kp + k0_ + ac0, true);  \
        cpa16(&As_[ar1 * 40 + ac1], A + (size_t)(row0 + ar1) * Kp + k0_ + ac1, true);  \
        cpa16(&Bs_[br0 * 136 + bc0],                                                   \
              ok0 ? (Bm + (size_t)kr0_ * N + col0 + bc0) : Bm, ok0);                   \
        cpa16(&Bs_[br1 * 136 + bc1],                                                   \
              ok1 ? (Bm + (size_t)kr1_ * N + col0 + bc1) : Bm, ok1);                   \
    } while (0)

    // prologue: issue stages 0..NSTAGE-2
    #pragma unroll
    for (int s = 0; s < NSTAGE - 1; s++) {
        if (s < T) ISSUE(s, s);
        asm volatile("cp.async.commit_group;");
    }

    for (int kt = 0; kt < T; kt++) {
        asm volatile("cp.async.wait_group %0;" :: "n"(NSTAGE - 2));
        __syncthreads();

        const int cur = kt % NSTAGE;
        const hf* As = AsBase + cur * AS_ELEMS;
        const hf* Bs = BsBase + cur * BS_ELEMS;
        #pragma unroll
        for (int kk = 0; kk < 2; kk++) {
            unsigned af[4][4], bfg[4][2];
            #pragma unroll
            for (int i = 0; i < 4; i++) {
                const hf* p = &As[(wm * 64 + i * 16 + (lane & 15)) * 40 + kk * 16 + (lane >> 4) * 8];
                unsigned addr = (unsigned)__cvta_generic_to_shared(p);
                asm volatile("ldmatrix.sync.aligned.m8n8.x4.shared.b16 {%0,%1,%2,%3}, [%4];"
                             : "=r"(af[i][0]), "=r"(af[i][1]), "=r"(af[i][2]), "=r"(af[i][3])
                             : "r"(addr));
            }
            #pragma unroll
            for (int j = 0; j < 4; j++) {
                const hf* p = &Bs[(kk * 16 + (lane & 15)) * 136 + wn * 32 + j * 8];
                unsigned addr = (unsigned)__cvta_generic_to_shared(p);
                asm volatile("ldmatrix.sync.aligned.m8n8.x2.trans.shared.b16 {%0,%1}, [%2];"
                             : "=r"(bfg[j][0]), "=r"(bfg[j][1]) : "r"(addr));
            }
            #pragma unroll
            for (int i = 0; i < 4; i++)
                #pragma unroll
                for (int j = 0; j < 4; j++)
                    asm volatile(
                        "mma.sync.aligned.m16n8k16.row.col.f32.f16.f16.f32 "
                        "{%0,%1,%2,%3}, {%4,%5,%6,%7}, {%8,%9}, {%0,%1,%2,%3};"
                        : "+f"(acc[i][j][0]), "+f"(acc[i][j][1]), "+f"(acc[i][j][2]), "+f"(acc[i][j][3])
                        : "r"(af[i][0]), "r"(af[i][1]), "r"(af[i][2]), "r"(af[i][3]),
                          "r"(bfg[j][0]), "r"(bfg[j][1]));
        }

        // issue next tile AFTER compute: targets stage (kt-1)%NSTAGE, drained above.
        if (kt + NSTAGE - 1 < T) ISSUE((kt + NSTAGE - 1) % NSTAGE, kt + NSTAGE - 1);
        asm volatile("cp.async.commit_group;");
    }
    #undef ISSUE

    // epilogue
    if (MODE == 4) {
        hf* C = (hf*)Cv;
        const int jblk = row0 >> 9;
        const int off  = (jblk == 0) ? o0 : (jblk == 1) ? o1 : (jblk == 2) ? o2 : o3;
        const int hmask = (1 << hdshift) - 1;
        const int Ktot = 2 * sec;
        #pragma unroll
        for (int i = 0; i < 4; i++)
            #pragma unroll
            for (int j = 0; j < 4; j++)
                #pragma unroll
                for (int g = 0; g < 4; g++) {
                    int rr = row0 + wm * 64 + i * 16 + (lane >> 2) + ((g >> 1) << 3);
                    int cc = col0 + wn * 32 + j * 8 + ((lane & 3) << 1) + (g & 1);
                    if (cc < N) {
                        int n = rr & (NN - 1);
                        int b = cc >> hdshift;
                        int c = cc & hmask;
                        store2(C + (size_t)(n * BB + b) * Ktot, off + c, sec, acc[i][j][g]);
                    }
                }
    } else {
        float* C = (float*)Cv;
        #pragma unroll
        for (int i = 0; i < 4; i++)
            #pragma unroll
            for (int j = 0; j < 4; j++)
                #pragma unroll
                for (int g = 0; g < 4; g++) {
                    int rr = row0 + wm * 64 + i * 16 + (lane >> 2) + ((g >> 1) << 3);
                    int cc = col0 + wn * 32 + j * 8 + ((lane & 3) << 1) + (g & 1);
                    if (cc >= N) continue;
                    float v = acc[i][j][g];
                    if (MODE == 2) {
                        v = 1.f / (1.f + expf(-(v + bias[cc])));
                        if (cc < splitN) C [(size_t)rr * splitN + cc]            = v;
                        else             C2[(size_t)rr * splitN + (cc - splitN)] = v;
                    } else { // MODE 3
                        C[(size_t)rr * ldC + cc] = tanhf(v + bias[cc]);
                    }
                }
    }
}

// ================= fp32 f32x2 SGEMM (small GEMMs only) =====================
template<int MODE>   // MODE 0: plain, MODE 1: 2*acc - I
__global__ void __launch_bounds__(256)
sgemm(const float* __restrict__ A, const float* __restrict__ Bm, float* __restrict__ C,
      int M, int N, int K)
{
    __shared__ __align__(16) float As[2][16][132];
    __shared__ __align__(16) float Bsh[2][16][132];
    const int tid = threadIdx.x;
    const int tx  = tid & 15;
    const int ty  = tid >> 4;
    const int row0 = blockIdx.y * 128;
    const int col0 = blockIdx.x * 128;

    const int am  = tid >> 1;
    const int ak0 = (tid & 1) << 2;
    const int bk  = tid >> 5;
    const int bn  = (tid & 31) << 2;
    const int gn  = col0 + bn;
    const bool bok = gn < N;

    unsigned long long acc[8][4];
    #pragma unroll
    for (int i = 0; i < 8; i++)
        #pragma unroll
        for (int j = 0; j < 4; j++) acc[i][j] = 0ull;

    const int T = K >> 4;
    const float4 z4 = make_float4(0.f, 0.f, 0.f, 0.f);
    const float* Abase = A + (size_t)(row0 + am) * K + ak0;

    float4 ra0 = *(const float4*)(Abase);
    float4 ra1 = *(const float4*)(Abase + 8);
    float4 rb0 = bok ? *(const float4*)(Bm + (size_t)bk * N + gn) : z4;
    float4 rb1 = bok ? *(const float4*)(Bm + (size_t)(bk + 8) * N + gn) : z4;
    As[0][ak0 + 0][am] = ra0.x; As[0][ak0 + 1][am] = ra0.y;
    As[0][ak0 + 2][am] = ra0.z; As[0][ak0 + 3][am] = ra0.w;
    As[0][ak0 + 8][am] = ra1.x; As[0][ak0 + 9][am] = ra1.y;
    As[0][ak0 +10][am] = ra1.z; As[0][ak0 +11][am] = ra1.w;
    *(float4*)&Bsh[0][bk][bn]     = rb0;
    *(float4*)&Bsh[0][bk + 8][bn] = rb1;
    __syncthreads();

    for (int kt = 0; kt < T; kt++) {
        const int cur = kt & 1;
        if (kt + 1 < T) {
            const float* Ap = Abase + (kt + 1) * 16;
            ra0 = *(const float4*)(Ap);
            ra1 = *(const float4*)(Ap + 8);
            const int gk = (kt + 1) * 16;
            rb0 = bok ? *(const float4*)(Bm + (size_t)(gk + bk) * N + gn) : z4;
            rb1 = bok ? *(const float4*)(Bm + (size_t)(gk + bk + 8) * N + gn) : z4;
        }
        #pragma unroll
        for (int kk = 0; kk < 16; kk++) {
            float4 a0 = *(const float4*)&As[cur][kk][ty * 8];
            float4 a1 = *(const float4*)&As[cur][kk][ty * 8 + 4];
            ulonglong2 bp0 = *(const ulonglong2*)&Bsh[cur][kk][tx * 8];
            ulonglong2 bp1 = *(const ulonglong2*)&Bsh[cur][kk][tx * 8 + 4];
            unsigned long long b2[4] = { bp0.x, bp0.y, bp1.x, bp1.y };
            unsigned long long a2[8] = {
                bcast2(a0.x), bcast2(a0.y), bcast2(a0.z), bcast2(a0.w),
                bcast2(a1.x), bcast2(a1.y), bcast2(a1.z), bcast2(a1.w)
            };
            #pragma unroll
            for (int i = 0; i < 8; i++)
                #pragma unroll
                for (int j = 0; j < 4; j++)
                    fma2(acc[i][j], a2[i], b2[j]);
        }
        if (kt + 1 < T) {
            const int nxt = cur ^ 1;
            As[nxt][ak0 + 0][am] = ra0.x; As[nxt][ak0 + 1][am] = ra0.y;
            As[nxt][ak0 + 2][am] = ra0.z; As[nxt][ak0 + 3][am] = ra0.w;
            As[nxt][ak0 + 8][am] = ra1.x; As[nxt][ak0 + 9][am] = ra1.y;
            As[nxt][ak0 +10][am] = ra1.z; As[nxt][ak0 +11][am] = ra1.w;
            *(float4*)&Bsh[nxt][bk][bn]     = rb0;
            *(float4*)&Bsh[nxt][bk + 8][bn] = rb1;
        }
        __syncthreads();
    }

    #pragma unroll
    for (int i = 0; i < 8; i++) {
        const int r = row0 + ty * 8 + i;
        #pragma unroll
        for (int j = 0; j < 4; j++) {
            #pragma unroll
            for (int h = 0; h < 2; h++) {
                const int cc = col0 + tx * 8 + 2 * j + h;
                if (cc >= N) continue;
                float v = h ? __uint_as_float((unsigned)(acc[i][j] >> 32))
                            : __uint_as_float((unsigned)(acc[i][j]));
                if (MODE == 0) C[(size_t)r * N + cc] = v;
                else           C[(size_t)r * N + cc] = 2.f * v - ((r == cc) ? 1.f : 0.f);
            }
        }
    }
}

// ---------------- small kernels ----------------
__global__ void k_zero(float* p, int n) {
    int i = blockIdx.x * blockDim.x + threadIdx.x;
    if (i < n) p[i] = 0.f;
}

// split fp32 (M x K) -> A-layout hf (M x 2K): [hi | lo]
__global__ void k_splitA(const float* __restrict__ in, hf* __restrict__ out, int K, int total) {
    int i = blockIdx.x * blockDim.x + threadIdx.x;
    if (i >= total) return;
    int m = i / K, k = i - m * K;
    hf h, l; split2h(in[i], h, l);
    hf* p = out + (size_t)m * 2 * K;
    p[k] = h; p[K + k] = l;
}

// fp32 (Kreal x N) -> B hf (single section, K x N)
__global__ void k_splitB(const float* __restrict__ in, hf* __restrict__ out,
                         int N, int total) {
    int i = blockIdx.x * blockDim.x + threadIdx.x;
    if (i >= total) return;
    out[i] = __float2half(in[i]);
}

__global__ void k_eW(const float* __restrict__ We, const float* __restrict__ Mem,
                     float* __restrict__ e) {
    int idx = blockIdx.x * blockDim.x + threadIdx.x;
    if (idx >= NN * 64) return;
    int n = idx >> 6, d = idx & 63;
    float s = 0.f;
    #pragma unroll
    for (int k = 0; k < 20; k++) s += We[n * 20 + k] * Mem[k * 64 + d];
    e[idx] = s;
}

__global__ void k_gsoftmax(const float* __restrict__ ea, const float* __restrict__ eb,
                           float* __restrict__ g) {
    __shared__ float er[64];
    __shared__ float buf[NN];
    __shared__ float red[128];
    int n = blockIdx.x, tid = threadIdx.x;
    if (tid < 64) er[tid] = ea[n * 64 + tid];
    __syncthreads();
    for (int m = tid; m < NN; m += 128) {
        float s = 0.f;
        #pragma unroll
        for (int d = 0; d < 64; d++) s += er[d] * eb[m * 64 + d];
        buf[m] = s > 0.f ? s : 0.f;
    }
    __syncthreads();
    float mx = -1e30f;
    for (int m = tid; m < NN; m += 128) mx = fmaxf(mx, buf[m]);
    red[tid] = mx; __syncthreads();
    for (int s = 64; s > 0; s >>= 1) { if (tid < s) red[tid] = fmaxf(red[tid], red[tid + s]); __syncthreads(); }
    mx = red[0]; __syncthreads();
    float sm = 0.f;
    for (int m = tid; m < NN; m += 128) { float e = expf(buf[m] - mx); buf[m] = e; sm += e; }
    red[tid] = sm; __syncthreads();
    for (int s = 64; s > 0; s >>= 1) { if (tid < s) red[tid] += red[tid + s]; __syncthreads(); }
    float inv = 1.f / red[0];
    for (int m = tid; m < NN; m += 128) g[n * NN + m] = buf[m] * inv;
}

__global__ void k_xT(const float* __restrict__ x, float* __restrict__ xT) {
    int idx = blockIdx.x * blockDim.x + threadIdx.x;
    if (idx >= BB * NN * LL) return;
    int l = idx % LL;
    int n = (idx / LL) % NN;
    int b = idx / (LL * NN);
    xT[(n * LL + l) * BB + b] = x[idx];
}

// fill encoder x-channels of xgE for step l (pairs)
__global__ void k_fill_enc_x(hf* __restrict__ xg, const float* __restrict__ xT,
                             const float* __restrict__ GX, int l) {
    int row = blockIdx.x * blockDim.x + threadIdx.x;
    if (row >= ROWS) return;
    int n = row >> 6, b = row & 63;
    hf* p = xg + (size_t)row * KPE;
    float xv = xT[(n * LL + l) * BB + b];
    store2(p, 0, SECE, xv);
    store2(p, 195, SECE, xv);
    store2(p, 65,  SECE, GX[(size_t)(0 * NN + n) * (LL * BB) + l * BB + b]);
    store2(p, 130, SECE, GX[(size_t)(1 * NN + n) * (LL * BB) + l * BB + b]);
    store2(p, 260, SECE, GX[(size_t)(2 * NN + n) * (LL * BB) + l * BB + b]);
    store2(p, 325, SECE, GX[(size_t)(3 * NN + n) * (LL * BB) + l * BB + b]);
}

// fill identity-support h-channels (blocks 0 and 3) as pairs (init only)
__global__ void k_fill_h_id(hf* __restrict__ xg, const float* __restrict__ h,
                            int hdshift, int sec, int off0, int off3, int total) {
    int i = blockIdx.x * blockDim.x + threadIdx.x;
    if (i >= total) return;
    int row = i >> hdshift;
    int c   = i & ((1 << hdshift) - 1);
    float v = h[i];
    hf* p = xg + (size_t)row * 2 * sec;
    store2(p, off0 + c, sec, v);
    store2(p, off3 + c, sec, v);
}

// hf (single-section) B fill from fp32 (init only)
__global__ void k_packB(const float* __restrict__ in, hf* __restrict__ out, int total) {
    int i = blockIdx.x * blockDim.x + threadIdx.x;
    if (i < total) out[i] = __float2half(in[i]);
}

// FUSED (2 elems/thread): zh = z*h -> xg id-blocks + hB (half2)
__global__ void k_zh_pack(const float* __restrict__ z, const float* __restrict__ h,
                          hf* __restrict__ xg, hf* __restrict__ hB,
                          int hdshift, int sec, int off0, int off3, int total2) {
    int i = blockIdx.x * blockDim.x + threadIdx.x;
    if (i >= total2) return;
    int base = i * 2;
    int row = base >> hdshift;
    int c   = base & ((1 << hdshift) - 1);
    float2 zv = *(const float2*)(z + base);
    float2 hv = *(const float2*)(h + base);
    float v0 = zv.x * hv.x, v1 = zv.y * hv.y;
    hf* p = xg + (size_t)row * 2 * sec;
    store2(p, off0 + c, sec, v0);     store2(p, off0 + c + 1, sec, v1);
    store2(p, off3 + c, sec, v0);     store2(p, off3 + c + 1, sec, v1);
    int n = row >> 6, b = row & 63;
    int Ncols = BB << hdshift;
    __half2 hv2 = __floats2half2_rn(v0, v1);
    *(__half2*)(hB + (size_t)n * Ncols + ((size_t)b << hdshift) + c) = hv2;
}

// FUSED (2 elems/thread): h' = r*h+(1-r)*hc -> h, xg id-blocks, hB (encoder)
__global__ void k_hupd_pack(const float* __restrict__ r, const float* __restrict__ hc,
                            float* __restrict__ h,
                            hf* __restrict__ xg, hf* __restrict__ hB,
                            int hdshift, int sec, int off0, int off3, int total2) {
    int i = blockIdx.x * blockDim.x + threadIdx.x;
    if (i >= total2) return;
    int base = i * 2;
    int row = base >> hdshift;
    int c   = base & ((1 << hdshift) - 1);
    float2 rv = *(const float2*)(r + base);
    float2 hcv = *(const float2*)(hc + base);
    float2 hv = *(const float2*)(h + base);
    float hn0 = rv.x * hv.x + (1.f - rv.x) * hcv.x;
    float hn1 = rv.y * hv.y + (1.f - rv.y) * hcv.y;
    *(float2*)(h + base) = make_float2(hn0, hn1);
    hf* p = xg + (size_t)row * 2 * sec;
    store2(p, off0 + c, sec, hn0);    store2(p, off0 + c + 1, sec, hn1);
    store2(p, off3 + c, sec, hn0);    store2(p, off3 + c + 1, sec, hn1);
    int n = row >> 6, b = row & 63;
    int Ncols = BB << hdshift;
    __half2 hv2 = __floats2half2_rn(hn0, hn1);
    *(__half2*)(hB + (size_t)n * Ncols + ((size_t)b << hdshift) + c) = hv2;
}

// fill decoder go + ycov channels for step t
__global__ void k_fill_dec(hf* __restrict__ xg, const float* __restrict__ go,
                           const float* __restrict__ Ggo, const float* __restrict__ tt, int t) {
    int row = blockIdx.x * blockDim.x + threadIdx.x;
    if (row >= ROWS) return;
    int n = row >> 6, b = row & 63;
    hf* p = xg + (size_t)row * KPD;
    float gv = go[row];
    store2(p, 0,   SECD, gv);
    store2(p, 402, SECD, gv);
    store2(p, 134, SECD, Ggo[(0 * NN + n) * BB + b]);
    store2(p, 268, SECD, Ggo[(1 * NN + n) * BB + b]);
    store2(p, 536, SECD, Ggo[(2 * NN + n) * BB + b]);
    store2(p, 670, SECD, Ggo[(3 * NN + n) * BB + b]);
    #pragma unroll
    for (int c = 0; c < 5; c++) {
        float v = tt[(b * 5 + c) * HH + t];
        store2(p, 1 + c,   SECD, v); store2(p, 135 + c, SECD, v);
        store2(p, 269 + c, SECD, v); store2(p, 403 + c, SECD, v);
        store2(p, 537 + c, SECD, v); store2(p, 671 + c, SECD, v);
    }
}

__global__ void k_attn(const float* __restrict__ h, const float* __restrict__ Wq,
                       const float* __restrict__ Mem, float* __restrict__ hde) {
    __shared__ float hr[64];
    __shared__ float q[64];
    __shared__ float sc[20];
    int row = blockIdx.x, tid = threadIdx.x;
    hr[tid] = h[row * 64 + tid];
    __syncthreads();
    float s = 0.f;
    #pragma unroll
    for (int c = 0; c < 64; c++) s += hr[c] * Wq[c * 64 + tid];
    q[tid] = s;
    __syncthreads();
    if (tid < 20) {
        float v = 0.f;
        #pragma unroll
        for (int c = 0; c < 64; c++) v += q[c] * Mem[tid * 64 + c];
        sc[tid] = v;
    }
    __syncthreads();
    if (tid == 0) {
        float mx = -1e30f;
        for (int j = 0; j < 20; j++) mx = fmaxf(mx, sc[j]);
        float sm = 0.f;
        for (int j = 0; j < 20; j++) { sc[j] = expf(sc[j] - mx); sm += sc[j]; }
        float inv = 1.f / sm;
        for (int j = 0; j < 20; j++) sc[j] *= inv;
    }
    __syncthreads();
    float ha = 0.f;
    #pragma unroll
    for (int j = 0; j < 20; j++) ha += sc[j] * Mem[j * 64 + tid];
    hde[row * 128 + tid]      = hr[tid];
    hde[row * 128 + 64 + tid] = ha;
}

// FUSED decoder h update + pack + projection + output write; 64 thr/row, 2 c/thread
__global__ void k_hupd_dec_pack(const float* __restrict__ r, const float* __restrict__ hc,
                                float* __restrict__ h, const float* __restrict__ pW,
                                const float* __restrict__ pb, float* __restrict__ go,
                                float* __restrict__ out, int t,
                                hf* __restrict__ xg, hf* __restrict__ hB) {
    __shared__ float red[64];
    int row = blockIdx.x, tid = threadIdx.x;
    int c = tid * 2;
    int i = row * 128 + c;
    float2 rv = *(const float2*)(r + i);
    float2 hcv = *(const float2*)(hc + i);
    float2 hv = *(const float2*)(h + i);
    float hn0 = rv.x * hv.x + (1.f - rv.x) * hcv.x;
    float hn1 = rv.y * hv.y + (1.f - rv.y) * hcv.y;
    *(float2*)(h + i) = make_float2(hn0, hn1);
    // pack for next step
    hf* p = xg + (size_t)row * KPD;
    store2(p, 6 + c, SECD, hn0);   store2(p, 6 + c + 1, SECD, hn1);
    store2(p, 408 + c, SECD, hn0); store2(p, 408 + c + 1, SECD, hn1);
    int n = row >> 6, b = row & 63;
    __half2 hv2 = __floats2half2_rn(hn0, hn1);
    *(__half2*)(hB + (size_t)n * (BB * DDEC) + b * DDEC + c) = hv2;
    // projection
    float2 pw = *(const float2*)(pW + c);
    red[tid] = hn0 * pw.x + hn1 * pw.y;
    __syncthreads();
    for (int s = 32; s > 0; s >>= 1) { if (tid < s) red[tid] += red[tid + s]; __syncthreads(); }
    if (tid == 0) {
        float g = red[0] + pb[0];
        go[row] = g;
        out[(b * NN + n) * HH + t] = g;
    }
}

// ---------------- host side ----------------
static void bgemm_launch(int mode, const hf* A, const hf* B, void* C,
                         int M, int N, int Kp,
                         const float* bias = nullptr, float* C2 = nullptr,
                         int splitN = 0, int ldC = 0, int hdshift = 0, int sec = 0,
                         int o0 = 0, int o1 = 0, int o2 = 0, int o3 = 0)
{
    dim3 grid((N + 127) / 128, M / 128);
    switch (mode) {
        case 2: bgemm<2><<<grid, 256, SMEM_BYTES>>>(A, B, C, M, N, Kp, bias, C2, splitN, ldC, hdshift, sec, o0, o1, o2, o3); break;
        case 3: bgemm<3><<<grid, 256, SMEM_BYTES>>>(A, B, C, M, N, Kp, bias, C2, splitN, ldC, hdshift, sec, o0, o1, o2, o3); break;
        case 4: bgemm<4><<<grid, 256, SMEM_BYTES>>>(A, B, C, M, N, Kp, bias, C2, splitN, ldC, hdshift, sec, o0, o1, o2, o3); break;
    }
}

extern "C" void kernel_launch(void* const* d_in, const int* in_sizes, int n_in,
                              void* d_out, int out_size)
{
    const float* x   = (const float*)d_in[0];
    const float* tt  = (const float*)d_in[3];
    const float* Mem = (const float*)d_in[5];
    const float* Wq  = (const float*)d_in[6];
    const float* We1 = (const float*)d_in[7];
    const float* We2 = (const float*)d_in[8];
    const float* egW = (const float*)d_in[9];
    const float* egb = (const float*)d_in[10];
    const float* euW = (const float*)d_in[11];
    const float* eub = (const float*)d_in[12];
    const float* dgW = (const float*)d_in[13];
    const float* dgb = (const float*)d_in[14];
    const float* duW = (const float*)d_in[15];
    const float* dub = (const float*)d_in[16];
    const float* pW  = (const float*)d_in[17];
    const float* pb  = (const float*)d_in[18];
    float* out = (float*)d_out;

    // opt in to >48KB dynamic smem (host attribute; not an allocation)
    cudaFuncSetAttribute(bgemm<2>, cudaFuncAttributeMaxDynamicSharedMemorySize, SMEM_BYTES);
    cudaFuncSetAttribute(bgemm<3>, cudaFuncAttributeMaxDynamicSharedMemorySize, SMEM_BYTES);
    cudaFuncSetAttribute(bgemm<4>, cudaFuncAttributeMaxDynamicSharedMemorySize, SMEM_BYTES);

    float *S, *e1, *e2, *xT, *GX, *henc, *hdec, *z, *r, *hc, *go, *Ggo;
    hf *Sbig, *hB, *xgE, *xgD, *egWB, *euWB, *dgWB, *duWB;
    cudaGetSymbolAddress((void**)&S,    g_S);
    cudaGetSymbolAddress((void**)&e1,   g_e1);
    cudaGetSymbolAddress((void**)&e2,   g_e2);
    cudaGetSymbolAddress((void**)&xT,   g_xT);
    cudaGetSymbolAddress((void**)&GX,   g_GX);
    cudaGetSymbolAddress((void**)&henc, g_henc);
    cudaGetSymbolAddress((void**)&hdec, g_hdec);
    cudaGetSymbolAddress((void**)&z,    g_z);
    cudaGetSymbolAddress((void**)&r,    g_r);
    cudaGetSymbolAddress((void**)&hc,   g_hc);
    cudaGetSymbolAddress((void**)&go,   g_go);
    cudaGetSymbolAddress((void**)&Ggo,  g_Ggo);
    cudaGetSymbolAddress((void**)&Sbig, g_Sbig);
    cudaGetSymbolAddress((void**)&hB,   g_hB);
    cudaGetSymbolAddress((void**)&xgE,  g_xgE);
    cudaGetSymbolAddress((void**)&xgD,  g_xgD);
    cudaGetSymbolAddress((void**)&egWB, g_egWB);
    cudaGetSymbolAddress((void**)&euWB, g_euWB);
    cudaGetSymbolAddress((void**)&dgWB, g_dgWB);
    cudaGetSymbolAddress((void**)&duWB, g_duWB);

    // --- weight packs (single section; pad rows stay zero) ---
    k_packB<<<(KENC * 128 + 255) / 256, 256>>>(egW, egWB, KENC * 128);
    k_packB<<<(KENC * 64  + 255) / 256, 256>>>(euW, euWB, KENC * 64);
    k_packB<<<(KDEC * 256 + 255) / 256, 256>>>(dgW, dgWB, KDEC * 256);
    k_packB<<<(KDEC * 128 + 255) / 256, 256>>>(duW, duWB, KDEC * 128);

    // --- supports (fp32) ---
    k_eW<<<(NN * 64 + 255) / 256, 256>>>(We1, Mem, e1);
    k_eW<<<(NN * 64 + 255) / 256, 256>>>(We2, Mem, e2);
    k_gsoftmax<<<NN, 128>>>(e1, e2, S);
    k_gsoftmax<<<NN, 128>>>(e2, e1, S + 2 * NN * NN);
    {
        dim3 g1(NN / 128, NN / 128);
        sgemm<1><<<g1, 256>>>(S,               S,               S + 1 * NN * NN, NN, NN, NN);
        sgemm<1><<<g1, 256>>>(S + 2 * NN * NN, S + 2 * NN * NN, S + 3 * NN * NN, NN, NN, NN);
    }
    k_splitA<<<(4 * NN * NN + 255) / 256, 256>>>(S, Sbig, NN, 4 * NN * NN);

    // --- encoder x precompute (fp32) ---
    k_xT<<<(BB * NN * LL + 255) / 256, 256>>>(x, xT);
    {
        dim3 g2((LL * BB + 127) / 128, 4 * NN / 128);
        sgemm<0><<<g2, 256>>>(S, xT, GX, 4 * NN, LL * BB, NN);
    }

    // --- init states (explicit: globals persist across graph replays) ---
    k_zero<<<(ROWS * RNN + 255) / 256, 256>>>(henc, ROWS * RNN);
    k_zero<<<(ROWS + 255) / 256, 256>>>(go, ROWS);
    k_fill_h_id<<<(ROWS * RNN) / 256, 256>>>(xgE, henc, 6, SECE, 1, 196, ROWS * RNN);
    k_packB<<<(ROWS * RNN + 255) / 256, 256>>>(henc, hB, ROWS * RNN);

    // --- encoder ---
    for (int l = 0; l < LL; l++) {
        k_fill_enc_x<<<ROWS / 256, 256>>>(xgE, xT, GX, l);
        bgemm_launch(4, Sbig, hB, xgE, 4 * NN, BB * RNN, KGC,
                     nullptr, nullptr, 0, 0, 6, SECE, 66, 131, 261, 326);
        bgemm_launch(2, xgE, egWB, z, ROWS, 2 * RNN, KPE, egb, r, RNN);
        k_zh_pack<<<(ROWS * RNN / 2) / 256, 256>>>(z, henc, xgE, hB, 6, SECE, 1, 196, ROWS * RNN / 2);
        bgemm_launch(4, Sbig, hB, xgE, 4 * NN, BB * RNN, KGC,
                     nullptr, nullptr, 0, 0, 6, SECE, 66, 131, 261, 326);
        bgemm_launch(3, xgE, euWB, hc, ROWS, RNN, KPE, eub, nullptr, 0, RNN);
        k_hupd_pack<<<(ROWS * RNN / 2) / 256, 256>>>(r, hc, henc, xgE, hB, 6, SECE, 1, 196, ROWS * RNN / 2);
    }

    // --- memory attention -> decoder initial hidden ---
    k_attn<<<ROWS, 64>>>(henc, Wq, Mem, hdec);
    k_fill_h_id<<<(ROWS * DDEC) / 256, 256>>>(xgD, hdec, 7, SECD, 6, 408, ROWS * DDEC);
    k_packB<<<(ROWS * DDEC + 255) / 256, 256>>>(hdec, hB, ROWS * DDEC);

    // --- decoder ---
    for (int t = 0; t < HH; t++) {
        {
            dim3 g3(1, 4 * NN / 128);
            sgemm<0><<<g3, 256>>>(S, go, Ggo, 4 * NN, BB, NN);
        }
        k_fill_dec<<<ROWS / 256, 256>>>(xgD, go, Ggo, tt, t);
        bgemm_launch(4, Sbig, hB, xgD, 4 * NN, BB * DDEC, KGC,
                     nullptr, nullptr, 0, 0, 7, SECD, 140, 274, 542, 676);
        bgemm_launch(2, xgD, dgWB, z, ROWS, 2 * DDEC, KPD, dgb, r, DDEC);
        k_zh_pack<<<(ROWS * DDEC / 2) / 256, 256>>>(z, hdec, xgD, hB, 7, SECD, 6, 408, ROWS * DDEC / 2);
        bgemm_launch(4, Sbig, hB, xgD, 4 * NN, BB * DDEC, KGC,
                     nullptr, nullptr, 0, 0, 7, SECD, 140, 274, 542, 676);
        bgemm_launch(3, xgD, duWB, hc, ROWS, DDEC, KPD, dub, nullptr, 0, DDEC);
        k_hupd_dec_pack<<<ROWS, 64>>>(r, hc, hdec, pW, pb, go, out, t, xgD, hB);
    }
}